// round 8
// baseline (speedup 1.0000x reference)
#include <cuda_runtime.h>
#include <cuda_bf16.h>
#include <math.h>
#include <stdint.h>

#define HIDDEN 5120
#define NHEADS 16
#define QLORA  1536
#define KVLORA 512
#define NOPE   128
#define ROPE_D 64
#define QKD    192
#define VDIM   128
#define SEQ    2048
#define QKVN   2112
#define SM_SCALE 0.07216878364870322f  // 192^-0.5
#define RESID_SCALE 0.125f

// ---------------- scratch ----------------------------------------------------
static __device__ float g_qackv[SEQ * QKVN];
static __device__ float2 g_rtab[SEQ * 32];   // (cos, sin) per (s, j)

static __device__ __nv_bfloat16 g_h_hi[SEQ * HIDDEN],    g_h_lo[SEQ * HIDDEN];
static __device__ __nv_bfloat16 g_qa_hi[SEQ * QLORA],    g_qa_lo[SEQ * QLORA];
static __device__ __nv_bfloat16 g_ckvn_hi[SEQ * KVLORA], g_ckvn_lo[SEQ * KVLORA];
static __device__ __nv_bfloat16 g_attn_hi[SEQ * 2048],   g_attn_lo[SEQ * 2048];
static __device__ __nv_bfloat16 g_qf_hi[NHEADS * SEQ * QKD], g_qf_lo[NHEADS * SEQ * QKD];
static __device__ __nv_bfloat16 g_k_hi[NHEADS * SEQ * QKD],  g_k_lo[NHEADS * SEQ * QKD];
static __device__ __nv_bfloat16 g_v_hi[NHEADS * SEQ * VDIM], g_v_lo[NHEADS * SEQ * VDIM];

static __device__ __nv_bfloat16 g_wqkva_hi[QKVN * HIDDEN], g_wqkva_lo[QKVN * HIDDEN];
static __device__ __nv_bfloat16 g_wqb_hi[3072 * QLORA],    g_wqb_lo[3072 * QLORA];
static __device__ __nv_bfloat16 g_wkvb_hi[4096 * KVLORA],  g_wkvb_lo[4096 * KVLORA];
static __device__ __nv_bfloat16 g_wo_hi[HIDDEN * 2048],    g_wo_lo[HIDDEN * 2048];

// ---------------- helpers ----------------------------------------------------
__device__ __forceinline__ uint32_t smem_u32(const void* p) {
    return (uint32_t)__cvta_generic_to_shared(p);
}
__device__ __forceinline__ void cpa16(uint32_t dst, const void* src, int sz) {
    asm volatile("cp.async.cg.shared.global [%0], [%1], 16, %2;"
                 :: "r"(dst), "l"(src), "r"(sz) : "memory");
}
#define CP_COMMIT() asm volatile("cp.async.commit_group;" ::: "memory")
#define CP_WAIT(n)  asm volatile("cp.async.wait_group %0;" :: "n"(n) : "memory")

__device__ __forceinline__ void ldsm4(uint32_t& r0, uint32_t& r1, uint32_t& r2, uint32_t& r3,
                                      uint32_t addr) {
    asm volatile("ldmatrix.sync.aligned.m8n8.x4.shared.b16 {%0,%1,%2,%3}, [%4];"
                 : "=r"(r0), "=r"(r1), "=r"(r2), "=r"(r3) : "r"(addr));
}
__device__ __forceinline__ void ldsm4t(uint32_t& r0, uint32_t& r1, uint32_t& r2, uint32_t& r3,
                                       uint32_t addr) {
    asm volatile("ldmatrix.sync.aligned.m8n8.x4.trans.shared.b16 {%0,%1,%2,%3}, [%4];"
                 : "=r"(r0), "=r"(r1), "=r"(r2), "=r"(r3) : "r"(addr));
}
__device__ __forceinline__ void mma16816(float* c, uint32_t a0, uint32_t a1, uint32_t a2,
                                         uint32_t a3, uint32_t b0, uint32_t b1) {
    asm volatile(
        "mma.sync.aligned.m16n8k16.row.col.f32.bf16.bf16.f32 "
        "{%0,%1,%2,%3}, {%4,%5,%6,%7}, {%8,%9}, {%0,%1,%2,%3};"
        : "+f"(c[0]), "+f"(c[1]), "+f"(c[2]), "+f"(c[3])
        : "r"(a0), "r"(a1), "r"(a2), "r"(a3), "r"(b0), "r"(b1));
}
__device__ __forceinline__ void split2(float v0, float v1, uint32_t& hi, uint32_t& lo) {
    __nv_bfloat16 h0 = __float2bfloat16(v0), h1 = __float2bfloat16(v1);
    float r0 = v0 - __bfloat162float(h0), r1 = v1 - __bfloat162float(h1);
    __nv_bfloat162 th; th.x = h0; th.y = h1;
    hi = *reinterpret_cast<uint32_t*>(&th);
    __nv_bfloat162 tl; tl.x = __float2bfloat16(r0); tl.y = __float2bfloat16(r1);
    lo = *reinterpret_cast<uint32_t*>(&tl);
}
__device__ __forceinline__ void split1(float v, __nv_bfloat16* hp, __nv_bfloat16* lp) {
    __nv_bfloat16 h = __float2bfloat16(v);
    *hp = h;
    *lp = __float2bfloat16(v - __bfloat162float(h));
}

// ---------------- rope cos/sin table ------------------------------------------
__global__ void rope_tab(const int* __restrict__ pos_ids) {
    int idx = blockIdx.x * blockDim.x + threadIdx.x;   // s*32+j
    if (idx >= SEQ * 32) return;
    int s = idx >> 5, j = idx & 31;
    double invf = exp(-(double)j * 0.28782313662425575);
    double ang = (double)pos_ids[s] * invf;
    g_rtab[idx] = make_float2((float)cos(ang), (float)sin(ang));
}

// ---------------- batched fp32 -> bf16 hi/lo converter ------------------------
__global__ void cvt_b16_multi(
    const float* __restrict__ x0, __nv_bfloat16* __restrict__ h0, __nv_bfloat16* __restrict__ l0, long c0,
    const float* __restrict__ x1, __nv_bfloat16* __restrict__ h1, __nv_bfloat16* __restrict__ l1, long c1,
    const float* __restrict__ x2, __nv_bfloat16* __restrict__ h2, __nv_bfloat16* __restrict__ l2, long c2,
    const float* __restrict__ x3, __nv_bfloat16* __restrict__ h3, __nv_bfloat16* __restrict__ l3, long c3,
    const float* __restrict__ x4, __nv_bfloat16* __restrict__ h4, __nv_bfloat16* __restrict__ l4, long c4)
{
    for (long i = (long)blockIdx.x * blockDim.x + threadIdx.x; i < c4;
         i += (long)gridDim.x * blockDim.x) {
        const float4* xp; __nv_bfloat162* hp; __nv_bfloat162* lp; long base;
        if (i < c0)      { xp = (const float4*)x0; hp = (__nv_bfloat162*)h0; lp = (__nv_bfloat162*)l0; base = 0; }
        else if (i < c1) { xp = (const float4*)x1; hp = (__nv_bfloat162*)h1; lp = (__nv_bfloat162*)l1; base = c0; }
        else if (i < c2) { xp = (const float4*)x2; hp = (__nv_bfloat162*)h2; lp = (__nv_bfloat162*)l2; base = c1; }
        else if (i < c3) { xp = (const float4*)x3; hp = (__nv_bfloat162*)h3; lp = (__nv_bfloat162*)l3; base = c2; }
        else             { xp = (const float4*)x4; hp = (__nv_bfloat162*)h4; lp = (__nv_bfloat162*)l4; base = c3; }
        long j = i - base;
        float4 v = xp[j];
        __nv_bfloat162 ha; ha.x = __float2bfloat16(v.x); ha.y = __float2bfloat16(v.y);
        __nv_bfloat162 hb; hb.x = __float2bfloat16(v.z); hb.y = __float2bfloat16(v.w);
        __nv_bfloat162 la; la.x = __float2bfloat16(v.x - __bfloat162float(ha.x));
        la.y = __float2bfloat16(v.y - __bfloat162float(ha.y));
        __nv_bfloat162 lb; lb.x = __float2bfloat16(v.z - __bfloat162float(hb.x));
        lb.y = __float2bfloat16(v.w - __bfloat162float(hb.y));
        hp[2 * j] = ha; hp[2 * j + 1] = hb;
        lp[2 * j] = la; lp[2 * j + 1] = lb;
    }
}

__global__ void rmsnorm_b16(const float* __restrict__ x, const float* __restrict__ w,
                            __nv_bfloat16* __restrict__ hi, __nv_bfloat16* __restrict__ lo,
                            int cols, int strideIn, int strideOut)
{
    int row = blockIdx.x;
    int t = threadIdx.x;
    const float4* xr = (const float4*)(x + (long)row * strideIn);
    const float4* w4 = (const float4*)w;
    int c4 = cols >> 2;
    float ss = 0.f;
    for (int c = t; c < c4; c += 256) {
        float4 v = xr[c];
        ss = fmaf(v.x, v.x, fmaf(v.y, v.y, fmaf(v.z, v.z, fmaf(v.w, v.w, ss))));
    }
    __shared__ float red[256];
    red[t] = ss; __syncthreads();
    for (int s = 128; s > 0; s >>= 1) { if (t < s) red[t] += red[t + s]; __syncthreads(); }
    float scale = rsqrtf(red[0] / (float)cols + 1e-6f);
    __nv_bfloat162* hr = (__nv_bfloat162*)(hi + (long)row * strideOut);
    __nv_bfloat162* lr = (__nv_bfloat162*)(lo + (long)row * strideOut);
    for (int c = t; c < c4; c += 256) {
        float4 v = xr[c];
        float4 wv = w4[c];
        float a = v.x * scale * wv.x, b = v.y * scale * wv.y;
        float d = v.z * scale * wv.z, e = v.w * scale * wv.w;
        __nv_bfloat162 ha; ha.x = __float2bfloat16(a); ha.y = __float2bfloat16(b);
        __nv_bfloat162 hb; hb.x = __float2bfloat16(d); hb.y = __float2bfloat16(e);
        __nv_bfloat162 la; la.x = __float2bfloat16(a - __bfloat162float(ha.x));
        la.y = __float2bfloat16(b - __bfloat162float(ha.y));
        __nv_bfloat162 lb; lb.x = __float2bfloat16(d - __bfloat162float(hb.x));
        lb.y = __float2bfloat16(e - __bfloat162float(hb.y));
        hr[2 * c] = ha; hr[2 * c + 1] = hb;
        lr[2 * c] = la; lr[2 * c + 1] = lb;
    }
}

// rmsnorm of ckv (512 cols within 2112-stride rows) + fused k_pe rope scatter
__global__ void rmsnorm_ckv_kpe(const float* __restrict__ qackv, const float* __restrict__ w,
                                float* __restrict__ kout)
{
    int row = blockIdx.x;
    int t = threadIdx.x;
    const float* xrow = qackv + (long)row * QKVN + QLORA;
    const float4* xr = (const float4*)xrow;
    const float4* w4 = (const float4*)w;
    float ss = 0.f;
#pragma unroll
    for (int c = t; c < 128; c += 256) {
        float4 v = xr[c];
        ss = fmaf(v.x, v.x, fmaf(v.y, v.y, fmaf(v.z, v.z, fmaf(v.w, v.w, ss))));
    }
    __shared__ float red[256];
    __shared__ float kr[64];
    red[t] = ss; __syncthreads();
    for (int s = 128; s > 0; s >>= 1) { if (t < s) red[t] += red[t + s]; __syncthreads(); }
    float scale = rsqrtf(red[0] / 512.0f + 1e-6f);
    // k_pe rope (raw tail of qackv row)
    if (t < 32) {
        float2 cs = g_rtab[row * 32 + t];
        float x0 = xrow[512 + 2 * t];
        float x1 = xrow[512 + 2 * t + 1];
        kr[t]      = x0 * cs.x - x1 * cs.y;
        kr[32 + t] = x1 * cs.x + x0 * cs.y;
    }
    __nv_bfloat162* hr = (__nv_bfloat162*)(g_ckvn_hi + (long)row * KVLORA);
    __nv_bfloat162* lr = (__nv_bfloat162*)(g_ckvn_lo + (long)row * KVLORA);
#pragma unroll
    for (int c = t; c < 128; c += 256) {
        float4 v = xr[c];
        float4 wv = w4[c];
        float a = v.x * scale * wv.x, b = v.y * scale * wv.y;
        float d = v.z * scale * wv.z, e = v.w * scale * wv.w;
        __nv_bfloat162 ha; ha.x = __float2bfloat16(a); ha.y = __float2bfloat16(b);
        __nv_bfloat162 hb; hb.x = __float2bfloat16(d); hb.y = __float2bfloat16(e);
        __nv_bfloat162 la; la.x = __float2bfloat16(a - __bfloat162float(ha.x));
        la.y = __float2bfloat16(b - __bfloat162float(ha.y));
        __nv_bfloat162 lb; lb.x = __float2bfloat16(d - __bfloat162float(hb.x));
        lb.y = __float2bfloat16(e - __bfloat162float(hb.y));
        hr[2 * c] = ha; hr[2 * c + 1] = hb;
        lr[2 * c] = la; lr[2 * c + 1] = lb;
    }
    __syncthreads();
    // broadcast k_pe to all 16 heads (cols 128..191 of K)
    for (int idx = t; idx < 16 * 64; idx += 256) {
        int h = idx >> 6, d = idx & 63;
        float v = kr[d];
        long o = ((long)h * SEQ + row) * QKD + 128 + d;
        kout[o] = v;
        split1(v, &g_k_hi[o], &g_k_lo[o]);
    }
}

// ---------------- mma.sync bf16x3 GEMM: swizzled 64B rows, 3 stages -----------
#define GT_BYTES (128 * 64)         // 8192
#define GS_BYTES (4 * GT_BYTES)     // 32768 per stage
#define GSTAGES 3
#define GEMM_SMEM (GSTAGES * GS_BYTES)  // 98304; 2 CTAs/SM

__device__ __forceinline__ void g_fill(uint32_t dstBase, const __nv_bfloat16* __restrict__ src,
                                       long ld, int rmax, int t)
{
#pragma unroll
    for (int i = 0; i < 2; ++i) {
        int id = t + 256 * i;
        int row = id >> 2, c = id & 3;
        bool ok = row < rmax;
        const __nv_bfloat16* g = src + (long)(ok ? row : 0) * ld + c * 8;
        uint32_t cs = (uint32_t)(c ^ ((row >> 1) & 3));
        cpa16(dstBase + row * 64 + cs * 16, g, ok ? 16 : 0);
    }
}

// mode 0: C (+beta*D). mode 1: q scatter+rope -> g_qf. mode 2: kv scatter -> kout/vout + hi/lo.
__device__ __forceinline__ void gemm_core(
    const __nv_bfloat16* __restrict__ Ah, const __nv_bfloat16* __restrict__ Al, int lda,
    const __nv_bfloat16* __restrict__ Bh, const __nv_bfloat16* __restrict__ Bl,
    float* __restrict__ C, int M, int N, int K,
    const float* __restrict__ D, float beta, int bx, int by, char* smem,
    int mode, float* __restrict__ kout, float* __restrict__ vout)
{
    uint32_t sb = smem_u32(smem);
    int t = threadIdx.x;
    int warp = t >> 5, lane = t & 31;
    int wm = warp >> 2, wn = warp & 3;
    int n0 = bx * 128, m0 = by * 128;
    int nc = K / 32;

    float acc[4][4][4];
#pragma unroll
    for (int i = 0; i < 4; i++)
#pragma unroll
        for (int j = 0; j < 4; j++)
#pragma unroll
            for (int r = 0; r < 4; r++) acc[i][j][r] = 0.f;

#pragma unroll
    for (int s = 0; s < 2; ++s) {
        uint32_t b0 = sb + s * GS_BYTES;
        int kc0 = s * 32;
        g_fill(b0 + 0 * GT_BYTES, Ah + (long)m0 * lda + kc0, lda, M - m0, t);
        g_fill(b0 + 1 * GT_BYTES, Al + (long)m0 * lda + kc0, lda, M - m0, t);
        g_fill(b0 + 2 * GT_BYTES, Bh + (long)n0 * K + kc0, K, N - n0, t);
        g_fill(b0 + 3 * GT_BYTES, Bl + (long)n0 * K + kc0, K, N - n0, t);
        CP_COMMIT();
    }

    int aRow = wm * 64 + (lane & 15);
    int aCl = lane >> 4;
    int bRow = wn * 32 + (lane & 7) + ((lane >> 4) << 3);
    int bCl = (lane >> 3) & 1;

    int stage = 0;
    for (int c = 0; c < nc; ++c) {
        CP_WAIT(1);
        __syncthreads();
        if (c + 2 < nc) {
            int ps = stage + 2; if (ps >= GSTAGES) ps -= GSTAGES;
            uint32_t bn = sb + ps * GS_BYTES;
            int kc0 = (c + 2) * 32;
            g_fill(bn + 0 * GT_BYTES, Ah + (long)m0 * lda + kc0, lda, M - m0, t);
            g_fill(bn + 1 * GT_BYTES, Al + (long)m0 * lda + kc0, lda, M - m0, t);
            g_fill(bn + 2 * GT_BYTES, Bh + (long)n0 * K + kc0, K, N - n0, t);
            g_fill(bn + 3 * GT_BYTES, Bl + (long)n0 * K + kc0, K, N - n0, t);
        }
        CP_COMMIT();

        uint32_t base = sb + stage * GS_BYTES;
#pragma unroll
        for (int k16 = 0; k16 < 2; ++k16) {
            uint32_t ah[4][4], al_[4][4];
#pragma unroll
            for (int im = 0; im < 4; ++im) {
                int r = aRow + im * 16;
                uint32_t addr = base + r * 64 + (((k16 * 2 + aCl) ^ ((r >> 1) & 3)) << 4);
                ldsm4(ah[im][0], ah[im][1], ah[im][2], ah[im][3], addr);
                ldsm4(al_[im][0], al_[im][1], al_[im][2], al_[im][3], addr + GT_BYTES);
            }
            uint32_t bh[4][2], bl[4][2];
#pragma unroll
            for (int j2 = 0; j2 < 2; ++j2) {
                int r = bRow + j2 * 16;
                uint32_t addr = base + 2 * GT_BYTES + r * 64 +
                                (((k16 * 2 + bCl) ^ ((r >> 1) & 3)) << 4);
                uint32_t r0, r1, r2, r3;
                ldsm4(r0, r1, r2, r3, addr);
                bh[2 * j2][0] = r0; bh[2 * j2][1] = r1;
                bh[2 * j2 + 1][0] = r2; bh[2 * j2 + 1][1] = r3;
                ldsm4(r0, r1, r2, r3, addr + GT_BYTES);
                bl[2 * j2][0] = r0; bl[2 * j2][1] = r1;
                bl[2 * j2 + 1][0] = r2; bl[2 * j2 + 1][1] = r3;
            }
#pragma unroll
            for (int im = 0; im < 4; ++im)
#pragma unroll
                for (int jn = 0; jn < 4; ++jn) {
                    mma16816(acc[im][jn], ah[im][0], ah[im][1], ah[im][2], ah[im][3],
                             bh[jn][0], bh[jn][1]);
                    mma16816(acc[im][jn], ah[im][0], ah[im][1], ah[im][2], ah[im][3],
                             bl[jn][0], bl[jn][1]);
                    mma16816(acc[im][jn], al_[im][0], al_[im][1], al_[im][2], al_[im][3],
                             bh[jn][0], bh[jn][1]);
                }
        }
        if (++stage >= GSTAGES) stage = 0;
    }

#pragma unroll
    for (int im = 0; im < 4; ++im) {
        int row0 = m0 + wm * 64 + im * 16 + (lane >> 2);
#pragma unroll
        for (int jn = 0; jn < 4; ++jn) {
            int col = n0 + wn * 32 + jn * 8 + (lane & 3) * 2;
            if (col >= N) continue;
            if (mode == 0) {
                float2 v0 = make_float2(acc[im][jn][0], acc[im][jn][1]);
                float2 v1 = make_float2(acc[im][jn][2], acc[im][jn][3]);
                if (D) {
                    float2 d0 = *(const float2*)&D[(long)row0 * N + col];
                    float2 d1 = *(const float2*)&D[(long)(row0 + 8) * N + col];
                    v0.x = fmaf(beta, d0.x, v0.x); v0.y = fmaf(beta, d0.y, v0.y);
                    v1.x = fmaf(beta, d1.x, v1.x); v1.y = fmaf(beta, d1.y, v1.y);
                }
                *(float2*)&C[(long)row0 * N + col] = v0;
                *(float2*)&C[(long)(row0 + 8) * N + col] = v1;
            } else if (mode == 1) {
                int head = col / QKD, d = col - head * QKD;
#pragma unroll
                for (int rr = 0; rr < 2; ++rr) {
                    int row = row0 + rr * 8;
                    float x0 = acc[im][jn][2 * rr], x1 = acc[im][jn][2 * rr + 1];
                    long ob = ((long)head * SEQ + row) * QKD;
                    if (d < 128) {
                        uint32_t hi, lo;
                        split2(x0, x1, hi, lo);
                        *(uint32_t*)&g_qf_hi[ob + d] = hi;
                        *(uint32_t*)&g_qf_lo[ob + d] = lo;
                    } else {
                        int j = (d - 128) >> 1;
                        float2 cs = g_rtab[row * 32 + j];
                        float a = x0 * cs.x - x1 * cs.y;
                        float b = x1 * cs.x + x0 * cs.y;
                        split1(a, &g_qf_hi[ob + 128 + j], &g_qf_lo[ob + 128 + j]);
                        split1(b, &g_qf_hi[ob + 160 + j], &g_qf_lo[ob + 160 + j]);
                    }
                }
            } else {
                int head = col >> 8, d = col & 255;
#pragma unroll
                for (int rr = 0; rr < 2; ++rr) {
                    int row = row0 + rr * 8;
                    float x0 = acc[im][jn][2 * rr], x1 = acc[im][jn][2 * rr + 1];
                    uint32_t hi, lo;
                    split2(x0, x1, hi, lo);
                    if (d < 128) {
                        long o = ((long)head * SEQ + row) * QKD + d;
                        *(float2*)&kout[o] = make_float2(x0, x1);
                        *(uint32_t*)&g_k_hi[o] = hi;
                        *(uint32_t*)&g_k_lo[o] = lo;
                    } else {
                        long o = ((long)head * SEQ + row) * VDIM + (d - 128);
                        *(float2*)&vout[o] = make_float2(x0, x1);
                        *(uint32_t*)&g_v_hi[o] = hi;
                        *(uint32_t*)&g_v_lo[o] = lo;
                    }
                }
            }
        }
    }
}

__global__ __launch_bounds__(256, 2)
void gemm_mma(const __nv_bfloat16* __restrict__ Ah, const __nv_bfloat16* __restrict__ Al, int lda,
              const __nv_bfloat16* __restrict__ Bh, const __nv_bfloat16* __restrict__ Bl,
              float* __restrict__ C, int M, int N, int K,
              const float* __restrict__ D, float beta)
{
    extern __shared__ __align__(128) char smem[];
    gemm_core(Ah, Al, lda, Bh, Bl, C, M, N, K, D, beta, blockIdx.x, blockIdx.y, smem,
              0, nullptr, nullptr);
}

// job1: q up-proj (mode 1), job2: kv up-proj (mode 2)
__global__ __launch_bounds__(256, 2)
void gemm_dual(const __nv_bfloat16* __restrict__ A1h, const __nv_bfloat16* __restrict__ A1l,
               const __nv_bfloat16* __restrict__ B1h, const __nv_bfloat16* __restrict__ B1l,
               const __nv_bfloat16* __restrict__ A2h, const __nv_bfloat16* __restrict__ A2l,
               const __nv_bfloat16* __restrict__ B2h, const __nv_bfloat16* __restrict__ B2l,
               float* __restrict__ kout, float* __restrict__ vout, int split)
{
    extern __shared__ __align__(128) char smem[];
    if ((int)blockIdx.x < split)
        gemm_core(A1h, A1l, QLORA, B1h, B1l, nullptr, SEQ, 3072, QLORA, nullptr, 0.f,
                  blockIdx.x, blockIdx.y, smem, 1, nullptr, nullptr);
    else
        gemm_core(A2h, A2l, KVLORA, B2h, B2l, nullptr, SEQ, 4096, KVLORA, nullptr, 0.f,
                  blockIdx.x - split, blockIdx.y, smem, 2, kout, vout);
}

// ---------------- flash attention: 128-row Q tile, 32-key stages --------------
#define FPADB 400
#define VPADB 272
#define QT_B (128 * FPADB)
#define KT_B (32 * FPADB)
#define VT_B (32 * VPADB)
#define KV_BASE (2 * QT_B)
#define KV_STAGE (2 * KT_B + 2 * VT_B)
#define FLASH_SMEM (KV_BASE + 2 * KV_STAGE)  // 188416

__device__ __forceinline__ void f_fill_kv(uint32_t dst,
                                          const __nv_bfloat16* __restrict__ Kh,
                                          const __nv_bfloat16* __restrict__ Kl,
                                          const __nv_bfloat16* __restrict__ Vh,
                                          const __nv_bfloat16* __restrict__ Vl,
                                          long k0, int t)
{
#pragma unroll
    for (int i = 0; i < 3; ++i) {
        int id = t + 256 * i;
        int row = id / 24, ch = id % 24;
        cpa16(dst + row * FPADB + ch * 16, Kh + (k0 + row) * 192 + ch * 8, 16);
        cpa16(dst + KT_B + row * FPADB + ch * 16, Kl + (k0 + row) * 192 + ch * 8, 16);
    }
#pragma unroll
    for (int i = 0; i < 2; ++i) {
        int id = t + 256 * i;
        int row = id >> 4, ch = id & 15;
        cpa16(dst + 2 * KT_B + row * VPADB + ch * 16, Vh + (k0 + row) * 128 + ch * 8, 16);
        cpa16(dst + 2 * KT_B + VT_B + row * VPADB + ch * 16, Vl + (k0 + row) * 128 + ch * 8, 16);
    }
}

__global__ __launch_bounds__(256, 1)
void flash_mma(const __nv_bfloat16* __restrict__ Qh_g, const __nv_bfloat16* __restrict__ Ql_g,
               const __nv_bfloat16* __restrict__ Kh_g, const __nv_bfloat16* __restrict__ Kl_g,
               const __nv_bfloat16* __restrict__ Vh_g, const __nv_bfloat16* __restrict__ Vl_g,
               __nv_bfloat16* __restrict__ Oh_g, __nv_bfloat16* __restrict__ Ol_g)
{
    extern __shared__ __align__(128) char smem[];
    uint32_t sb = smem_u32(smem);
    int qt = (int)gridDim.x - 1 - (int)blockIdx.x;
    int h = blockIdx.y;
    int q0 = qt * 128;
    int t = threadIdx.x;
    int warp = t >> 5, lane = t & 31;

    const __nv_bfloat16* Kgh = Kh_g + (long)h * SEQ * 192;
    const __nv_bfloat16* Kgl = Kl_g + (long)h * SEQ * 192;
    const __nv_bfloat16* Vgh = Vh_g + (long)h * SEQ * 128;
    const __nv_bfloat16* Vgl = Vl_g + (long)h * SEQ * 128;

    {
        const __nv_bfloat16* qg = Qh_g + ((long)h * SEQ + q0) * 192;
        const __nv_bfloat16* qg2 = Ql_g + ((long)h * SEQ + q0) * 192;
#pragma unroll
        for (int i = 0; i < 12; ++i) {
            int id = t + 256 * i;
            int row = id / 24, ch = id % 24;
            cpa16(sb + row * FPADB + ch * 16, qg + (long)row * 192 + ch * 8, 16);
            cpa16(sb + QT_B + row * FPADB + ch * 16, qg2 + (long)row * 192 + ch * 8, 16);
        }
        CP_COMMIT();
    }
    f_fill_kv(sb + KV_BASE, Kgh, Kgl, Vgh, Vgl, 0, t);
    CP_COMMIT();

    float o[16][4];
#pragma unroll
    for (int i = 0; i < 16; i++)
#pragma unroll
        for (int r = 0; r < 4; r++) o[i][r] = 0.f;
    float mrow[2] = {-1e30f, -1e30f};
    float lrow[2] = {0.f, 0.f};

    uint32_t qoff = (uint32_t)((warp * 16 + (lane & 15)) * FPADB + (lane >> 4) * 16);
    uint32_t koff = (uint32_t)(((lane & 7) + ((lane >> 4) << 3)) * FPADB +
                               ((lane >> 3) & 1) * 16);
    uint32_t voff = (uint32_t)(((lane & 7) + (((lane >> 3) & 1) << 3)) * VPADB +
                               ((lane >> 4) << 3) * 2);

    int rA = (lane >> 2);
    int colq = (lane & 3) * 2;
    int rowA = q0 + warp * 16 + rA;
    int rowB = rowA + 8;
    int nkt = 4 * qt + 4;

    for (int kt = 0; kt < nkt; ++kt) {
        __syncthreads();
        if (kt + 1 < nkt)
            f_fill_kv(sb + KV_BASE + ((kt + 1) & 1) * KV_STAGE, Kgh, Kgl, Vgh, Vgl,
                      (long)(kt + 1) * 32, t);
        CP_COMMIT();
        CP_WAIT(1);
        __syncthreads();

        int k0 = kt * 32;
        uint32_t kvb = sb + KV_BASE + (kt & 1) * KV_STAGE;

        float sc[4][4];
#pragma unroll
        for (int j = 0; j < 4; j++)
#pragma unroll
            for (int r = 0; r < 4; r++) sc[j][r] = 0.f;

#pragma unroll 1
        for (int k16 = 0; k16 < 12; ++k16) {
            uint32_t qfh[4], qfl[4];
            uint32_t addr = sb + qoff + k16 * 32;
            ldsm4(qfh[0], qfh[1], qfh[2], qfh[3], addr);
            ldsm4(qfl[0], qfl[1], qfl[2], qfl[3], addr + QT_B);
            uint32_t kbh[4][2], kbl[4][2];
#pragma unroll
            for (int j2 = 0; j2 < 2; ++j2) {
                uint32_t ka = kvb + koff + j2 * 16 * FPADB + k16 * 32;
                uint32_t r0, r1, r2, r3;
                ldsm4(r0, r1, r2, r3, ka);
                kbh[2 * j2][0] = r0; kbh[2 * j2][1] = r1;
                kbh[2 * j2 + 1][0] = r2; kbh[2 * j2 + 1][1] = r3;
                ldsm4(r0, r1, r2, r3, ka + KT_B);
                kbl[2 * j2][0] = r0; kbl[2 * j2][1] = r1;
                kbl[2 * j2 + 1][0] = r2; kbl[2 * j2 + 1][1] = r3;
            }
#pragma unroll
            for (int j = 0; j < 4; ++j) {
                mma16816(sc[j], qfh[0], qfh[1], qfh[2], qfh[3], kbh[j][0], kbh[j][1]);
                mma16816(sc[j], qfh[0], qfh[1], qfh[2], qfh[3], kbl[j][0], kbl[j][1]);
                mma16816(sc[j], qfl[0], qfl[1], qfl[2], qfl[3], kbh[j][0], kbh[j][1]);
            }
        }

        bool diag = (kt >= 4 * qt);
#pragma unroll
        for (int j = 0; j < 4; ++j) {
#pragma unroll
            for (int r = 0; r < 4; r++) sc[j][r] *= SM_SCALE;
            if (diag) {
                int col = k0 + j * 8 + colq;
                if (col > rowA)     sc[j][0] = -1e30f;
                if (col + 1 > rowA) sc[j][1] = -1e30f;
                if (col > rowB)     sc[j][2] = -1e30f;
                if (col + 1 > rowB) sc[j][3] = -1e30f;
            }
        }
        float mxa = -1e30f, mxb = -1e30f;
#pragma unroll
        for (int j = 0; j < 4; ++j) {
            mxa = fmaxf(mxa, fmaxf(sc[j][0], sc[j][1]));
            mxb = fmaxf(mxb, fmaxf(sc[j][2], sc[j][3]));
        }
        mxa = fmaxf(mxa, __shfl_xor_sync(0xffffffffu, mxa, 1));
        mxa = fmaxf(mxa, __shfl_xor_sync(0xffffffffu, mxa, 2));
        mxb = fmaxf(mxb, __shfl_xor_sync(0xffffffffu, mxb, 1));
        mxb = fmaxf(mxb, __shfl_xor_sync(0xffffffffu, mxb, 2));
        float mna = fmaxf(mrow[0], mxa), mnb = fmaxf(mrow[1], mxb);
        float ala = __expf(mrow[0] - mna), alb = __expf(mrow[1] - mnb);
        mrow[0] = mna; mrow[1] = mnb;

        float suma = 0.f, sumb = 0.f;
#pragma unroll
        for (int j = 0; j < 4; ++j) {
            sc[j][0] = __expf(sc[j][0] - mna);
            sc[j][1] = __expf(sc[j][1] - mna);
            sc[j][2] = __expf(sc[j][2] - mnb);
            sc[j][3] = __expf(sc[j][3] - mnb);
            suma += sc[j][0] + sc[j][1];
            sumb += sc[j][2] + sc[j][3];
        }
        suma += __shfl_xor_sync(0xffffffffu, suma, 1);
        suma += __shfl_xor_sync(0xffffffffu, suma, 2);
        sumb += __shfl_xor_sync(0xffffffffu, sumb, 1);
        sumb += __shfl_xor_sync(0xffffffffu, sumb, 2);
        lrow[0] = lrow[0] * ala + suma;
        lrow[1] = lrow[1] * alb + sumb;
#pragma unroll
        for (int nb = 0; nb < 16; ++nb) {
            o[nb][0] *= ala; o[nb][1] *= ala;
            o[nb][2] *= alb; o[nb][3] *= alb;
        }

        uint32_t pah[2][4], pal[2][4];
#pragma unroll
        for (int j = 0; j < 2; ++j) {
            split2(sc[2 * j][0],     sc[2 * j][1],     pah[j][0], pal[j][0]);
            split2(sc[2 * j][2],     sc[2 * j][3],     pah[j][1], pal[j][1]);
            split2(sc[2 * j + 1][0], sc[2 * j + 1][1], pah[j][2], pal[j][2]);
            split2(sc[2 * j + 1][2], sc[2 * j + 1][3], pah[j][3], pal[j][3]);
        }

        uint32_t vbase = kvb + 2 * KT_B;
#pragma unroll 1
        for (int j = 0; j < 2; ++j) {
#pragma unroll
            for (int nb2 = 0; nb2 < 8; ++nb2) {
                uint32_t va = vbase + voff + j * 16 * VPADB + nb2 * 32;
                uint32_t h0, h1, h2, h3, l0, l1, l2, l3;
                ldsm4t(h0, h1, h2, h3, va);
                ldsm4t(l0, l1, l2, l3, va + VT_B);
                mma16816(o[2 * nb2],     pah[j][0], pah[j][1], pah[j][2], pah[j][3], h0, h1);
                mma16816(o[2 * nb2],     pah[j][0], pah[j][1], pah[j][2], pah[j][3], l0, l1);
                mma16816(o[2 * nb2],     pal[j][0], pal[j][1], pal[j][2], pal[j][3], h0, h1);
                mma16816(o[2 * nb2 + 1], pah[j][0], pah[j][1], pah[j][2], pah[j][3], h2, h3);
                mma16816(o[2 * nb2 + 1], pah[j][0], pah[j][1], pah[j][2], pah[j][3], l2, l3);
                mma16816(o[2 * nb2 + 1], pal[j][0], pal[j][1], pal[j][2], pal[j][3], h2, h3);
            }
        }
    }

    float inva = 1.0f / lrow[0], invb = 1.0f / lrow[1];
#pragma unroll
    for (int nb = 0; nb < 16; ++nb) {
        int col = h * 128 + nb * 8 + colq;
        uint32_t hA, lA, hB, lB;
        split2(o[nb][0] * inva, o[nb][1] * inva, hA, lA);
        split2(o[nb][2] * invb, o[nb][3] * invb, hB, lB);
        *(uint32_t*)&Oh_g[(long)rowA * 2048 + col] = hA;
        *(uint32_t*)&Ol_g[(long)rowA * 2048 + col] = lA;
        *(uint32_t*)&Oh_g[(long)rowB * 2048 + col] = hB;
        *(uint32_t*)&Ol_g[(long)rowB * 2048 + col] = lB;
    }
}

// ---------------- launch ------------------------------------------------------
extern "C" void kernel_launch(void* const* d_in, const int* in_sizes, int n_in,
                              void* d_out, int out_size)
{
    const float* hidden   = (const float*)d_in[0];
    const int*   pos      = (const int*)d_in[1];
    const float* ln_w     = (const float*)d_in[3];
    const float* wq_a     = (const float*)d_in[4];
    const float* q_a_ln   = (const float*)d_in[5];
    const float* wq_b     = (const float*)d_in[6];
    const float* wkv_a    = (const float*)d_in[7];
    const float* kv_a_ln  = (const float*)d_in[8];
    const float* wkv_b    = (const float*)d_in[9];
    const float* wo       = (const float*)d_in[10];

    float* out   = (float*)d_out;
    float* k_out = out + (long)SEQ * HIDDEN;
    float* v_out = k_out + (long)NHEADS * SEQ * QKD;

    float* p_qackv;
    cudaGetSymbolAddress((void**)&p_qackv, g_qackv);

    __nv_bfloat16 *h_hi, *h_lo, *qa_hi, *qa_lo, *ckvn_hi, *ckvn_lo, *attn_hi, *attn_lo;
    __nv_bfloat16 *qf_hi, *qf_lo, *k_hi, *k_lo, *v_hi, *v_lo;
    __nv_bfloat16 *wqkva_hi, *wqkva_lo, *wqb_hi, *wqb_lo, *wkvb_hi, *wkvb_lo, *wo_hi, *wo_lo;
    cudaGetSymbolAddress((void**)&h_hi, g_h_hi);       cudaGetSymbolAddress((void**)&h_lo, g_h_lo);
    cudaGetSymbolAddress((void**)&qa_hi, g_qa_hi);     cudaGetSymbolAddress((void**)&qa_lo, g_qa_lo);
    cudaGetSymbolAddress((void**)&ckvn_hi, g_ckvn_hi); cudaGetSymbolAddress((void**)&ckvn_lo, g_ckvn_lo);
    cudaGetSymbolAddress((void**)&attn_hi, g_attn_hi); cudaGetSymbolAddress((void**)&attn_lo, g_attn_lo);
    cudaGetSymbolAddress((void**)&qf_hi, g_qf_hi);     cudaGetSymbolAddress((void**)&qf_lo, g_qf_lo);
    cudaGetSymbolAddress((void**)&k_hi, g_k_hi);       cudaGetSymbolAddress((void**)&k_lo, g_k_lo);
    cudaGetSymbolAddress((void**)&v_hi, g_v_hi);       cudaGetSymbolAddress((void**)&v_lo, g_v_lo);
    cudaGetSymbolAddress((void**)&wqkva_hi, g_wqkva_hi); cudaGetSymbolAddress((void**)&wqkva_lo, g_wqkva_lo);
    cudaGetSymbolAddress((void**)&wqb_hi, g_wqb_hi);   cudaGetSymbolAddress((void**)&wqb_lo, g_wqb_lo);
    cudaGetSymbolAddress((void**)&wkvb_hi, g_wkvb_hi); cudaGetSymbolAddress((void**)&wkvb_lo, g_wkvb_lo);
    cudaGetSymbolAddress((void**)&wo_hi, g_wo_hi);     cudaGetSymbolAddress((void**)&wo_lo, g_wo_lo);

    cudaFuncSetAttribute(gemm_mma, cudaFuncAttributeMaxDynamicSharedMemorySize, GEMM_SMEM);
    cudaFuncSetAttribute(gemm_dual, cudaFuncAttributeMaxDynamicSharedMemorySize, GEMM_SMEM);
    cudaFuncSetAttribute(flash_mma, cudaFuncAttributeMaxDynamicSharedMemorySize, FLASH_SMEM);

    long c0 = (long)QLORA * HIDDEN / 4;
    long c1 = c0 + (long)576 * HIDDEN / 4;
    long c2 = c1 + (long)3072 * QLORA / 4;
    long c3 = c2 + (long)4096 * KVLORA / 4;
    long c4 = c3 + (long)HIDDEN * 2048 / 4;
    cvt_b16_multi<<<1184, 256>>>(
        wq_a,  wqkva_hi, wqkva_lo, c0,
        wkv_a, wqkva_hi + (long)QLORA * HIDDEN, wqkva_lo + (long)QLORA * HIDDEN, c1,
        wq_b,  wqb_hi,  wqb_lo,  c2,
        wkv_b, wkvb_hi, wkvb_lo, c3,
        wo,    wo_hi,   wo_lo,   c4);

    rope_tab<<<(SEQ * 32 + 255) / 256, 256>>>(pos);
    rmsnorm_b16<<<SEQ, 256>>>(hidden, ln_w, h_hi, h_lo, HIDDEN, HIDDEN, HIDDEN);
    gemm_mma<<<dim3(17, SEQ / 128), 256, GEMM_SMEM>>>(
        h_hi, h_lo, HIDDEN, wqkva_hi, wqkva_lo, p_qackv, SEQ, QKVN, HIDDEN, nullptr, 0.f);
    rmsnorm_b16<<<SEQ, 256>>>(p_qackv, q_a_ln, qa_hi, qa_lo, QLORA, QKVN, QLORA);
    rmsnorm_ckv_kpe<<<SEQ, 256>>>(p_qackv, kv_a_ln, k_out);
    // q up-proj (mode1: rope+scatter) + kv up-proj (mode2: K/V scatter)
    gemm_dual<<<dim3(24 + 32, SEQ / 128), 256, GEMM_SMEM>>>(
        qa_hi, qa_lo, wqb_hi, wqb_lo,
        ckvn_hi, ckvn_lo, wkvb_hi, wkvb_lo, k_out, v_out, 24);
    flash_mma<<<dim3(SEQ / 128, NHEADS), 256, FLASH_SMEM>>>(
        qf_hi, qf_lo, k_hi, k_lo, v_hi, v_lo, attn_hi, attn_lo);
    gemm_mma<<<dim3(HIDDEN / 128, SEQ / 128), 256, GEMM_SMEM>>>(
        attn_hi, attn_lo, 2048, wo_hi, wo_lo, out, SEQ, HIDDEN, 2048,
        hidden, RESID_SCALE);
}

// round 9
// speedup vs baseline: 1.5128x; 1.5128x over previous
#include <cuda_runtime.h>
#include <cuda_bf16.h>
#include <math.h>
#include <stdint.h>

#define HIDDEN 5120
#define NHEADS 16
#define QLORA  1536
#define KVLORA 512
#define NOPE   128
#define ROPE_D 64
#define QKD    192
#define VDIM   128
#define SEQ    2048
#define QKVN   2112
#define SM_SCALE 0.07216878364870322f  // 192^-0.5
#define RESID_SCALE 0.125f

// ---------------- scratch ----------------------------------------------------
static __device__ float g_qackv[SEQ * QKVN];
static __device__ float g_q[SEQ * NHEADS * QKD];
static __device__ float g_kv[SEQ * 4096];

static __device__ __nv_bfloat16 g_h_hi[SEQ * HIDDEN],    g_h_lo[SEQ * HIDDEN];
static __device__ __nv_bfloat16 g_qa_hi[SEQ * QLORA],    g_qa_lo[SEQ * QLORA];
static __device__ __nv_bfloat16 g_ckvn_hi[SEQ * KVLORA], g_ckvn_lo[SEQ * KVLORA];
static __device__ __nv_bfloat16 g_attn_hi[SEQ * 2048],   g_attn_lo[SEQ * 2048];
static __device__ __nv_bfloat16 g_qf_hi[NHEADS * SEQ * QKD], g_qf_lo[NHEADS * SEQ * QKD];
static __device__ __nv_bfloat16 g_k_hi[NHEADS * SEQ * QKD],  g_k_lo[NHEADS * SEQ * QKD];
static __device__ __nv_bfloat16 g_v_hi[NHEADS * SEQ * VDIM], g_v_lo[NHEADS * SEQ * VDIM];

static __device__ __nv_bfloat16 g_wqkva_hi[QKVN * HIDDEN], g_wqkva_lo[QKVN * HIDDEN];
static __device__ __nv_bfloat16 g_wqb_hi[3072 * QLORA],    g_wqb_lo[3072 * QLORA];
static __device__ __nv_bfloat16 g_wkvb_hi[4096 * KVLORA],  g_wkvb_lo[4096 * KVLORA];
static __device__ __nv_bfloat16 g_wo_hi[HIDDEN * 2048],    g_wo_lo[HIDDEN * 2048];

// ---------------- helpers ----------------------------------------------------
__device__ __forceinline__ uint32_t smem_u32(const void* p) {
    return (uint32_t)__cvta_generic_to_shared(p);
}
__device__ __forceinline__ void cpa16(uint32_t dst, const void* src, int sz) {
    asm volatile("cp.async.cg.shared.global [%0], [%1], 16, %2;"
                 :: "r"(dst), "l"(src), "r"(sz) : "memory");
}
#define CP_COMMIT() asm volatile("cp.async.commit_group;" ::: "memory")
#define CP_WAIT(n)  asm volatile("cp.async.wait_group %0;" :: "n"(n) : "memory")

__device__ __forceinline__ void ldsm4(uint32_t& r0, uint32_t& r1, uint32_t& r2, uint32_t& r3,
                                      uint32_t addr) {
    asm volatile("ldmatrix.sync.aligned.m8n8.x4.shared.b16 {%0,%1,%2,%3}, [%4];"
                 : "=r"(r0), "=r"(r1), "=r"(r2), "=r"(r3) : "r"(addr));
}
__device__ __forceinline__ void ldsm4t(uint32_t& r0, uint32_t& r1, uint32_t& r2, uint32_t& r3,
                                       uint32_t addr) {
    asm volatile("ldmatrix.sync.aligned.m8n8.x4.trans.shared.b16 {%0,%1,%2,%3}, [%4];"
                 : "=r"(r0), "=r"(r1), "=r"(r2), "=r"(r3) : "r"(addr));
}
__device__ __forceinline__ void mma16816(float* c, uint32_t a0, uint32_t a1, uint32_t a2,
                                         uint32_t a3, uint32_t b0, uint32_t b1) {
    asm volatile(
        "mma.sync.aligned.m16n8k16.row.col.f32.bf16.bf16.f32 "
        "{%0,%1,%2,%3}, {%4,%5,%6,%7}, {%8,%9}, {%0,%1,%2,%3};"
        : "+f"(c[0]), "+f"(c[1]), "+f"(c[2]), "+f"(c[3])
        : "r"(a0), "r"(a1), "r"(a2), "r"(a3), "r"(b0), "r"(b1));
}
__device__ __forceinline__ void split2(float v0, float v1, uint32_t& hi, uint32_t& lo) {
    __nv_bfloat16 h0 = __float2bfloat16(v0), h1 = __float2bfloat16(v1);
    float r0 = v0 - __bfloat162float(h0), r1 = v1 - __bfloat162float(h1);
    __nv_bfloat162 th; th.x = h0; th.y = h1;
    hi = *reinterpret_cast<uint32_t*>(&th);
    __nv_bfloat162 tl; tl.x = __float2bfloat16(r0); tl.y = __float2bfloat16(r1);
    lo = *reinterpret_cast<uint32_t*>(&tl);
}

// ---------------- batched fp32 -> bf16 hi/lo converter ------------------------
__global__ void cvt_b16_multi(
    const float* __restrict__ x0, __nv_bfloat16* __restrict__ h0, __nv_bfloat16* __restrict__ l0, long c0,
    const float* __restrict__ x1, __nv_bfloat16* __restrict__ h1, __nv_bfloat16* __restrict__ l1, long c1,
    const float* __restrict__ x2, __nv_bfloat16* __restrict__ h2, __nv_bfloat16* __restrict__ l2, long c2,
    const float* __restrict__ x3, __nv_bfloat16* __restrict__ h3, __nv_bfloat16* __restrict__ l3, long c3,
    const float* __restrict__ x4, __nv_bfloat16* __restrict__ h4, __nv_bfloat16* __restrict__ l4, long c4)
{
    for (long i = (long)blockIdx.x * blockDim.x + threadIdx.x; i < c4;
         i += (long)gridDim.x * blockDim.x) {
        const float4* xp; __nv_bfloat162* hp; __nv_bfloat162* lp; long base;
        if (i < c0)      { xp = (const float4*)x0; hp = (__nv_bfloat162*)h0; lp = (__nv_bfloat162*)l0; base = 0; }
        else if (i < c1) { xp = (const float4*)x1; hp = (__nv_bfloat162*)h1; lp = (__nv_bfloat162*)l1; base = c0; }
        else if (i < c2) { xp = (const float4*)x2; hp = (__nv_bfloat162*)h2; lp = (__nv_bfloat162*)l2; base = c1; }
        else if (i < c3) { xp = (const float4*)x3; hp = (__nv_bfloat162*)h3; lp = (__nv_bfloat162*)l3; base = c2; }
        else             { xp = (const float4*)x4; hp = (__nv_bfloat162*)h4; lp = (__nv_bfloat162*)l4; base = c3; }
        long j = i - base;
        float4 v = xp[j];
        __nv_bfloat162 ha; ha.x = __float2bfloat16(v.x); ha.y = __float2bfloat16(v.y);
        __nv_bfloat162 hb; hb.x = __float2bfloat16(v.z); hb.y = __float2bfloat16(v.w);
        __nv_bfloat162 la; la.x = __float2bfloat16(v.x - __bfloat162float(ha.x));
        la.y = __float2bfloat16(v.y - __bfloat162float(ha.y));
        __nv_bfloat162 lb; lb.x = __float2bfloat16(v.z - __bfloat162float(hb.x));
        lb.y = __float2bfloat16(v.w - __bfloat162float(hb.y));
        hp[2 * j] = ha; hp[2 * j + 1] = hb;
        lp[2 * j] = la; lp[2 * j + 1] = lb;
    }
}

__global__ void rmsnorm_b16(const float* __restrict__ x, const float* __restrict__ w,
                            __nv_bfloat16* __restrict__ hi, __nv_bfloat16* __restrict__ lo,
                            int cols, int strideIn, int strideOut)
{
    int row = blockIdx.x;
    int t = threadIdx.x;
    const float4* xr = (const float4*)(x + (long)row * strideIn);
    const float4* w4 = (const float4*)w;
    int c4 = cols >> 2;
    float ss = 0.f;
    for (int c = t; c < c4; c += 256) {
        float4 v = xr[c];
        ss = fmaf(v.x, v.x, fmaf(v.y, v.y, fmaf(v.z, v.z, fmaf(v.w, v.w, ss))));
    }
    __shared__ float red[256];
    red[t] = ss; __syncthreads();
    for (int s = 128; s > 0; s >>= 1) { if (t < s) red[t] += red[t + s]; __syncthreads(); }
    float scale = rsqrtf(red[0] / (float)cols + 1e-6f);
    __nv_bfloat162* hr = (__nv_bfloat162*)(hi + (long)row * strideOut);
    __nv_bfloat162* lr = (__nv_bfloat162*)(lo + (long)row * strideOut);
    for (int c = t; c < c4; c += 256) {
        float4 v = xr[c];
        float4 wv = w4[c];
        float a = v.x * scale * wv.x, b = v.y * scale * wv.y;
        float d = v.z * scale * wv.z, e = v.w * scale * wv.w;
        __nv_bfloat162 ha; ha.x = __float2bfloat16(a); ha.y = __float2bfloat16(b);
        __nv_bfloat162 hb; hb.x = __float2bfloat16(d); hb.y = __float2bfloat16(e);
        __nv_bfloat162 la; la.x = __float2bfloat16(a - __bfloat162float(ha.x));
        la.y = __float2bfloat16(b - __bfloat162float(ha.y));
        __nv_bfloat162 lb; lb.x = __float2bfloat16(d - __bfloat162float(hb.x));
        lb.y = __float2bfloat16(e - __bfloat162float(hb.y));
        hr[2 * c] = ha; hr[2 * c + 1] = hb;
        lr[2 * c] = la; lr[2 * c + 1] = lb;
    }
}

// ---------------- mma.sync bf16x3 GEMM: swizzled 64B rows, 3 stages -----------
#define GT_BYTES (128 * 64)         // 8192
#define GS_BYTES (4 * GT_BYTES)     // 32768 per stage
#define GSTAGES 3
#define GEMM_SMEM (GSTAGES * GS_BYTES)  // 98304; 2 CTAs/SM

__device__ __forceinline__ void g_fill(uint32_t dstBase, const __nv_bfloat16* __restrict__ src,
                                       long ld, int rmax, int t)
{
#pragma unroll
    for (int i = 0; i < 2; ++i) {
        int id = t + 256 * i;
        int row = id >> 2, c = id & 3;
        bool ok = row < rmax;
        const __nv_bfloat16* g = src + (long)(ok ? row : 0) * ld + c * 8;
        uint32_t cs = (uint32_t)(c ^ ((row >> 1) & 3));
        cpa16(dstBase + row * 64 + cs * 16, g, ok ? 16 : 0);
    }
}

__device__ __forceinline__ void gemm_core(
    const __nv_bfloat16* __restrict__ Ah, const __nv_bfloat16* __restrict__ Al, int lda,
    const __nv_bfloat16* __restrict__ Bh, const __nv_bfloat16* __restrict__ Bl,
    float* __restrict__ C, int M, int N, int K,
    const float* __restrict__ D, float beta, int bx, int by, char* smem)
{
    uint32_t sb = smem_u32(smem);
    int t = threadIdx.x;
    int warp = t >> 5, lane = t & 31;
    int wm = warp >> 2, wn = warp & 3;
    int n0 = bx * 128, m0 = by * 128;
    int nc = K / 32;

    float acc[4][4][4];
#pragma unroll
    for (int i = 0; i < 4; i++)
#pragma unroll
        for (int j = 0; j < 4; j++)
#pragma unroll
            for (int r = 0; r < 4; r++) acc[i][j][r] = 0.f;

#pragma unroll
    for (int s = 0; s < 2; ++s) {
        uint32_t b0 = sb + s * GS_BYTES;
        int kc0 = s * 32;
        g_fill(b0 + 0 * GT_BYTES, Ah + (long)m0 * lda + kc0, lda, M - m0, t);
        g_fill(b0 + 1 * GT_BYTES, Al + (long)m0 * lda + kc0, lda, M - m0, t);
        g_fill(b0 + 2 * GT_BYTES, Bh + (long)n0 * K + kc0, K, N - n0, t);
        g_fill(b0 + 3 * GT_BYTES, Bl + (long)n0 * K + kc0, K, N - n0, t);
        CP_COMMIT();
    }

    int aRow = wm * 64 + (lane & 15);
    int aCl = lane >> 4;
    int bRow = wn * 32 + (lane & 7) + ((lane >> 4) << 3);
    int bCl = (lane >> 3) & 1;

    int stage = 0;
    for (int c = 0; c < nc; ++c) {
        CP_WAIT(1);
        __syncthreads();
        if (c + 2 < nc) {
            int ps = stage + 2; if (ps >= GSTAGES) ps -= GSTAGES;
            uint32_t bn = sb + ps * GS_BYTES;
            int kc0 = (c + 2) * 32;
            g_fill(bn + 0 * GT_BYTES, Ah + (long)m0 * lda + kc0, lda, M - m0, t);
            g_fill(bn + 1 * GT_BYTES, Al + (long)m0 * lda + kc0, lda, M - m0, t);
            g_fill(bn + 2 * GT_BYTES, Bh + (long)n0 * K + kc0, K, N - n0, t);
            g_fill(bn + 3 * GT_BYTES, Bl + (long)n0 * K + kc0, K, N - n0, t);
        }
        CP_COMMIT();

        uint32_t base = sb + stage * GS_BYTES;
#pragma unroll
        for (int k16 = 0; k16 < 2; ++k16) {
            uint32_t ah[4][4], al_[4][4];
#pragma unroll
            for (int im = 0; im < 4; ++im) {
                int r = aRow + im * 16;
                uint32_t addr = base + r * 64 + (((k16 * 2 + aCl) ^ ((r >> 1) & 3)) << 4);
                ldsm4(ah[im][0], ah[im][1], ah[im][2], ah[im][3], addr);
                ldsm4(al_[im][0], al_[im][1], al_[im][2], al_[im][3], addr + GT_BYTES);
            }
            uint32_t bh[4][2], bl[4][2];
#pragma unroll
            for (int j2 = 0; j2 < 2; ++j2) {
                int r = bRow + j2 * 16;
                uint32_t addr = base + 2 * GT_BYTES + r * 64 +
                                (((k16 * 2 + bCl) ^ ((r >> 1) & 3)) << 4);
                uint32_t r0, r1, r2, r3;
                ldsm4(r0, r1, r2, r3, addr);
                bh[2 * j2][0] = r0; bh[2 * j2][1] = r1;
                bh[2 * j2 + 1][0] = r2; bh[2 * j2 + 1][1] = r3;
                ldsm4(r0, r1, r2, r3, addr + GT_BYTES);
                bl[2 * j2][0] = r0; bl[2 * j2][1] = r1;
                bl[2 * j2 + 1][0] = r2; bl[2 * j2 + 1][1] = r3;
            }
#pragma unroll
            for (int im = 0; im < 4; ++im)
#pragma unroll
                for (int jn = 0; jn < 4; ++jn) {
                    mma16816(acc[im][jn], ah[im][0], ah[im][1], ah[im][2], ah[im][3],
                             bh[jn][0], bh[jn][1]);
                    mma16816(acc[im][jn], ah[im][0], ah[im][1], ah[im][2], ah[im][3],
                             bl[jn][0], bl[jn][1]);
                    mma16816(acc[im][jn], al_[im][0], al_[im][1], al_[im][2], al_[im][3],
                             bh[jn][0], bh[jn][1]);
                }
        }
        if (++stage >= GSTAGES) stage = 0;
    }

#pragma unroll
    for (int im = 0; im < 4; ++im) {
        int row0 = m0 + wm * 64 + im * 16 + (lane >> 2);
#pragma unroll
        for (int jn = 0; jn < 4; ++jn) {
            int col = n0 + wn * 32 + jn * 8 + (lane & 3) * 2;
            if (col < N) {
                float2 v0 = make_float2(acc[im][jn][0], acc[im][jn][1]);
                float2 v1 = make_float2(acc[im][jn][2], acc[im][jn][3]);
                if (D) {
                    float2 d0 = *(const float2*)&D[(long)row0 * N + col];
                    float2 d1 = *(const float2*)&D[(long)(row0 + 8) * N + col];
                    v0.x = fmaf(beta, d0.x, v0.x); v0.y = fmaf(beta, d0.y, v0.y);
                    v1.x = fmaf(beta, d1.x, v1.x); v1.y = fmaf(beta, d1.y, v1.y);
                }
                *(float2*)&C[(long)row0 * N + col] = v0;
                *(float2*)&C[(long)(row0 + 8) * N + col] = v1;
            }
        }
    }
}

__global__ __launch_bounds__(256, 2)
void gemm_mma(const __nv_bfloat16* __restrict__ Ah, const __nv_bfloat16* __restrict__ Al, int lda,
              const __nv_bfloat16* __restrict__ Bh, const __nv_bfloat16* __restrict__ Bl,
              float* __restrict__ C, int M, int N, int K,
              const float* __restrict__ D, float beta)
{
    extern __shared__ __align__(128) char smem[];
    gemm_core(Ah, Al, lda, Bh, Bl, C, M, N, K, D, beta, blockIdx.x, blockIdx.y, smem);
}

__global__ __launch_bounds__(256, 2)
void gemm_dual(const __nv_bfloat16* __restrict__ A1h, const __nv_bfloat16* __restrict__ A1l,
               int lda1, const __nv_bfloat16* __restrict__ B1h,
               const __nv_bfloat16* __restrict__ B1l, float* __restrict__ C1, int N1, int K1,
               const __nv_bfloat16* __restrict__ A2h, const __nv_bfloat16* __restrict__ A2l,
               int lda2, const __nv_bfloat16* __restrict__ B2h,
               const __nv_bfloat16* __restrict__ B2l, float* __restrict__ C2, int N2, int K2,
               int split)
{
    extern __shared__ __align__(128) char smem[];
    if ((int)blockIdx.x < split)
        gemm_core(A1h, A1l, lda1, B1h, B1l, C1, SEQ, N1, K1, nullptr, 0.f,
                  blockIdx.x, blockIdx.y, smem);
    else
        gemm_core(A2h, A2l, lda2, B2h, B2l, C2, SEQ, N2, K2, nullptr, 0.f,
                  blockIdx.x - split, blockIdx.y, smem);
}

// ---------------- RoPE + scatter ----------------------------------------------
__global__ void rope_scatter(const float* __restrict__ qin,    // [s][3072]
                             const float* __restrict__ qackv,  // [s][2112]
                             const float* __restrict__ kvin,   // [s][4096]
                             const int* __restrict__ pos_ids,
                             __nv_bfloat16* __restrict__ qh, __nv_bfloat16* __restrict__ ql,
                             float* __restrict__ kout,
                             __nv_bfloat16* __restrict__ kh, __nv_bfloat16* __restrict__ kl,
                             float* __restrict__ vout,
                             __nv_bfloat16* __restrict__ vh, __nv_bfloat16* __restrict__ vl)
{
    int s = blockIdx.x;
    int t = threadIdx.x;
    __shared__ float cs[32], sn[32], kr[64];
    if (t < 32) {
        double invf = exp(-(double)t * 0.28782313662425575); // ln(10000)/32
        double ang = (double)pos_ids[s] * invf;
        cs[t] = (float)cos(ang);
        sn[t] = (float)sin(ang);
    }
    __syncthreads();
    if (t < 32) {
        float x0 = qackv[(long)s * QKVN + 2048 + 2 * t];
        float x1 = qackv[(long)s * QKVN + 2048 + 2 * t + 1];
        kr[t]      = x0 * cs[t] - x1 * sn[t];
        kr[32 + t] = x1 * cs[t] + x0 * sn[t];
    }
    __syncthreads();
    for (int idx = t; idx < 512; idx += 256) {
        int h = idx >> 5, j = idx & 31;
        const float* qb = qin + (long)s * 3072 + h * 192;
        float x0 = qb[128 + 2 * j], x1 = qb[128 + 2 * j + 1];
        float a = x0 * cs[j] - x1 * sn[j];
        float b = x1 * cs[j] + x0 * sn[j];
        long o = ((long)h * SEQ + s) * 192;
        __nv_bfloat16 ha = __float2bfloat16(a), hb = __float2bfloat16(b);
        qh[o + 128 + j] = ha; ql[o + 128 + j] = __float2bfloat16(a - __bfloat162float(ha));
        qh[o + 160 + j] = hb; ql[o + 160 + j] = __float2bfloat16(b - __bfloat162float(hb));
    }
    for (int idx = t; idx < 2048; idx += 256) {
        int h = idx >> 7, d = idx & 127;
        float v = qin[(long)s * 3072 + h * 192 + d];
        long o = ((long)h * SEQ + s) * 192 + d;
        __nv_bfloat16 hv = __float2bfloat16(v);
        qh[o] = hv; ql[o] = __float2bfloat16(v - __bfloat162float(hv));
    }
    for (int idx = t; idx < 16 * 192; idx += 256) {
        int h = idx / 192, d = idx - h * 192;
        float v = (d < 128) ? kvin[(long)s * 4096 + h * 256 + d] : kr[d - 128];
        long o = ((long)h * SEQ + s) * 192 + d;
        kout[o] = v;
        __nv_bfloat16 hv = __float2bfloat16(v);
        kh[o] = hv; kl[o] = __float2bfloat16(v - __bfloat162float(hv));
    }
    for (int idx = t; idx < 2048; idx += 256) {
        int h = idx >> 7, d = idx & 127;
        float v = kvin[(long)s * 4096 + h * 256 + 128 + d];
        long o = ((long)h * SEQ + s) * 128 + d;
        vout[o] = v;
        __nv_bfloat16 hv = __float2bfloat16(v);
        vh[o] = hv; vl[o] = __float2bfloat16(v - __bfloat162float(hv));
    }
}

// ---------------- flash attention: 64-row Q tile, 16-key stages, 2 CTA/SM -----
#define FPADB 400   // (192+8)*2 bytes per smem row (Q/K)
#define VPADB 272   // (128+8)*2 bytes per smem row (V)
#define F_QT (64 * FPADB)           // 25600
#define F_KT (16 * FPADB)           // 6400
#define F_VT (16 * VPADB)           // 4352
#define F_KVB (2 * F_QT)            // 51200
#define F_STG (2 * F_KT + 2 * F_VT) // 21504
#define FLASH_SMEM (F_KVB + 2 * F_STG)  // 94208 -> 2 CTAs/SM

__device__ __forceinline__ void f_fill_kv(uint32_t dst,
                                          const __nv_bfloat16* __restrict__ Kh,
                                          const __nv_bfloat16* __restrict__ Kl,
                                          const __nv_bfloat16* __restrict__ Vh,
                                          const __nv_bfloat16* __restrict__ Vl,
                                          long k0, int t)
{
#pragma unroll
    for (int i = 0; i < 3; ++i) {               // 384 ids: K 16 rows x 24 chunks
        int id = t + 128 * i;
        int row = id / 24, ch = id % 24;
        cpa16(dst + row * FPADB + ch * 16, Kh + (k0 + row) * 192 + ch * 8, 16);
        cpa16(dst + F_KT + row * FPADB + ch * 16, Kl + (k0 + row) * 192 + ch * 8, 16);
    }
#pragma unroll
    for (int i = 0; i < 2; ++i) {               // 256 ids: V 16 rows x 16 chunks
        int id = t + 128 * i;
        int row = id >> 4, ch = id & 15;
        cpa16(dst + 2 * F_KT + row * VPADB + ch * 16, Vh + (k0 + row) * 128 + ch * 8, 16);
        cpa16(dst + 2 * F_KT + F_VT + row * VPADB + ch * 16, Vl + (k0 + row) * 128 + ch * 8, 16);
    }
}

__global__ __launch_bounds__(128, 2)
void flash_mma(const __nv_bfloat16* __restrict__ Qh_g, const __nv_bfloat16* __restrict__ Ql_g,
               const __nv_bfloat16* __restrict__ Kh_g, const __nv_bfloat16* __restrict__ Kl_g,
               const __nv_bfloat16* __restrict__ Vh_g, const __nv_bfloat16* __restrict__ Vl_g,
               __nv_bfloat16* __restrict__ Oh_g, __nv_bfloat16* __restrict__ Ol_g)
{
    extern __shared__ __align__(128) char smem[];
    uint32_t sb = smem_u32(smem);
    int qt = (int)gridDim.x - 1 - (int)blockIdx.x;   // LPT: longest first
    int h = blockIdx.y;
    int q0 = qt * 64;
    int t = threadIdx.x;
    int warp = t >> 5, lane = t & 31;

    const __nv_bfloat16* Kgh = Kh_g + (long)h * SEQ * 192;
    const __nv_bfloat16* Kgl = Kl_g + (long)h * SEQ * 192;
    const __nv_bfloat16* Vgh = Vh_g + (long)h * SEQ * 128;
    const __nv_bfloat16* Vgl = Vl_g + (long)h * SEQ * 128;

    // Q tile 64 x 192 hi+lo
    {
        const __nv_bfloat16* qg = Qh_g + ((long)h * SEQ + q0) * 192;
        const __nv_bfloat16* qg2 = Ql_g + ((long)h * SEQ + q0) * 192;
#pragma unroll
        for (int i = 0; i < 12; ++i) {          // 1536 ids
            int id = t + 128 * i;
            int row = id / 24, ch = id % 24;
            cpa16(sb + row * FPADB + ch * 16, qg + (long)row * 192 + ch * 8, 16);
            cpa16(sb + F_QT + row * FPADB + ch * 16, qg2 + (long)row * 192 + ch * 8, 16);
        }
        CP_COMMIT();
    }
    f_fill_kv(sb + F_KVB, Kgh, Kgl, Vgh, Vgl, 0, t);
    CP_COMMIT();

    float o[16][4];
#pragma unroll
    for (int i = 0; i < 16; i++)
#pragma unroll
        for (int r = 0; r < 4; r++) o[i][r] = 0.f;
    float mrow[2] = {-1e30f, -1e30f};
    float lrow[2] = {0.f, 0.f};

    uint32_t qoff = (uint32_t)((warp * 16 + (lane & 15)) * FPADB + (lane >> 4) * 16);
    uint32_t koff = (uint32_t)(((lane & 7) + ((lane >> 4) << 3)) * FPADB +
                               ((lane >> 3) & 1) * 16);
    uint32_t voff = (uint32_t)(((lane & 7) + (((lane >> 3) & 1) << 3)) * VPADB +
                               ((lane >> 4) << 3) * 2);

    int rA = (lane >> 2);
    int colq = (lane & 3) * 2;
    int rowA = q0 + warp * 16 + rA;
    int rowB = rowA + 8;
    int nkt = 4 * qt + 4;   // 16-key tiles

    for (int kt = 0; kt < nkt; ++kt) {
        __syncthreads();
        if (kt + 1 < nkt)
            f_fill_kv(sb + F_KVB + ((kt + 1) & 1) * F_STG, Kgh, Kgl, Vgh, Vgl,
                      (long)(kt + 1) * 16, t);
        CP_COMMIT();
        CP_WAIT(1);
        __syncthreads();

        int k0 = kt * 16;
        uint32_t kvb = sb + F_KVB + (kt & 1) * F_STG;

        // ---- S = Q @ K^T : 16 rows x 16 keys per warp ----
        float sc[2][4];
#pragma unroll
        for (int j = 0; j < 2; j++)
#pragma unroll
            for (int r = 0; r < 4; r++) sc[j][r] = 0.f;

#pragma unroll 1
        for (int k16 = 0; k16 < 12; ++k16) {
            uint32_t qfh[4], qfl[4];
            uint32_t addr = sb + qoff + k16 * 32;
            ldsm4(qfh[0], qfh[1], qfh[2], qfh[3], addr);
            ldsm4(qfl[0], qfl[1], qfl[2], qfl[3], addr + F_QT);
            uint32_t kbh[2][2], kbl[2][2];
            {
                uint32_t ka = kvb + koff + k16 * 32;
                uint32_t r0, r1, r2, r3;
                ldsm4(r0, r1, r2, r3, ka);
                kbh[0][0] = r0; kbh[0][1] = r1;
                kbh[1][0] = r2; kbh[1][1] = r3;
                ldsm4(r0, r1, r2, r3, ka + F_KT);
                kbl[0][0] = r0; kbl[0][1] = r1;
                kbl[1][0] = r2; kbl[1][1] = r3;
            }
#pragma unroll
            for (int j = 0; j < 2; ++j) {
                mma16816(sc[j], qfh[0], qfh[1], qfh[2], qfh[3], kbh[j][0], kbh[j][1]);
                mma16816(sc[j], qfh[0], qfh[1], qfh[2], qfh[3], kbl[j][0], kbl[j][1]);
                mma16816(sc[j], qfl[0], qfl[1], qfl[2], qfl[3], kbh[j][0], kbh[j][1]);
            }
        }

        bool diag = (kt >= 4 * qt);
#pragma unroll
        for (int j = 0; j < 2; ++j) {
#pragma unroll
            for (int r = 0; r < 4; r++) sc[j][r] *= SM_SCALE;
            if (diag) {
                int col = k0 + j * 8 + colq;
                if (col > rowA)     sc[j][0] = -1e30f;
                if (col + 1 > rowA) sc[j][1] = -1e30f;
                if (col > rowB)     sc[j][2] = -1e30f;
                if (col + 1 > rowB) sc[j][3] = -1e30f;
            }
        }
        float mxa = fmaxf(fmaxf(sc[0][0], sc[0][1]), fmaxf(sc[1][0], sc[1][1]));
        float mxb = fmaxf(fmaxf(sc[0][2], sc[0][3]), fmaxf(sc[1][2], sc[1][3]));
        mxa = fmaxf(mxa, __shfl_xor_sync(0xffffffffu, mxa, 1));
        mxa = fmaxf(mxa, __shfl_xor_sync(0xffffffffu, mxa, 2));
        mxb = fmaxf(mxb, __shfl_xor_sync(0xffffffffu, mxb, 1));
        mxb = fmaxf(mxb, __shfl_xor_sync(0xffffffffu, mxb, 2));
        float mna = fmaxf(mrow[0], mxa), mnb = fmaxf(mrow[1], mxb);
        float ala = __expf(mrow[0] - mna), alb = __expf(mrow[1] - mnb);
        mrow[0] = mna; mrow[1] = mnb;

        float suma = 0.f, sumb = 0.f;
#pragma unroll
        for (int j = 0; j < 2; ++j) {
            sc[j][0] = __expf(sc[j][0] - mna);
            sc[j][1] = __expf(sc[j][1] - mna);
            sc[j][2] = __expf(sc[j][2] - mnb);
            sc[j][3] = __expf(sc[j][3] - mnb);
            suma += sc[j][0] + sc[j][1];
            sumb += sc[j][2] + sc[j][3];
        }
        suma += __shfl_xor_sync(0xffffffffu, suma, 1);
        suma += __shfl_xor_sync(0xffffffffu, suma, 2);
        sumb += __shfl_xor_sync(0xffffffffu, sumb, 1);
        sumb += __shfl_xor_sync(0xffffffffu, sumb, 2);
        lrow[0] = lrow[0] * ala + suma;
        lrow[1] = lrow[1] * alb + sumb;
#pragma unroll
        for (int nb = 0; nb < 16; ++nb) {
            o[nb][0] *= ala; o[nb][1] *= ala;
            o[nb][2] *= alb; o[nb][3] *= alb;
        }

        // P as one 16x16 A-frag (hi + lo)
        uint32_t pah[4], pal[4];
        split2(sc[0][0], sc[0][1], pah[0], pal[0]);
        split2(sc[0][2], sc[0][3], pah[1], pal[1]);
        split2(sc[1][0], sc[1][1], pah[2], pal[2]);
        split2(sc[1][2], sc[1][3], pah[3], pal[3]);

        // ---- O += P @ V (16 keys) ----
        uint32_t vbase = kvb + 2 * F_KT;
#pragma unroll
        for (int nb2 = 0; nb2 < 8; ++nb2) {
            uint32_t va = vbase + voff + nb2 * 32;
            uint32_t h0, h1, h2, h3, l0, l1, l2, l3;
            ldsm4t(h0, h1, h2, h3, va);
            ldsm4t(l0, l1, l2, l3, va + F_VT);
            mma16816(o[2 * nb2],     pah[0], pah[1], pah[2], pah[3], h0, h1);
            mma16816(o[2 * nb2],     pah[0], pah[1], pah[2], pah[3], l0, l1);
            mma16816(o[2 * nb2],     pal[0], pal[1], pal[2], pal[3], h0, h1);
            mma16816(o[2 * nb2 + 1], pah[0], pah[1], pah[2], pah[3], h2, h3);
            mma16816(o[2 * nb2 + 1], pah[0], pah[1], pah[2], pah[3], l2, l3);
            mma16816(o[2 * nb2 + 1], pal[0], pal[1], pal[2], pal[3], h2, h3);
        }
    }

    float inva = 1.0f / lrow[0], invb = 1.0f / lrow[1];
#pragma unroll
    for (int nb = 0; nb < 16; ++nb) {
        int col = h * 128 + nb * 8 + colq;
        uint32_t hA, lA, hB, lB;
        split2(o[nb][0] * inva, o[nb][1] * inva, hA, lA);
        split2(o[nb][2] * invb, o[nb][3] * invb, hB, lB);
        *(uint32_t*)&Oh_g[(long)rowA * 2048 + col] = hA;
        *(uint32_t*)&Ol_g[(long)rowA * 2048 + col] = lA;
        *(uint32_t*)&Oh_g[(long)rowB * 2048 + col] = hB;
        *(uint32_t*)&Ol_g[(long)rowB * 2048 + col] = lB;
    }
}

// ---------------- launch ------------------------------------------------------
extern "C" void kernel_launch(void* const* d_in, const int* in_sizes, int n_in,
                              void* d_out, int out_size)
{
    const float* hidden   = (const float*)d_in[0];
    const int*   pos      = (const int*)d_in[1];
    const float* ln_w     = (const float*)d_in[3];
    const float* wq_a     = (const float*)d_in[4];
    const float* q_a_ln   = (const float*)d_in[5];
    const float* wq_b     = (const float*)d_in[6];
    const float* wkv_a    = (const float*)d_in[7];
    const float* kv_a_ln  = (const float*)d_in[8];
    const float* wkv_b    = (const float*)d_in[9];
    const float* wo       = (const float*)d_in[10];

    float* out   = (float*)d_out;
    float* k_out = out + (long)SEQ * HIDDEN;
    float* v_out = k_out + (long)NHEADS * SEQ * QKD;

    float *p_qackv, *p_q, *p_kv;
    cudaGetSymbolAddress((void**)&p_qackv, g_qackv);
    cudaGetSymbolAddress((void**)&p_q, g_q);
    cudaGetSymbolAddress((void**)&p_kv, g_kv);

    __nv_bfloat16 *h_hi, *h_lo, *qa_hi, *qa_lo, *ckvn_hi, *ckvn_lo, *attn_hi, *attn_lo;
    __nv_bfloat16 *qf_hi, *qf_lo, *k_hi, *k_lo, *v_hi, *v_lo;
    __nv_bfloat16 *wqkva_hi, *wqkva_lo, *wqb_hi, *wqb_lo, *wkvb_hi, *wkvb_lo, *wo_hi, *wo_lo;
    cudaGetSymbolAddress((void**)&h_hi, g_h_hi);       cudaGetSymbolAddress((void**)&h_lo, g_h_lo);
    cudaGetSymbolAddress((void**)&qa_hi, g_qa_hi);     cudaGetSymbolAddress((void**)&qa_lo, g_qa_lo);
    cudaGetSymbolAddress((void**)&ckvn_hi, g_ckvn_hi); cudaGetSymbolAddress((void**)&ckvn_lo, g_ckvn_lo);
    cudaGetSymbolAddress((void**)&attn_hi, g_attn_hi); cudaGetSymbolAddress((void**)&attn_lo, g_attn_lo);
    cudaGetSymbolAddress((void**)&qf_hi, g_qf_hi);     cudaGetSymbolAddress((void**)&qf_lo, g_qf_lo);
    cudaGetSymbolAddress((void**)&k_hi, g_k_hi);       cudaGetSymbolAddress((void**)&k_lo, g_k_lo);
    cudaGetSymbolAddress((void**)&v_hi, g_v_hi);       cudaGetSymbolAddress((void**)&v_lo, g_v_lo);
    cudaGetSymbolAddress((void**)&wqkva_hi, g_wqkva_hi); cudaGetSymbolAddress((void**)&wqkva_lo, g_wqkva_lo);
    cudaGetSymbolAddress((void**)&wqb_hi, g_wqb_hi);   cudaGetSymbolAddress((void**)&wqb_lo, g_wqb_lo);
    cudaGetSymbolAddress((void**)&wkvb_hi, g_wkvb_hi); cudaGetSymbolAddress((void**)&wkvb_lo, g_wkvb_lo);
    cudaGetSymbolAddress((void**)&wo_hi, g_wo_hi);     cudaGetSymbolAddress((void**)&wo_lo, g_wo_lo);

    cudaFuncSetAttribute(gemm_mma, cudaFuncAttributeMaxDynamicSharedMemorySize, GEMM_SMEM);
    cudaFuncSetAttribute(gemm_dual, cudaFuncAttributeMaxDynamicSharedMemorySize, GEMM_SMEM);
    cudaFuncSetAttribute(flash_mma, cudaFuncAttributeMaxDynamicSharedMemorySize, FLASH_SMEM);

    long c0 = (long)QLORA * HIDDEN / 4;
    long c1 = c0 + (long)576 * HIDDEN / 4;
    long c2 = c1 + (long)3072 * QLORA / 4;
    long c3 = c2 + (long)4096 * KVLORA / 4;
    long c4 = c3 + (long)HIDDEN * 2048 / 4;
    cvt_b16_multi<<<1184, 256>>>(
        wq_a,  wqkva_hi, wqkva_lo, c0,
        wkv_a, wqkva_hi + (long)QLORA * HIDDEN, wqkva_lo + (long)QLORA * HIDDEN, c1,
        wq_b,  wqb_hi,  wqb_lo,  c2,
        wkv_b, wkvb_hi, wkvb_lo, c3,
        wo,    wo_hi,   wo_lo,   c4);

    rmsnorm_b16<<<SEQ, 256>>>(hidden, ln_w, h_hi, h_lo, HIDDEN, HIDDEN, HIDDEN);
    gemm_mma<<<dim3(17, SEQ / 128), 256, GEMM_SMEM>>>(
        h_hi, h_lo, HIDDEN, wqkva_hi, wqkva_lo, p_qackv, SEQ, QKVN, HIDDEN, nullptr, 0.f);
    rmsnorm_b16<<<SEQ, 256>>>(p_qackv, q_a_ln, qa_hi, qa_lo, QLORA, QKVN, QLORA);
    rmsnorm_b16<<<SEQ, 256>>>(p_qackv + QLORA, kv_a_ln, ckvn_hi, ckvn_lo, KVLORA, QKVN, KVLORA);
    gemm_dual<<<dim3(24 + 32, SEQ / 128), 256, GEMM_SMEM>>>(
        qa_hi, qa_lo, QLORA, wqb_hi, wqb_lo, p_q, 3072, QLORA,
        ckvn_hi, ckvn_lo, KVLORA, wkvb_hi, wkvb_lo, p_kv, 4096, KVLORA, 24);
    rope_scatter<<<SEQ, 256>>>(p_q, p_qackv, p_kv, pos, qf_hi, qf_lo,
                               k_out, k_hi, k_lo, v_out, v_hi, v_lo);
    flash_mma<<<dim3(SEQ / 64, NHEADS), 128, FLASH_SMEM>>>(
        qf_hi, qf_lo, k_hi, k_lo, v_hi, v_lo, attn_hi, attn_lo);
    gemm_mma<<<dim3(HIDDEN / 128, SEQ / 128), 256, GEMM_SMEM>>>(
        attn_hi, attn_lo, 2048, wo_hi, wo_lo, out, SEQ, HIDDEN, 2048,
        hidden, RESID_SCALE);
}

// round 10
// speedup vs baseline: 1.5302x; 1.0115x over previous
#include <cuda_runtime.h>
#include <cuda_bf16.h>
#include <math.h>
#include <stdint.h>

#define HIDDEN 5120
#define NHEADS 16
#define QLORA  1536
#define KVLORA 512
#define NOPE   128
#define ROPE_D 64
#define QKD    192
#define VDIM   128
#define SEQ    2048
#define QKVN   2112
#define SM_SCALE 0.07216878364870322f  // 192^-0.5
#define RESID_SCALE 0.125f

// ---------------- scratch ----------------------------------------------------
static __device__ float g_qackv[SEQ * QKVN];
static __device__ float g_q[SEQ * NHEADS * QKD];
static __device__ float g_kv[SEQ * 4096];

static __device__ __nv_bfloat16 g_h_hi[SEQ * HIDDEN],    g_h_lo[SEQ * HIDDEN];
static __device__ __nv_bfloat16 g_qa_hi[SEQ * QLORA],    g_qa_lo[SEQ * QLORA];
static __device__ __nv_bfloat16 g_ckvn_hi[SEQ * KVLORA], g_ckvn_lo[SEQ * KVLORA];
static __device__ __nv_bfloat16 g_attn_hi[SEQ * 2048],   g_attn_lo[SEQ * 2048];
static __device__ __nv_bfloat16 g_qf_hi[NHEADS * SEQ * QKD], g_qf_lo[NHEADS * SEQ * QKD];
static __device__ __nv_bfloat16 g_k_hi[NHEADS * SEQ * QKD],  g_k_lo[NHEADS * SEQ * QKD];
static __device__ __nv_bfloat16 g_v_hi[NHEADS * SEQ * VDIM], g_v_lo[NHEADS * SEQ * VDIM];

static __device__ __nv_bfloat16 g_wqkva_hi[QKVN * HIDDEN], g_wqkva_lo[QKVN * HIDDEN];
static __device__ __nv_bfloat16 g_wqb_hi[3072 * QLORA],    g_wqb_lo[3072 * QLORA];
static __device__ __nv_bfloat16 g_wkvb_hi[4096 * KVLORA],  g_wkvb_lo[4096 * KVLORA];
static __device__ __nv_bfloat16 g_wo_hi[HIDDEN * 2048],    g_wo_lo[HIDDEN * 2048];

// ---------------- helpers ----------------------------------------------------
__device__ __forceinline__ uint32_t smem_u32(const void* p) {
    return (uint32_t)__cvta_generic_to_shared(p);
}
__device__ __forceinline__ void cpa16(uint32_t dst, const void* src, int sz) {
    asm volatile("cp.async.cg.shared.global [%0], [%1], 16, %2;"
                 :: "r"(dst), "l"(src), "r"(sz) : "memory");
}
#define CP_COMMIT() asm volatile("cp.async.commit_group;" ::: "memory")
#define CP_WAIT(n)  asm volatile("cp.async.wait_group %0;" :: "n"(n) : "memory")

__device__ __forceinline__ void ldsm4(uint32_t& r0, uint32_t& r1, uint32_t& r2, uint32_t& r3,
                                      uint32_t addr) {
    asm volatile("ldmatrix.sync.aligned.m8n8.x4.shared.b16 {%0,%1,%2,%3}, [%4];"
                 : "=r"(r0), "=r"(r1), "=r"(r2), "=r"(r3) : "r"(addr));
}
__device__ __forceinline__ void ldsm4t(uint32_t& r0, uint32_t& r1, uint32_t& r2, uint32_t& r3,
                                       uint32_t addr) {
    asm volatile("ldmatrix.sync.aligned.m8n8.x4.trans.shared.b16 {%0,%1,%2,%3}, [%4];"
                 : "=r"(r0), "=r"(r1), "=r"(r2), "=r"(r3) : "r"(addr));
}
__device__ __forceinline__ void mma16816(float* c, uint32_t a0, uint32_t a1, uint32_t a2,
                                         uint32_t a3, uint32_t b0, uint32_t b1) {
    asm volatile(
        "mma.sync.aligned.m16n8k16.row.col.f32.bf16.bf16.f32 "
        "{%0,%1,%2,%3}, {%4,%5,%6,%7}, {%8,%9}, {%0,%1,%2,%3};"
        : "+f"(c[0]), "+f"(c[1]), "+f"(c[2]), "+f"(c[3])
        : "r"(a0), "r"(a1), "r"(a2), "r"(a3), "r"(b0), "r"(b1));
}
__device__ __forceinline__ void split2(float v0, float v1, uint32_t& hi, uint32_t& lo) {
    __nv_bfloat16 h0 = __float2bfloat16(v0), h1 = __float2bfloat16(v1);
    float r0 = v0 - __bfloat162float(h0), r1 = v1 - __bfloat162float(h1);
    __nv_bfloat162 th; th.x = h0; th.y = h1;
    hi = *reinterpret_cast<uint32_t*>(&th);
    __nv_bfloat162 tl; tl.x = __float2bfloat16(r0); tl.y = __float2bfloat16(r1);
    lo = *reinterpret_cast<uint32_t*>(&tl);
}

// ---------------- batched fp32 -> bf16 hi/lo converter ------------------------
__global__ void cvt_b16_multi(
    const float* __restrict__ x0, __nv_bfloat16* __restrict__ h0, __nv_bfloat16* __restrict__ l0, long c0,
    const float* __restrict__ x1, __nv_bfloat16* __restrict__ h1, __nv_bfloat16* __restrict__ l1, long c1,
    const float* __restrict__ x2, __nv_bfloat16* __restrict__ h2, __nv_bfloat16* __restrict__ l2, long c2,
    const float* __restrict__ x3, __nv_bfloat16* __restrict__ h3, __nv_bfloat16* __restrict__ l3, long c3,
    const float* __restrict__ x4, __nv_bfloat16* __restrict__ h4, __nv_bfloat16* __restrict__ l4, long c4)
{
    for (long i = (long)blockIdx.x * blockDim.x + threadIdx.x; i < c4;
         i += (long)gridDim.x * blockDim.x) {
        const float4* xp; __nv_bfloat162* hp; __nv_bfloat162* lp; long base;
        if (i < c0)      { xp = (const float4*)x0; hp = (__nv_bfloat162*)h0; lp = (__nv_bfloat162*)l0; base = 0; }
        else if (i < c1) { xp = (const float4*)x1; hp = (__nv_bfloat162*)h1; lp = (__nv_bfloat162*)l1; base = c0; }
        else if (i < c2) { xp = (const float4*)x2; hp = (__nv_bfloat162*)h2; lp = (__nv_bfloat162*)l2; base = c1; }
        else if (i < c3) { xp = (const float4*)x3; hp = (__nv_bfloat162*)h3; lp = (__nv_bfloat162*)l3; base = c2; }
        else             { xp = (const float4*)x4; hp = (__nv_bfloat162*)h4; lp = (__nv_bfloat162*)l4; base = c3; }
        long j = i - base;
        float4 v = xp[j];
        __nv_bfloat162 ha; ha.x = __float2bfloat16(v.x); ha.y = __float2bfloat16(v.y);
        __nv_bfloat162 hb; hb.x = __float2bfloat16(v.z); hb.y = __float2bfloat16(v.w);
        __nv_bfloat162 la; la.x = __float2bfloat16(v.x - __bfloat162float(ha.x));
        la.y = __float2bfloat16(v.y - __bfloat162float(ha.y));
        __nv_bfloat162 lb; lb.x = __float2bfloat16(v.z - __bfloat162float(hb.x));
        lb.y = __float2bfloat16(v.w - __bfloat162float(hb.y));
        hp[2 * j] = ha; hp[2 * j + 1] = hb;
        lp[2 * j] = la; lp[2 * j + 1] = lb;
    }
}

__global__ void rmsnorm_b16(const float* __restrict__ x, const float* __restrict__ w,
                            __nv_bfloat16* __restrict__ hi, __nv_bfloat16* __restrict__ lo,
                            int cols, int strideIn, int strideOut)
{
    int row = blockIdx.x;
    int t = threadIdx.x;
    const float4* xr = (const float4*)(x + (long)row * strideIn);
    const float4* w4 = (const float4*)w;
    int c4 = cols >> 2;
    float ss = 0.f;
    for (int c = t; c < c4; c += 256) {
        float4 v = xr[c];
        ss = fmaf(v.x, v.x, fmaf(v.y, v.y, fmaf(v.z, v.z, fmaf(v.w, v.w, ss))));
    }
    __shared__ float red[256];
    red[t] = ss; __syncthreads();
    for (int s = 128; s > 0; s >>= 1) { if (t < s) red[t] += red[t + s]; __syncthreads(); }
    float scale = rsqrtf(red[0] / (float)cols + 1e-6f);
    __nv_bfloat162* hr = (__nv_bfloat162*)(hi + (long)row * strideOut);
    __nv_bfloat162* lr = (__nv_bfloat162*)(lo + (long)row * strideOut);
    for (int c = t; c < c4; c += 256) {
        float4 v = xr[c];
        float4 wv = w4[c];
        float a = v.x * scale * wv.x, b = v.y * scale * wv.y;
        float d = v.z * scale * wv.z, e = v.w * scale * wv.w;
        __nv_bfloat162 ha; ha.x = __float2bfloat16(a); ha.y = __float2bfloat16(b);
        __nv_bfloat162 hb; hb.x = __float2bfloat16(d); hb.y = __float2bfloat16(e);
        __nv_bfloat162 la; la.x = __float2bfloat16(a - __bfloat162float(ha.x));
        la.y = __float2bfloat16(b - __bfloat162float(ha.y));
        __nv_bfloat162 lb; lb.x = __float2bfloat16(d - __bfloat162float(hb.x));
        lb.y = __float2bfloat16(e - __bfloat162float(hb.y));
        hr[2 * c] = ha; hr[2 * c + 1] = hb;
        lr[2 * c] = la; lr[2 * c + 1] = lb;
    }
}

// ---------------- mma.sync bf16x3 GEMM: swizzled 64B rows, 3 stages -----------
#define GT_BYTES (128 * 64)         // 8192
#define GS_BYTES (4 * GT_BYTES)     // 32768 per stage
#define GSTAGES 3
#define GEMM_SMEM (GSTAGES * GS_BYTES)  // 98304; 2 CTAs/SM

__device__ __forceinline__ void g_fill(uint32_t dstBase, const __nv_bfloat16* __restrict__ src,
                                       long ld, int rmax, int t)
{
#pragma unroll
    for (int i = 0; i < 2; ++i) {
        int id = t + 256 * i;
        int row = id >> 2, c = id & 3;
        bool ok = row < rmax;
        const __nv_bfloat16* g = src + (long)(ok ? row : 0) * ld + c * 8;
        uint32_t cs = (uint32_t)(c ^ ((row >> 1) & 3));
        cpa16(dstBase + row * 64 + cs * 16, g, ok ? 16 : 0);
    }
}

__device__ __forceinline__ void gemm_core(
    const __nv_bfloat16* __restrict__ Ah, const __nv_bfloat16* __restrict__ Al, int lda,
    const __nv_bfloat16* __restrict__ Bh, const __nv_bfloat16* __restrict__ Bl,
    float* __restrict__ C, int M, int N, int K,
    const float* __restrict__ D, float beta, int bx, int by, char* smem)
{
    uint32_t sb = smem_u32(smem);
    int t = threadIdx.x;
    int warp = t >> 5, lane = t & 31;
    int wm = warp >> 2, wn = warp & 3;
    int n0 = bx * 128, m0 = by * 128;
    int nc = K / 32;

    float acc[4][4][4];
#pragma unroll
    for (int i = 0; i < 4; i++)
#pragma unroll
        for (int j = 0; j < 4; j++)
#pragma unroll
            for (int r = 0; r < 4; r++) acc[i][j][r] = 0.f;

#pragma unroll
    for (int s = 0; s < 2; ++s) {
        uint32_t b0 = sb + s * GS_BYTES;
        int kc0 = s * 32;
        g_fill(b0 + 0 * GT_BYTES, Ah + (long)m0 * lda + kc0, lda, M - m0, t);
        g_fill(b0 + 1 * GT_BYTES, Al + (long)m0 * lda + kc0, lda, M - m0, t);
        g_fill(b0 + 2 * GT_BYTES, Bh + (long)n0 * K + kc0, K, N - n0, t);
        g_fill(b0 + 3 * GT_BYTES, Bl + (long)n0 * K + kc0, K, N - n0, t);
        CP_COMMIT();
    }

    int aRow = wm * 64 + (lane & 15);
    int aCl = lane >> 4;
    int bRow = wn * 32 + (lane & 7) + ((lane >> 4) << 3);
    int bCl = (lane >> 3) & 1;

    int stage = 0;
    for (int c = 0; c < nc; ++c) {
        CP_WAIT(1);
        __syncthreads();
        if (c + 2 < nc) {
            int ps = stage + 2; if (ps >= GSTAGES) ps -= GSTAGES;
            uint32_t bn = sb + ps * GS_BYTES;
            int kc0 = (c + 2) * 32;
            g_fill(bn + 0 * GT_BYTES, Ah + (long)m0 * lda + kc0, lda, M - m0, t);
            g_fill(bn + 1 * GT_BYTES, Al + (long)m0 * lda + kc0, lda, M - m0, t);
            g_fill(bn + 2 * GT_BYTES, Bh + (long)n0 * K + kc0, K, N - n0, t);
            g_fill(bn + 3 * GT_BYTES, Bl + (long)n0 * K + kc0, K, N - n0, t);
        }
        CP_COMMIT();

        uint32_t base = sb + stage * GS_BYTES;
#pragma unroll
        for (int k16 = 0; k16 < 2; ++k16) {
            uint32_t ah[4][4], al_[4][4];
#pragma unroll
            for (int im = 0; im < 4; ++im) {
                int r = aRow + im * 16;
                uint32_t addr = base + r * 64 + (((k16 * 2 + aCl) ^ ((r >> 1) & 3)) << 4);
                ldsm4(ah[im][0], ah[im][1], ah[im][2], ah[im][3], addr);
                ldsm4(al_[im][0], al_[im][1], al_[im][2], al_[im][3], addr + GT_BYTES);
            }
            uint32_t bh[4][2], bl[4][2];
#pragma unroll
            for (int j2 = 0; j2 < 2; ++j2) {
                int r = bRow + j2 * 16;
                uint32_t addr = base + 2 * GT_BYTES + r * 64 +
                                (((k16 * 2 + bCl) ^ ((r >> 1) & 3)) << 4);
                uint32_t r0, r1, r2, r3;
                ldsm4(r0, r1, r2, r3, addr);
                bh[2 * j2][0] = r0; bh[2 * j2][1] = r1;
                bh[2 * j2 + 1][0] = r2; bh[2 * j2 + 1][1] = r3;
                ldsm4(r0, r1, r2, r3, addr + GT_BYTES);
                bl[2 * j2][0] = r0; bl[2 * j2][1] = r1;
                bl[2 * j2 + 1][0] = r2; bl[2 * j2 + 1][1] = r3;
            }
            // pass-outer ordering: 16 independent accumulators between
            // dependent updates to the same acc (breaks HMMA RAW chains).
#pragma unroll
            for (int im = 0; im < 4; ++im)
#pragma unroll
                for (int jn = 0; jn < 4; ++jn)
                    mma16816(acc[im][jn], ah[im][0], ah[im][1], ah[im][2], ah[im][3],
                             bh[jn][0], bh[jn][1]);
#pragma unroll
            for (int im = 0; im < 4; ++im)
#pragma unroll
                for (int jn = 0; jn < 4; ++jn)
                    mma16816(acc[im][jn], ah[im][0], ah[im][1], ah[im][2], ah[im][3],
                             bl[jn][0], bl[jn][1]);
#pragma unroll
            for (int im = 0; im < 4; ++im)
#pragma unroll
                for (int jn = 0; jn < 4; ++jn)
                    mma16816(acc[im][jn], al_[im][0], al_[im][1], al_[im][2], al_[im][3],
                             bh[jn][0], bh[jn][1]);
        }
        if (++stage >= GSTAGES) stage = 0;
    }

#pragma unroll
    for (int im = 0; im < 4; ++im) {
        int row0 = m0 + wm * 64 + im * 16 + (lane >> 2);
#pragma unroll
        for (int jn = 0; jn < 4; ++jn) {
            int col = n0 + wn * 32 + jn * 8 + (lane & 3) * 2;
            if (col < N) {
                float2 v0 = make_float2(acc[im][jn][0], acc[im][jn][1]);
                float2 v1 = make_float2(acc[im][jn][2], acc[im][jn][3]);
                if (D) {
                    float2 d0 = *(const float2*)&D[(long)row0 * N + col];
                    float2 d1 = *(const float2*)&D[(long)(row0 + 8) * N + col];
                    v0.x = fmaf(beta, d0.x, v0.x); v0.y = fmaf(beta, d0.y, v0.y);
                    v1.x = fmaf(beta, d1.x, v1.x); v1.y = fmaf(beta, d1.y, v1.y);
                }
                *(float2*)&C[(long)row0 * N + col] = v0;
                *(float2*)&C[(long)(row0 + 8) * N + col] = v1;
            }
        }
    }
}

__global__ __launch_bounds__(256, 2)
void gemm_mma(const __nv_bfloat16* __restrict__ Ah, const __nv_bfloat16* __restrict__ Al, int lda,
              const __nv_bfloat16* __restrict__ Bh, const __nv_bfloat16* __restrict__ Bl,
              float* __restrict__ C, int M, int N, int K,
              const float* __restrict__ D, float beta)
{
    extern __shared__ __align__(128) char smem[];
    gemm_core(Ah, Al, lda, Bh, Bl, C, M, N, K, D, beta, blockIdx.x, blockIdx.y, smem);
}

__global__ __launch_bounds__(256, 2)
void gemm_dual(const __nv_bfloat16* __restrict__ A1h, const __nv_bfloat16* __restrict__ A1l,
               int lda1, const __nv_bfloat16* __restrict__ B1h,
               const __nv_bfloat16* __restrict__ B1l, float* __restrict__ C1, int N1, int K1,
               const __nv_bfloat16* __restrict__ A2h, const __nv_bfloat16* __restrict__ A2l,
               int lda2, const __nv_bfloat16* __restrict__ B2h,
               const __nv_bfloat16* __restrict__ B2l, float* __restrict__ C2, int N2, int K2,
               int split)
{
    extern __shared__ __align__(128) char smem[];
    if ((int)blockIdx.x < split)
        gemm_core(A1h, A1l, lda1, B1h, B1l, C1, SEQ, N1, K1, nullptr, 0.f,
                  blockIdx.x, blockIdx.y, smem);
    else
        gemm_core(A2h, A2l, lda2, B2h, B2l, C2, SEQ, N2, K2, nullptr, 0.f,
                  blockIdx.x - split, blockIdx.y, smem);
}

// ---------------- RoPE + scatter ----------------------------------------------
__global__ void rope_scatter(const float* __restrict__ qin,    // [s][3072]
                             const float* __restrict__ qackv,  // [s][2112]
                             const float* __restrict__ kvin,   // [s][4096]
                             const int* __restrict__ pos_ids,
                             __nv_bfloat16* __restrict__ qh, __nv_bfloat16* __restrict__ ql,
                             float* __restrict__ kout,
                             __nv_bfloat16* __restrict__ kh, __nv_bfloat16* __restrict__ kl,
                             float* __restrict__ vout,
                             __nv_bfloat16* __restrict__ vh, __nv_bfloat16* __restrict__ vl)
{
    int s = blockIdx.x;
    int t = threadIdx.x;
    __shared__ float cs[32], sn[32], kr[64];
    if (t < 32) {
        double invf = exp(-(double)t * 0.28782313662425575); // ln(10000)/32
        double ang = (double)pos_ids[s] * invf;
        cs[t] = (float)cos(ang);
        sn[t] = (float)sin(ang);
    }
    __syncthreads();
    if (t < 32) {
        float x0 = qackv[(long)s * QKVN + 2048 + 2 * t];
        float x1 = qackv[(long)s * QKVN + 2048 + 2 * t + 1];
        kr[t]      = x0 * cs[t] - x1 * sn[t];
        kr[32 + t] = x1 * cs[t] + x0 * sn[t];
    }
    __syncthreads();
    for (int idx = t; idx < 512; idx += 256) {
        int h = idx >> 5, j = idx & 31;
        const float* qb = qin + (long)s * 3072 + h * 192;
        float x0 = qb[128 + 2 * j], x1 = qb[128 + 2 * j + 1];
        float a = x0 * cs[j] - x1 * sn[j];
        float b = x1 * cs[j] + x0 * sn[j];
        long o = ((long)h * SEQ + s) * 192;
        __nv_bfloat16 ha = __float2bfloat16(a), hb = __float2bfloat16(b);
        qh[o + 128 + j] = ha; ql[o + 128 + j] = __float2bfloat16(a - __bfloat162float(ha));
        qh[o + 160 + j] = hb; ql[o + 160 + j] = __float2bfloat16(b - __bfloat162float(hb));
    }
    for (int idx = t; idx < 2048; idx += 256) {
        int h = idx >> 7, d = idx & 127;
        float v = qin[(long)s * 3072 + h * 192 + d];
        long o = ((long)h * SEQ + s) * 192 + d;
        __nv_bfloat16 hv = __float2bfloat16(v);
        qh[o] = hv; ql[o] = __float2bfloat16(v - __bfloat162float(hv));
    }
    for (int idx = t; idx < 16 * 192; idx += 256) {
        int h = idx / 192, d = idx - h * 192;
        float v = (d < 128) ? kvin[(long)s * 4096 + h * 256 + d] : kr[d - 128];
        long o = ((long)h * SEQ + s) * 192 + d;
        kout[o] = v;
        __nv_bfloat16 hv = __float2bfloat16(v);
        kh[o] = hv; kl[o] = __float2bfloat16(v - __bfloat162float(hv));
    }
    for (int idx = t; idx < 2048; idx += 256) {
        int h = idx >> 7, d = idx & 127;
        float v = kvin[(long)s * 4096 + h * 256 + 128 + d];
        long o = ((long)h * SEQ + s) * 128 + d;
        vout[o] = v;
        __nv_bfloat16 hv = __float2bfloat16(v);
        vh[o] = hv; vl[o] = __float2bfloat16(v - __bfloat162float(hv));
    }
}

// ---------------- flash attention: 128-row Q tile, 32-key stages --------------
#define FPADB 400
#define VPADB 272
#define QT_B (128 * FPADB)
#define KT_B (32 * FPADB)
#define VT_B (32 * VPADB)
#define KV_BASE (2 * QT_B)
#define KV_STAGE (2 * KT_B + 2 * VT_B)
#define FLASH_SMEM (KV_BASE + 2 * KV_STAGE)  // 188416

__device__ __forceinline__ void f_fill_kv(uint32_t dst,
                                          const __nv_bfloat16* __restrict__ Kh,
                                          const __nv_bfloat16* __restrict__ Kl,
                                          const __nv_bfloat16* __restrict__ Vh,
                                          const __nv_bfloat16* __restrict__ Vl,
                                          long k0, int t)
{
#pragma unroll
    for (int i = 0; i < 3; ++i) {
        int id = t + 256 * i;
        int row = id / 24, ch = id % 24;
        cpa16(dst + row * FPADB + ch * 16, Kh + (k0 + row) * 192 + ch * 8, 16);
        cpa16(dst + KT_B + row * FPADB + ch * 16, Kl + (k0 + row) * 192 + ch * 8, 16);
    }
#pragma unroll
    for (int i = 0; i < 2; ++i) {
        int id = t + 256 * i;
        int row = id >> 4, ch = id & 15;
        cpa16(dst + 2 * KT_B + row * VPADB + ch * 16, Vh + (k0 + row) * 128 + ch * 8, 16);
        cpa16(dst + 2 * KT_B + VT_B + row * VPADB + ch * 16, Vl + (k0 + row) * 128 + ch * 8, 16);
    }
}

__global__ __launch_bounds__(256, 1)
void flash_mma(const __nv_bfloat16* __restrict__ Qh_g, const __nv_bfloat16* __restrict__ Ql_g,
               const __nv_bfloat16* __restrict__ Kh_g, const __nv_bfloat16* __restrict__ Kl_g,
               const __nv_bfloat16* __restrict__ Vh_g, const __nv_bfloat16* __restrict__ Vl_g,
               __nv_bfloat16* __restrict__ Oh_g, __nv_bfloat16* __restrict__ Ol_g)
{
    extern __shared__ __align__(128) char smem[];
    uint32_t sb = smem_u32(smem);
    int qt = (int)gridDim.x - 1 - (int)blockIdx.x;
    int h = blockIdx.y;
    int q0 = qt * 128;
    int t = threadIdx.x;
    int warp = t >> 5, lane = t & 31;

    const __nv_bfloat16* Kgh = Kh_g + (long)h * SEQ * 192;
    const __nv_bfloat16* Kgl = Kl_g + (long)h * SEQ * 192;
    const __nv_bfloat16* Vgh = Vh_g + (long)h * SEQ * 128;
    const __nv_bfloat16* Vgl = Vl_g + (long)h * SEQ * 128;

    {
        const __nv_bfloat16* qg = Qh_g + ((long)h * SEQ + q0) * 192;
        const __nv_bfloat16* qg2 = Ql_g + ((long)h * SEQ + q0) * 192;
#pragma unroll
        for (int i = 0; i < 12; ++i) {
            int id = t + 256 * i;
            int row = id / 24, ch = id % 24;
            cpa16(sb + row * FPADB + ch * 16, qg + (long)row * 192 + ch * 8, 16);
            cpa16(sb + QT_B + row * FPADB + ch * 16, qg2 + (long)row * 192 + ch * 8, 16);
        }
        CP_COMMIT();
    }
    f_fill_kv(sb + KV_BASE, Kgh, Kgl, Vgh, Vgl, 0, t);
    CP_COMMIT();

    float o[16][4];
#pragma unroll
    for (int i = 0; i < 16; i++)
#pragma unroll
        for (int r = 0; r < 4; r++) o[i][r] = 0.f;
    float mrow[2] = {-1e30f, -1e30f};
    float lrow[2] = {0.f, 0.f};

    uint32_t qoff = (uint32_t)((warp * 16 + (lane & 15)) * FPADB + (lane >> 4) * 16);
    uint32_t koff = (uint32_t)(((lane & 7) + ((lane >> 4) << 3)) * FPADB +
                               ((lane >> 3) & 1) * 16);
    uint32_t voff = (uint32_t)(((lane & 7) + (((lane >> 3) & 1) << 3)) * VPADB +
                               ((lane >> 4) << 3) * 2);

    int rA = (lane >> 2);
    int colq = (lane & 3) * 2;
    int rowA = q0 + warp * 16 + rA;
    int rowB = rowA + 8;
    int nkt = 4 * qt + 4;

    for (int kt = 0; kt < nkt; ++kt) {
        __syncthreads();
        if (kt + 1 < nkt)
            f_fill_kv(sb + KV_BASE + ((kt + 1) & 1) * KV_STAGE, Kgh, Kgl, Vgh, Vgl,
                      (long)(kt + 1) * 32, t);
        CP_COMMIT();
        CP_WAIT(1);
        __syncthreads();

        int k0 = kt * 32;
        uint32_t kvb = sb + KV_BASE + (kt & 1) * KV_STAGE;

        float sc[4][4];
#pragma unroll
        for (int j = 0; j < 4; j++)
#pragma unroll
            for (int r = 0; r < 4; r++) sc[j][r] = 0.f;

#pragma unroll 1
        for (int k16 = 0; k16 < 12; ++k16) {
            uint32_t qfh[4], qfl[4];
            uint32_t addr = sb + qoff + k16 * 32;
            ldsm4(qfh[0], qfh[1], qfh[2], qfh[3], addr);
            ldsm4(qfl[0], qfl[1], qfl[2], qfl[3], addr + QT_B);
            uint32_t kbh[4][2], kbl[4][2];
#pragma unroll
            for (int j2 = 0; j2 < 2; ++j2) {
                uint32_t ka = kvb + koff + j2 * 16 * FPADB + k16 * 32;
                uint32_t r0, r1, r2, r3;
                ldsm4(r0, r1, r2, r3, ka);
                kbh[2 * j2][0] = r0; kbh[2 * j2][1] = r1;
                kbh[2 * j2 + 1][0] = r2; kbh[2 * j2 + 1][1] = r3;
                ldsm4(r0, r1, r2, r3, ka + KT_B);
                kbl[2 * j2][0] = r0; kbl[2 * j2][1] = r1;
                kbl[2 * j2 + 1][0] = r2; kbl[2 * j2 + 1][1] = r3;
            }
            // pass-outer: 4 independent accumulators between same-acc updates
#pragma unroll
            for (int j = 0; j < 4; ++j)
                mma16816(sc[j], qfh[0], qfh[1], qfh[2], qfh[3], kbh[j][0], kbh[j][1]);
#pragma unroll
            for (int j = 0; j < 4; ++j)
                mma16816(sc[j], qfh[0], qfh[1], qfh[2], qfh[3], kbl[j][0], kbl[j][1]);
#pragma unroll
            for (int j = 0; j < 4; ++j)
                mma16816(sc[j], qfl[0], qfl[1], qfl[2], qfl[3], kbh[j][0], kbh[j][1]);
        }

        bool diag = (kt >= 4 * qt);
#pragma unroll
        for (int j = 0; j < 4; ++j) {
#pragma unroll
            for (int r = 0; r < 4; r++) sc[j][r] *= SM_SCALE;
            if (diag) {
                int col = k0 + j * 8 + colq;
                if (col > rowA)     sc[j][0] = -1e30f;
                if (col + 1 > rowA) sc[j][1] = -1e30f;
                if (col > rowB)     sc[j][2] = -1e30f;
                if (col + 1 > rowB) sc[j][3] = -1e30f;
            }
        }
        float mxa = -1e30f, mxb = -1e30f;
#pragma unroll
        for (int j = 0; j < 4; ++j) {
            mxa = fmaxf(mxa, fmaxf(sc[j][0], sc[j][1]));
            mxb = fmaxf(mxb, fmaxf(sc[j][2], sc[j][3]));
        }
        mxa = fmaxf(mxa, __shfl_xor_sync(0xffffffffu, mxa, 1));
        mxa = fmaxf(mxa, __shfl_xor_sync(0xffffffffu, mxa, 2));
        mxb = fmaxf(mxb, __shfl_xor_sync(0xffffffffu, mxb, 1));
        mxb = fmaxf(mxb, __shfl_xor_sync(0xffffffffu, mxb, 2));
        float mna = fmaxf(mrow[0], mxa), mnb = fmaxf(mrow[1], mxb);
        float ala = __expf(mrow[0] - mna), alb = __expf(mrow[1] - mnb);
        mrow[0] = mna; mrow[1] = mnb;

        float suma = 0.f, sumb = 0.f;
#pragma unroll
        for (int j = 0; j < 4; ++j) {
            sc[j][0] = __expf(sc[j][0] - mna);
            sc[j][1] = __expf(sc[j][1] - mna);
            sc[j][2] = __expf(sc[j][2] - mnb);
            sc[j][3] = __expf(sc[j][3] - mnb);
            suma += sc[j][0] + sc[j][1];
            sumb += sc[j][2] + sc[j][3];
        }
        suma += __shfl_xor_sync(0xffffffffu, suma, 1);
        suma += __shfl_xor_sync(0xffffffffu, suma, 2);
        sumb += __shfl_xor_sync(0xffffffffu, sumb, 1);
        sumb += __shfl_xor_sync(0xffffffffu, sumb, 2);
        lrow[0] = lrow[0] * ala + suma;
        lrow[1] = lrow[1] * alb + sumb;
#pragma unroll
        for (int nb = 0; nb < 16; ++nb) {
            o[nb][0] *= ala; o[nb][1] *= ala;
            o[nb][2] *= alb; o[nb][3] *= alb;
        }

        uint32_t pah[2][4], pal[2][4];
#pragma unroll
        for (int j = 0; j < 2; ++j) {
            split2(sc[2 * j][0],     sc[2 * j][1],     pah[j][0], pal[j][0]);
            split2(sc[2 * j][2],     sc[2 * j][3],     pah[j][1], pal[j][1]);
            split2(sc[2 * j + 1][0], sc[2 * j + 1][1], pah[j][2], pal[j][2]);
            split2(sc[2 * j + 1][2], sc[2 * j + 1][3], pah[j][3], pal[j][3]);
        }

        uint32_t vbase = kvb + 2 * KT_B;
#pragma unroll 1
        for (int j = 0; j < 2; ++j) {
#pragma unroll
            for (int nb2 = 0; nb2 < 8; ++nb2) {
                uint32_t va = vbase + voff + j * 16 * VPADB + nb2 * 32;
                uint32_t h0, h1, h2, h3, l0, l1, l2, l3;
                ldsm4t(h0, h1, h2, h3, va);
                ldsm4t(l0, l1, l2, l3, va + VT_B);
                // alternate the two accumulators to separate RAW chains
                mma16816(o[2 * nb2],     pah[j][0], pah[j][1], pah[j][2], pah[j][3], h0, h1);
                mma16816(o[2 * nb2 + 1], pah[j][0], pah[j][1], pah[j][2], pah[j][3], h2, h3);
                mma16816(o[2 * nb2],     pah[j][0], pah[j][1], pah[j][2], pah[j][3], l0, l1);
                mma16816(o[2 * nb2 + 1], pah[j][0], pah[j][1], pah[j][2], pah[j][3], l2, l3);
                mma16816(o[2 * nb2],     pal[j][0], pal[j][1], pal[j][2], pal[j][3], h0, h1);
                mma16816(o[2 * nb2 + 1], pal[j][0], pal[j][1], pal[j][2], pal[j][3], h2, h3);
            }
        }
    }

    float inva = 1.0f / lrow[0], invb = 1.0f / lrow[1];
#pragma unroll
    for (int nb = 0; nb < 16; ++nb) {
        int col = h * 128 + nb * 8 + colq;
        uint32_t hA, lA, hB, lB;
        split2(o[nb][0] * inva, o[nb][1] * inva, hA, lA);
        split2(o[nb][2] * invb, o[nb][3] * invb, hB, lB);
        *(uint32_t*)&Oh_g[(long)rowA * 2048 + col] = hA;
        *(uint32_t*)&Ol_g[(long)rowA * 2048 + col] = lA;
        *(uint32_t*)&Oh_g[(long)rowB * 2048 + col] = hB;
        *(uint32_t*)&Ol_g[(long)rowB * 2048 + col] = lB;
    }
}

// ---------------- launch ------------------------------------------------------
extern "C" void kernel_launch(void* const* d_in, const int* in_sizes, int n_in,
                              void* d_out, int out_size)
{
    const float* hidden   = (const float*)d_in[0];
    const int*   pos      = (const int*)d_in[1];
    const float* ln_w     = (const float*)d_in[3];
    const float* wq_a     = (const float*)d_in[4];
    const float* q_a_ln   = (const float*)d_in[5];
    const float* wq_b     = (const float*)d_in[6];
    const float* wkv_a    = (const float*)d_in[7];
    const float* kv_a_ln  = (const float*)d_in[8];
    const float* wkv_b    = (const float*)d_in[9];
    const float* wo       = (const float*)d_in[10];

    float* out   = (float*)d_out;
    float* k_out = out + (long)SEQ * HIDDEN;
    float* v_out = k_out + (long)NHEADS * SEQ * QKD;

    float *p_qackv, *p_q, *p_kv;
    cudaGetSymbolAddress((void**)&p_qackv, g_qackv);
    cudaGetSymbolAddress((void**)&p_q, g_q);
    cudaGetSymbolAddress((void**)&p_kv, g_kv);

    __nv_bfloat16 *h_hi, *h_lo, *qa_hi, *qa_lo, *ckvn_hi, *ckvn_lo, *attn_hi, *attn_lo;
    __nv_bfloat16 *qf_hi, *qf_lo, *k_hi, *k_lo, *v_hi, *v_lo;
    __nv_bfloat16 *wqkva_hi, *wqkva_lo, *wqb_hi, *wqb_lo, *wkvb_hi, *wkvb_lo, *wo_hi, *wo_lo;
    cudaGetSymbolAddress((void**)&h_hi, g_h_hi);       cudaGetSymbolAddress((void**)&h_lo, g_h_lo);
    cudaGetSymbolAddress((void**)&qa_hi, g_qa_hi);     cudaGetSymbolAddress((void**)&qa_lo, g_qa_lo);
    cudaGetSymbolAddress((void**)&ckvn_hi, g_ckvn_hi); cudaGetSymbolAddress((void**)&ckvn_lo, g_ckvn_lo);
    cudaGetSymbolAddress((void**)&attn_hi, g_attn_hi); cudaGetSymbolAddress((void**)&attn_lo, g_attn_lo);
    cudaGetSymbolAddress((void**)&qf_hi, g_qf_hi);     cudaGetSymbolAddress((void**)&qf_lo, g_qf_lo);
    cudaGetSymbolAddress((void**)&k_hi, g_k_hi);       cudaGetSymbolAddress((void**)&k_lo, g_k_lo);
    cudaGetSymbolAddress((void**)&v_hi, g_v_hi);       cudaGetSymbolAddress((void**)&v_lo, g_v_lo);
    cudaGetSymbolAddress((void**)&wqkva_hi, g_wqkva_hi); cudaGetSymbolAddress((void**)&wqkva_lo, g_wqkva_lo);
    cudaGetSymbolAddress((void**)&wqb_hi, g_wqb_hi);   cudaGetSymbolAddress((void**)&wqb_lo, g_wqb_lo);
    cudaGetSymbolAddress((void**)&wkvb_hi, g_wkvb_hi); cudaGetSymbolAddress((void**)&wkvb_lo, g_wkvb_lo);
    cudaGetSymbolAddress((void**)&wo_hi, g_wo_hi);     cudaGetSymbolAddress((void**)&wo_lo, g_wo_lo);

    cudaFuncSetAttribute(gemm_mma, cudaFuncAttributeMaxDynamicSharedMemorySize, GEMM_SMEM);
    cudaFuncSetAttribute(gemm_dual, cudaFuncAttributeMaxDynamicSharedMemorySize, GEMM_SMEM);
    cudaFuncSetAttribute(flash_mma, cudaFuncAttributeMaxDynamicSharedMemorySize, FLASH_SMEM);

    long c0 = (long)QLORA * HIDDEN / 4;
    long c1 = c0 + (long)576 * HIDDEN / 4;
    long c2 = c1 + (long)3072 * QLORA / 4;
    long c3 = c2 + (long)4096 * KVLORA / 4;
    long c4 = c3 + (long)HIDDEN * 2048 / 4;
    cvt_b16_multi<<<1184, 256>>>(
        wq_a,  wqkva_hi, wqkva_lo, c0,
        wkv_a, wqkva_hi + (long)QLORA * HIDDEN, wqkva_lo + (long)QLORA * HIDDEN, c1,
        wq_b,  wqb_hi,  wqb_lo,  c2,
        wkv_b, wkvb_hi, wkvb_lo, c3,
        wo,    wo_hi,   wo_lo,   c4);

    rmsnorm_b16<<<SEQ, 256>>>(hidden, ln_w, h_hi, h_lo, HIDDEN, HIDDEN, HIDDEN);
    gemm_mma<<<dim3(17, SEQ / 128), 256, GEMM_SMEM>>>(
        h_hi, h_lo, HIDDEN, wqkva_hi, wqkva_lo, p_qackv, SEQ, QKVN, HIDDEN, nullptr, 0.f);
    rmsnorm_b16<<<SEQ, 256>>>(p_qackv, q_a_ln, qa_hi, qa_lo, QLORA, QKVN, QLORA);
    rmsnorm_b16<<<SEQ, 256>>>(p_qackv + QLORA, kv_a_ln, ckvn_hi, ckvn_lo, KVLORA, QKVN, KVLORA);
    gemm_dual<<<dim3(24 + 32, SEQ / 128), 256, GEMM_SMEM>>>(
        qa_hi, qa_lo, QLORA, wqb_hi, wqb_lo, p_q, 3072, QLORA,
        ckvn_hi, ckvn_lo, KVLORA, wkvb_hi, wkvb_lo, p_kv, 4096, KVLORA, 24);
    rope_scatter<<<SEQ, 256>>>(p_q, p_qackv, p_kv, pos, qf_hi, qf_lo,
                               k_out, k_hi, k_lo, v_out, v_hi, v_lo);
    flash_mma<<<dim3(SEQ / 128, NHEADS), 256, FLASH_SMEM>>>(
        qf_hi, qf_lo, k_hi, k_lo, v_hi, v_lo, attn_hi, attn_lo);
    gemm_mma<<<dim3(HIDDEN / 128, SEQ / 128), 256, GEMM_SMEM>>>(
        attn_hi, attn_lo, 2048, wo_hi, wo_lo, out, SEQ, HIDDEN, 2048,
        hidden, RESID_SCALE);
}

// round 11
// speedup vs baseline: 1.6950x; 1.1077x over previous
#include <cuda_runtime.h>
#include <cuda_bf16.h>
#include <math.h>
#include <stdint.h>

#define HIDDEN 5120
#define NHEADS 16
#define QLORA  1536
#define KVLORA 512
#define NOPE   128
#define ROPE_D 64
#define QKD    192
#define VDIM   128
#define SEQ    2048
#define QKVN   2112
#define SM_SCALE 0.07216878364870322f  // 192^-0.5
#define RESID_SCALE 0.125f

// ---------------- scratch ----------------------------------------------------
static __device__ float g_qackv[SEQ * QKVN];
static __device__ float g_q[SEQ * NHEADS * QKD];
static __device__ float g_kv[SEQ * 4096];

static __device__ float g_h_f[SEQ * HIDDEN];
static __device__ float g_qa_f[SEQ * QLORA];
static __device__ float g_ckvn_f[SEQ * KVLORA];
static __device__ float g_wqkva_f[QKVN * HIDDEN];
static __device__ float g_wqb_f[3072 * QLORA];
static __device__ float g_wkvb_f[4096 * KVLORA];

static __device__ __nv_bfloat16 g_attn_hi[SEQ * 2048],   g_attn_lo[SEQ * 2048];
static __device__ __nv_bfloat16 g_qf_hi[NHEADS * SEQ * QKD], g_qf_lo[NHEADS * SEQ * QKD];
static __device__ __nv_bfloat16 g_k_hi[NHEADS * SEQ * QKD],  g_k_lo[NHEADS * SEQ * QKD];
static __device__ __nv_bfloat16 g_v_hi[NHEADS * SEQ * VDIM], g_v_lo[NHEADS * SEQ * VDIM];
static __device__ __nv_bfloat16 g_wo_hi[HIDDEN * 2048],    g_wo_lo[HIDDEN * 2048];

// ---------------- helpers ----------------------------------------------------
__device__ __forceinline__ uint32_t smem_u32(const void* p) {
    return (uint32_t)__cvta_generic_to_shared(p);
}
__device__ __forceinline__ void cpa16(uint32_t dst, const void* src, int sz) {
    asm volatile("cp.async.cg.shared.global [%0], [%1], 16, %2;"
                 :: "r"(dst), "l"(src), "r"(sz) : "memory");
}
#define CP_COMMIT() asm volatile("cp.async.commit_group;" ::: "memory")
#define CP_WAIT(n)  asm volatile("cp.async.wait_group %0;" :: "n"(n) : "memory")

__device__ __forceinline__ void ldsm4(uint32_t& r0, uint32_t& r1, uint32_t& r2, uint32_t& r3,
                                      uint32_t addr) {
    asm volatile("ldmatrix.sync.aligned.m8n8.x4.shared.b16 {%0,%1,%2,%3}, [%4];"
                 : "=r"(r0), "=r"(r1), "=r"(r2), "=r"(r3) : "r"(addr));
}
__device__ __forceinline__ void ldsm4t(uint32_t& r0, uint32_t& r1, uint32_t& r2, uint32_t& r3,
                                       uint32_t addr) {
    asm volatile("ldmatrix.sync.aligned.m8n8.x4.trans.shared.b16 {%0,%1,%2,%3}, [%4];"
                 : "=r"(r0), "=r"(r1), "=r"(r2), "=r"(r3) : "r"(addr));
}
__device__ __forceinline__ void mma16816(float* c, uint32_t a0, uint32_t a1, uint32_t a2,
                                         uint32_t a3, uint32_t b0, uint32_t b1) {
    asm volatile(
        "mma.sync.aligned.m16n8k16.row.col.f32.bf16.bf16.f32 "
        "{%0,%1,%2,%3}, {%4,%5,%6,%7}, {%8,%9}, {%0,%1,%2,%3};"
        : "+f"(c[0]), "+f"(c[1]), "+f"(c[2]), "+f"(c[3])
        : "r"(a0), "r"(a1), "r"(a2), "r"(a3), "r"(b0), "r"(b1));
}
__device__ __forceinline__ void mma_tf32(float* c, uint32_t a0, uint32_t a1, uint32_t a2,
                                         uint32_t a3, uint32_t b0, uint32_t b1) {
    asm volatile(
        "mma.sync.aligned.m16n8k8.row.col.f32.tf32.tf32.f32 "
        "{%0,%1,%2,%3}, {%4,%5,%6,%7}, {%8,%9}, {%0,%1,%2,%3};"
        : "+f"(c[0]), "+f"(c[1]), "+f"(c[2]), "+f"(c[3])
        : "r"(a0), "r"(a1), "r"(a2), "r"(a3), "r"(b0), "r"(b1));
}
__device__ __forceinline__ float tf32r(float x) {
    uint32_t u;
    asm("cvt.rna.tf32.f32 %0, %1;" : "=r"(u) : "f"(x));
    return __uint_as_float(u);
}
__device__ __forceinline__ void split2(float v0, float v1, uint32_t& hi, uint32_t& lo) {
    __nv_bfloat16 h0 = __float2bfloat16(v0), h1 = __float2bfloat16(v1);
    float r0 = v0 - __bfloat162float(h0), r1 = v1 - __bfloat162float(h1);
    __nv_bfloat162 th; th.x = h0; th.y = h1;
    hi = *reinterpret_cast<uint32_t*>(&th);
    __nv_bfloat162 tl; tl.x = __float2bfloat16(r0); tl.y = __float2bfloat16(r1);
    lo = *reinterpret_cast<uint32_t*>(&tl);
}

// ---------------- weight converters -------------------------------------------
// tf32-round 4 fp32 weight ranges (cumulative float4 counts)
__global__ void cvt_tf32_multi(
    const float* __restrict__ x0, float* __restrict__ y0, long c0,
    const float* __restrict__ x1, float* __restrict__ y1, long c1,
    const float* __restrict__ x2, float* __restrict__ y2, long c2,
    const float* __restrict__ x3, float* __restrict__ y3, long c3)
{
    for (long i = (long)blockIdx.x * blockDim.x + threadIdx.x; i < c3;
         i += (long)gridDim.x * blockDim.x) {
        const float4* xp; float4* yp; long base;
        if (i < c0)      { xp = (const float4*)x0; yp = (float4*)y0; base = 0; }
        else if (i < c1) { xp = (const float4*)x1; yp = (float4*)y1; base = c0; }
        else if (i < c2) { xp = (const float4*)x2; yp = (float4*)y2; base = c1; }
        else             { xp = (const float4*)x3; yp = (float4*)y3; base = c2; }
        long j = i - base;
        float4 v = xp[j];
        v.x = tf32r(v.x); v.y = tf32r(v.y); v.z = tf32r(v.z); v.w = tf32r(v.w);
        yp[j] = v;
    }
}

__global__ void cvt_b16(const float* __restrict__ x, __nv_bfloat16* __restrict__ hi,
                        __nv_bfloat16* __restrict__ lo, long n)
{
    long n4 = n >> 2;
    const float4* x4 = (const float4*)x;
    __nv_bfloat162* h2 = (__nv_bfloat162*)hi;
    __nv_bfloat162* l2 = (__nv_bfloat162*)lo;
    for (long i = (long)blockIdx.x * blockDim.x + threadIdx.x; i < n4;
         i += (long)gridDim.x * blockDim.x) {
        float4 v = x4[i];
        __nv_bfloat162 ha; ha.x = __float2bfloat16(v.x); ha.y = __float2bfloat16(v.y);
        __nv_bfloat162 hb; hb.x = __float2bfloat16(v.z); hb.y = __float2bfloat16(v.w);
        __nv_bfloat162 la; la.x = __float2bfloat16(v.x - __bfloat162float(ha.x));
        la.y = __float2bfloat16(v.y - __bfloat162float(ha.y));
        __nv_bfloat162 lb; lb.x = __float2bfloat16(v.z - __bfloat162float(hb.x));
        lb.y = __float2bfloat16(v.w - __bfloat162float(hb.y));
        h2[2 * i] = ha; h2[2 * i + 1] = hb;
        l2[2 * i] = la; l2[2 * i + 1] = lb;
    }
}

// rmsnorm -> tf32-rounded fp32
__global__ void rmsnorm_f32(const float* __restrict__ x, const float* __restrict__ w,
                            float* __restrict__ y,
                            int cols, int strideIn, int strideOut)
{
    int row = blockIdx.x;
    int t = threadIdx.x;
    const float4* xr = (const float4*)(x + (long)row * strideIn);
    const float4* w4 = (const float4*)w;
    int c4 = cols >> 2;
    float ss = 0.f;
    for (int c = t; c < c4; c += 256) {
        float4 v = xr[c];
        ss = fmaf(v.x, v.x, fmaf(v.y, v.y, fmaf(v.z, v.z, fmaf(v.w, v.w, ss))));
    }
    __shared__ float red[256];
    red[t] = ss; __syncthreads();
    for (int s = 128; s > 0; s >>= 1) { if (t < s) red[t] += red[t + s]; __syncthreads(); }
    float scale = rsqrtf(red[0] / (float)cols + 1e-6f);
    float4* yr = (float4*)(y + (long)row * strideOut);
    for (int c = t; c < c4; c += 256) {
        float4 v = xr[c];
        float4 wv = w4[c];
        float4 o;
        o.x = tf32r(v.x * scale * wv.x);
        o.y = tf32r(v.y * scale * wv.y);
        o.z = tf32r(v.z * scale * wv.z);
        o.w = tf32r(v.w * scale * wv.w);
        yr[c] = o;
    }
}

// ---------------- tf32 single-pass GEMM: swizzled 128B rows, 3 stages ---------
// CTA tile 128x128, Kc=32, 256 threads (8 warps 2x4), warp tile 64x32.
#define T32_TILE 16384              // 128 rows x 128 B (32 fp32)
#define T32_STAGE (2 * T32_TILE)    // 32768
#define GSTAGES 3
#define GEMM_SMEM (GSTAGES * T32_STAGE)  // 98304; 2 CTAs/SM

__device__ __forceinline__ void gt_fill(uint32_t dstBase, const float* __restrict__ src,
                                        long ld, int rmax, int t)
{
#pragma unroll
    for (int i = 0; i < 4; ++i) {
        int id = t + 256 * i;       // 0..1023
        int row = id >> 3, ch = id & 7;
        bool ok = row < rmax;
        const float* g = src + (long)(ok ? row : 0) * ld + ch * 4;
        uint32_t cs = (uint32_t)(ch ^ (row & 7));
        cpa16(dstBase + row * 128 + cs * 16, g, ok ? 16 : 0);
    }
}

__device__ __forceinline__ void gemm_t32_core(
    const float* __restrict__ A, int lda,
    const float* __restrict__ B,
    float* __restrict__ C, int M, int N, int K,
    int bx, int by, char* smem)
{
    uint32_t sb = smem_u32(smem);
    int t = threadIdx.x;
    int warp = t >> 5, lane = t & 31;
    int wm = warp >> 2, wn = warp & 3;
    int n0 = bx * 128, m0 = by * 128;
    int nc = K / 32;
    int x = lane >> 2;              // xor index (rows ≡ x mod 8 for all frags)
    uint32_t o4 = (lane & 3) * 4;

    float acc[4][4][4];
#pragma unroll
    for (int i = 0; i < 4; i++)
#pragma unroll
        for (int j = 0; j < 4; j++)
#pragma unroll
            for (int r = 0; r < 4; r++) acc[i][j][r] = 0.f;

#pragma unroll
    for (int s = 0; s < 2; ++s) {
        uint32_t b0 = sb + s * T32_STAGE;
        int kc0 = s * 32;
        gt_fill(b0,            A + (long)m0 * lda + kc0, lda, M - m0, t);
        gt_fill(b0 + T32_TILE, B + (long)n0 * K + kc0, K, N - n0, t);
        CP_COMMIT();
    }

    int stage = 0;
    for (int c = 0; c < nc; ++c) {
        CP_WAIT(1);
        __syncthreads();
        if (c + 2 < nc) {
            int ps = stage + 2; if (ps >= GSTAGES) ps -= GSTAGES;
            uint32_t bn = sb + ps * T32_STAGE;
            int kc0 = (c + 2) * 32;
            gt_fill(bn,            A + (long)m0 * lda + kc0, lda, M - m0, t);
            gt_fill(bn + T32_TILE, B + (long)n0 * K + kc0, K, N - n0, t);
        }
        CP_COMMIT();

        const char* base = smem + stage * T32_STAGE;
        const char* baseB = base + T32_TILE;
#pragma unroll
        for (int k8 = 0; k8 < 4; ++k8) {
            uint32_t co0 = (uint32_t)(((2 * k8) ^ x) << 4);
            uint32_t co1 = (uint32_t)(((2 * k8 + 1) ^ x) << 4);
            uint32_t au[4][4];
#pragma unroll
            for (int im = 0; im < 4; ++im) {
                uint32_t r0 = (uint32_t)((wm * 64 + im * 16 + x) * 128) + o4;
                uint32_t r1 = r0 + 8 * 128;
                au[im][0] = *(const uint32_t*)(base + r0 + co0);
                au[im][1] = *(const uint32_t*)(base + r1 + co0);
                au[im][2] = *(const uint32_t*)(base + r0 + co1);
                au[im][3] = *(const uint32_t*)(base + r1 + co1);
            }
            uint32_t bu[4][2];
#pragma unroll
            for (int jn = 0; jn < 4; ++jn) {
                uint32_t rb = (uint32_t)((wn * 32 + jn * 8 + x) * 128) + o4;
                bu[jn][0] = *(const uint32_t*)(baseB + rb + co0);
                bu[jn][1] = *(const uint32_t*)(baseB + rb + co1);
            }
#pragma unroll
            for (int im = 0; im < 4; ++im)
#pragma unroll
                for (int jn = 0; jn < 4; ++jn)
                    mma_tf32(acc[im][jn], au[im][0], au[im][1], au[im][2], au[im][3],
                             bu[jn][0], bu[jn][1]);
        }
        if (++stage >= GSTAGES) stage = 0;
    }

#pragma unroll
    for (int im = 0; im < 4; ++im) {
        int row0 = m0 + wm * 64 + im * 16 + (lane >> 2);
#pragma unroll
        for (int jn = 0; jn < 4; ++jn) {
            int col = n0 + wn * 32 + jn * 8 + (lane & 3) * 2;
            if (col < N) {
                *(float2*)&C[(long)row0 * N + col] =
                    make_float2(acc[im][jn][0], acc[im][jn][1]);
                *(float2*)&C[(long)(row0 + 8) * N + col] =
                    make_float2(acc[im][jn][2], acc[im][jn][3]);
            }
        }
    }
}

__global__ __launch_bounds__(256, 2)
void gemm_t32(const float* __restrict__ A, int lda, const float* __restrict__ B,
              float* __restrict__ C, int M, int N, int K)
{
    extern __shared__ __align__(128) char smem[];
    gemm_t32_core(A, lda, B, C, M, N, K, blockIdx.x, blockIdx.y, smem);
}

__global__ __launch_bounds__(256, 2)
void gemm_t32_dual(const float* __restrict__ A1, int lda1, const float* __restrict__ B1,
                   float* __restrict__ C1, int N1, int K1,
                   const float* __restrict__ A2, int lda2, const float* __restrict__ B2,
                   float* __restrict__ C2, int N2, int K2, int split)
{
    extern __shared__ __align__(128) char smem[];
    if ((int)blockIdx.x < split)
        gemm_t32_core(A1, lda1, B1, C1, SEQ, N1, K1, blockIdx.x, blockIdx.y, smem);
    else
        gemm_t32_core(A2, lda2, B2, C2, SEQ, N2, K2, blockIdx.x - split, blockIdx.y, smem);
}

// ---------------- bf16x3 GEMM (out-proj only) ---------------------------------
#define GT_BYTES (128 * 64)         // 8192
#define GS_BYTES (4 * GT_BYTES)     // 32768 per stage (same as tf32 stage)

__device__ __forceinline__ void g_fill(uint32_t dstBase, const __nv_bfloat16* __restrict__ src,
                                       long ld, int rmax, int t)
{
#pragma unroll
    for (int i = 0; i < 2; ++i) {
        int id = t + 256 * i;
        int row = id >> 2, c = id & 3;
        bool ok = row < rmax;
        const __nv_bfloat16* g = src + (long)(ok ? row : 0) * ld + c * 8;
        uint32_t cs = (uint32_t)(c ^ ((row >> 1) & 3));
        cpa16(dstBase + row * 64 + cs * 16, g, ok ? 16 : 0);
    }
}

__global__ __launch_bounds__(256, 2)
void gemm_mma(const __nv_bfloat16* __restrict__ Ah, const __nv_bfloat16* __restrict__ Al, int lda,
              const __nv_bfloat16* __restrict__ Bh, const __nv_bfloat16* __restrict__ Bl,
              float* __restrict__ C, int M, int N, int K,
              const float* __restrict__ D, float beta)
{
    extern __shared__ __align__(128) char smem[];
    uint32_t sb = smem_u32(smem);
    int t = threadIdx.x;
    int warp = t >> 5, lane = t & 31;
    int wm = warp >> 2, wn = warp & 3;
    int n0 = blockIdx.x * 128, m0 = blockIdx.y * 128;
    int nc = K / 32;

    float acc[4][4][4];
#pragma unroll
    for (int i = 0; i < 4; i++)
#pragma unroll
        for (int j = 0; j < 4; j++)
#pragma unroll
            for (int r = 0; r < 4; r++) acc[i][j][r] = 0.f;

#pragma unroll
    for (int s = 0; s < 2; ++s) {
        uint32_t b0 = sb + s * GS_BYTES;
        int kc0 = s * 32;
        g_fill(b0 + 0 * GT_BYTES, Ah + (long)m0 * lda + kc0, lda, M - m0, t);
        g_fill(b0 + 1 * GT_BYTES, Al + (long)m0 * lda + kc0, lda, M - m0, t);
        g_fill(b0 + 2 * GT_BYTES, Bh + (long)n0 * K + kc0, K, N - n0, t);
        g_fill(b0 + 3 * GT_BYTES, Bl + (long)n0 * K + kc0, K, N - n0, t);
        CP_COMMIT();
    }

    int aRow = wm * 64 + (lane & 15);
    int aCl = lane >> 4;
    int bRow = wn * 32 + (lane & 7) + ((lane >> 4) << 3);
    int bCl = (lane >> 3) & 1;

    int stage = 0;
    for (int c = 0; c < nc; ++c) {
        CP_WAIT(1);
        __syncthreads();
        if (c + 2 < nc) {
            int ps = stage + 2; if (ps >= GSTAGES) ps -= GSTAGES;
            uint32_t bn = sb + ps * GS_BYTES;
            int kc0 = (c + 2) * 32;
            g_fill(bn + 0 * GT_BYTES, Ah + (long)m0 * lda + kc0, lda, M - m0, t);
            g_fill(bn + 1 * GT_BYTES, Al + (long)m0 * lda + kc0, lda, M - m0, t);
            g_fill(bn + 2 * GT_BYTES, Bh + (long)n0 * K + kc0, K, N - n0, t);
            g_fill(bn + 3 * GT_BYTES, Bl + (long)n0 * K + kc0, K, N - n0, t);
        }
        CP_COMMIT();

        uint32_t base = sb + stage * GS_BYTES;
#pragma unroll
        for (int k16 = 0; k16 < 2; ++k16) {
            uint32_t ah[4][4], al_[4][4];
#pragma unroll
            for (int im = 0; im < 4; ++im) {
                int r = aRow + im * 16;
                uint32_t addr = base + r * 64 + (((k16 * 2 + aCl) ^ ((r >> 1) & 3)) << 4);
                ldsm4(ah[im][0], ah[im][1], ah[im][2], ah[im][3], addr);
                ldsm4(al_[im][0], al_[im][1], al_[im][2], al_[im][3], addr + GT_BYTES);
            }
            uint32_t bh[4][2], bl[4][2];
#pragma unroll
            for (int j2 = 0; j2 < 2; ++j2) {
                int r = bRow + j2 * 16;
                uint32_t addr = base + 2 * GT_BYTES + r * 64 +
                                (((k16 * 2 + bCl) ^ ((r >> 1) & 3)) << 4);
                uint32_t r0, r1, r2, r3;
                ldsm4(r0, r1, r2, r3, addr);
                bh[2 * j2][0] = r0; bh[2 * j2][1] = r1;
                bh[2 * j2 + 1][0] = r2; bh[2 * j2 + 1][1] = r3;
                ldsm4(r0, r1, r2, r3, addr + GT_BYTES);
                bl[2 * j2][0] = r0; bl[2 * j2][1] = r1;
                bl[2 * j2 + 1][0] = r2; bl[2 * j2 + 1][1] = r3;
            }
#pragma unroll
            for (int im = 0; im < 4; ++im)
#pragma unroll
                for (int jn = 0; jn < 4; ++jn)
                    mma16816(acc[im][jn], ah[im][0], ah[im][1], ah[im][2], ah[im][3],
                             bh[jn][0], bh[jn][1]);
#pragma unroll
            for (int im = 0; im < 4; ++im)
#pragma unroll
                for (int jn = 0; jn < 4; ++jn)
                    mma16816(acc[im][jn], ah[im][0], ah[im][1], ah[im][2], ah[im][3],
                             bl[jn][0], bl[jn][1]);
#pragma unroll
            for (int im = 0; im < 4; ++im)
#pragma unroll
                for (int jn = 0; jn < 4; ++jn)
                    mma16816(acc[im][jn], al_[im][0], al_[im][1], al_[im][2], al_[im][3],
                             bh[jn][0], bh[jn][1]);
        }
        if (++stage >= GSTAGES) stage = 0;
    }

#pragma unroll
    for (int im = 0; im < 4; ++im) {
        int row0 = m0 + wm * 64 + im * 16 + (lane >> 2);
#pragma unroll
        for (int jn = 0; jn < 4; ++jn) {
            int col = n0 + wn * 32 + jn * 8 + (lane & 3) * 2;
            if (col < N) {
                float2 v0 = make_float2(acc[im][jn][0], acc[im][jn][1]);
                float2 v1 = make_float2(acc[im][jn][2], acc[im][jn][3]);
                if (D) {
                    float2 d0 = *(const float2*)&D[(long)row0 * N + col];
                    float2 d1 = *(const float2*)&D[(long)(row0 + 8) * N + col];
                    v0.x = fmaf(beta, d0.x, v0.x); v0.y = fmaf(beta, d0.y, v0.y);
                    v1.x = fmaf(beta, d1.x, v1.x); v1.y = fmaf(beta, d1.y, v1.y);
                }
                *(float2*)&C[(long)row0 * N + col] = v0;
                *(float2*)&C[(long)(row0 + 8) * N + col] = v1;
            }
        }
    }
}

// ---------------- RoPE + scatter ----------------------------------------------
__global__ void rope_scatter(const float* __restrict__ qin,    // [s][3072]
                             const float* __restrict__ qackv,  // [s][2112]
                             const float* __restrict__ kvin,   // [s][4096]
                             const int* __restrict__ pos_ids,
                             __nv_bfloat16* __restrict__ qh, __nv_bfloat16* __restrict__ ql,
                             float* __restrict__ kout,
                             __nv_bfloat16* __restrict__ kh, __nv_bfloat16* __restrict__ kl,
                             float* __restrict__ vout,
                             __nv_bfloat16* __restrict__ vh, __nv_bfloat16* __restrict__ vl)
{
    int s = blockIdx.x;
    int t = threadIdx.x;
    __shared__ float cs[32], sn[32], kr[64];
    if (t < 32) {
        double invf = exp(-(double)t * 0.28782313662425575); // ln(10000)/32
        double ang = (double)pos_ids[s] * invf;
        cs[t] = (float)cos(ang);
        sn[t] = (float)sin(ang);
    }
    __syncthreads();
    if (t < 32) {
        float x0 = qackv[(long)s * QKVN + 2048 + 2 * t];
        float x1 = qackv[(long)s * QKVN + 2048 + 2 * t + 1];
        kr[t]      = x0 * cs[t] - x1 * sn[t];
        kr[32 + t] = x1 * cs[t] + x0 * sn[t];
    }
    __syncthreads();
    for (int idx = t; idx < 512; idx += 256) {
        int h = idx >> 5, j = idx & 31;
        const float* qb = qin + (long)s * 3072 + h * 192;
        float x0 = qb[128 + 2 * j], x1 = qb[128 + 2 * j + 1];
        float a = x0 * cs[j] - x1 * sn[j];
        float b = x1 * cs[j] + x0 * sn[j];
        long o = ((long)h * SEQ + s) * 192;
        __nv_bfloat16 ha = __float2bfloat16(a), hb = __float2bfloat16(b);
        qh[o + 128 + j] = ha; ql[o + 128 + j] = __float2bfloat16(a - __bfloat162float(ha));
        qh[o + 160 + j] = hb; ql[o + 160 + j] = __float2bfloat16(b - __bfloat162float(hb));
    }
    for (int idx = t; idx < 2048; idx += 256) {
        int h = idx >> 7, d = idx & 127;
        float v = qin[(long)s * 3072 + h * 192 + d];
        long o = ((long)h * SEQ + s) * 192 + d;
        __nv_bfloat16 hv = __float2bfloat16(v);
        qh[o] = hv; ql[o] = __float2bfloat16(v - __bfloat162float(hv));
    }
    for (int idx = t; idx < 16 * 192; idx += 256) {
        int h = idx / 192, d = idx - h * 192;
        float v = (d < 128) ? kvin[(long)s * 4096 + h * 256 + d] : kr[d - 128];
        long o = ((long)h * SEQ + s) * 192 + d;
        kout[o] = v;
        __nv_bfloat16 hv = __float2bfloat16(v);
        kh[o] = hv; kl[o] = __float2bfloat16(v - __bfloat162float(hv));
    }
    for (int idx = t; idx < 2048; idx += 256) {
        int h = idx >> 7, d = idx & 127;
        float v = kvin[(long)s * 4096 + h * 256 + 128 + d];
        long o = ((long)h * SEQ + s) * 128 + d;
        vout[o] = v;
        __nv_bfloat16 hv = __float2bfloat16(v);
        vh[o] = hv; vl[o] = __float2bfloat16(v - __bfloat162float(hv));
    }
}

// ---------------- flash attention: 128-row Q tile, 32-key stages --------------
#define FPADB 400
#define VPADB 272
#define QT_B (128 * FPADB)
#define KT_B (32 * FPADB)
#define VT_B (32 * VPADB)
#define KV_BASE (2 * QT_B)
#define KV_STAGE (2 * KT_B + 2 * VT_B)
#define FLASH_SMEM (KV_BASE + 2 * KV_STAGE)  // 188416

__device__ __forceinline__ void f_fill_kv(uint32_t dst,
                                          const __nv_bfloat16* __restrict__ Kh,
                                          const __nv_bfloat16* __restrict__ Kl,
                                          const __nv_bfloat16* __restrict__ Vh,
                                          const __nv_bfloat16* __restrict__ Vl,
                                          long k0, int t)
{
#pragma unroll
    for (int i = 0; i < 3; ++i) {
        int id = t + 256 * i;
        int row = id / 24, ch = id % 24;
        cpa16(dst + row * FPADB + ch * 16, Kh + (k0 + row) * 192 + ch * 8, 16);
        cpa16(dst + KT_B + row * FPADB + ch * 16, Kl + (k0 + row) * 192 + ch * 8, 16);
    }
#pragma unroll
    for (int i = 0; i < 2; ++i) {
        int id = t + 256 * i;
        int row = id >> 4, ch = id & 15;
        cpa16(dst + 2 * KT_B + row * VPADB + ch * 16, Vh + (k0 + row) * 128 + ch * 8, 16);
        cpa16(dst + 2 * KT_B + VT_B + row * VPADB + ch * 16, Vl + (k0 + row) * 128 + ch * 8, 16);
    }
}

__global__ __launch_bounds__(256, 1)
void flash_mma(const __nv_bfloat16* __restrict__ Qh_g, const __nv_bfloat16* __restrict__ Ql_g,
               const __nv_bfloat16* __restrict__ Kh_g, const __nv_bfloat16* __restrict__ Kl_g,
               const __nv_bfloat16* __restrict__ Vh_g, const __nv_bfloat16* __restrict__ Vl_g,
               __nv_bfloat16* __restrict__ Oh_g, __nv_bfloat16* __restrict__ Ol_g)
{
    extern __shared__ __align__(128) char smem[];
    uint32_t sb = smem_u32(smem);
    int qt = (int)gridDim.x - 1 - (int)blockIdx.x;
    int h = blockIdx.y;
    int q0 = qt * 128;
    int t = threadIdx.x;
    int warp = t >> 5, lane = t & 31;

    const __nv_bfloat16* Kgh = Kh_g + (long)h * SEQ * 192;
    const __nv_bfloat16* Kgl = Kl_g + (long)h * SEQ * 192;
    const __nv_bfloat16* Vgh = Vh_g + (long)h * SEQ * 128;
    const __nv_bfloat16* Vgl = Vl_g + (long)h * SEQ * 128;

    {
        const __nv_bfloat16* qg = Qh_g + ((long)h * SEQ + q0) * 192;
        const __nv_bfloat16* qg2 = Ql_g + ((long)h * SEQ + q0) * 192;
#pragma unroll
        for (int i = 0; i < 12; ++i) {
            int id = t + 256 * i;
            int row = id / 24, ch = id % 24;
            cpa16(sb + row * FPADB + ch * 16, qg + (long)row * 192 + ch * 8, 16);
            cpa16(sb + QT_B + row * FPADB + ch * 16, qg2 + (long)row * 192 + ch * 8, 16);
        }
        CP_COMMIT();
    }
    f_fill_kv(sb + KV_BASE, Kgh, Kgl, Vgh, Vgl, 0, t);
    CP_COMMIT();

    float o[16][4];
#pragma unroll
    for (int i = 0; i < 16; i++)
#pragma unroll
        for (int r = 0; r < 4; r++) o[i][r] = 0.f;
    float mrow[2] = {-1e30f, -1e30f};
    float lrow[2] = {0.f, 0.f};

    uint32_t qoff = (uint32_t)((warp * 16 + (lane & 15)) * FPADB + (lane >> 4) * 16);
    uint32_t koff = (uint32_t)(((lane & 7) + ((lane >> 4) << 3)) * FPADB +
                               ((lane >> 3) & 1) * 16);
    uint32_t voff = (uint32_t)(((lane & 7) + (((lane >> 3) & 1) << 3)) * VPADB +
                               ((lane >> 4) << 3) * 2);

    int rA = (lane >> 2);
    int colq = (lane & 3) * 2;
    int rowA = q0 + warp * 16 + rA;
    int rowB = rowA + 8;
    int nkt = 4 * qt + 4;

    for (int kt = 0; kt < nkt; ++kt) {
        __syncthreads();
        if (kt + 1 < nkt)
            f_fill_kv(sb + KV_BASE + ((kt + 1) & 1) * KV_STAGE, Kgh, Kgl, Vgh, Vgl,
                      (long)(kt + 1) * 32, t);
        CP_COMMIT();
        CP_WAIT(1);
        __syncthreads();

        int k0 = kt * 32;
        uint32_t kvb = sb + KV_BASE + (kt & 1) * KV_STAGE;

        float sc[4][4];
#pragma unroll
        for (int j = 0; j < 4; j++)
#pragma unroll
            for (int r = 0; r < 4; r++) sc[j][r] = 0.f;

#pragma unroll 1
        for (int k16 = 0; k16 < 12; ++k16) {
            uint32_t qfh[4], qfl[4];
            uint32_t addr = sb + qoff + k16 * 32;
            ldsm4(qfh[0], qfh[1], qfh[2], qfh[3], addr);
            ldsm4(qfl[0], qfl[1], qfl[2], qfl[3], addr + QT_B);
            uint32_t kbh[4][2], kbl[4][2];
#pragma unroll
            for (int j2 = 0; j2 < 2; ++j2) {
                uint32_t ka = kvb + koff + j2 * 16 * FPADB + k16 * 32;
                uint32_t r0, r1, r2, r3;
                ldsm4(r0, r1, r2, r3, ka);
                kbh[2 * j2][0] = r0; kbh[2 * j2][1] = r1;
                kbh[2 * j2 + 1][0] = r2; kbh[2 * j2 + 1][1] = r3;
                ldsm4(r0, r1, r2, r3, ka + KT_B);
                kbl[2 * j2][0] = r0; kbl[2 * j2][1] = r1;
                kbl[2 * j2 + 1][0] = r2; kbl[2 * j2 + 1][1] = r3;
            }
#pragma unroll
            for (int j = 0; j < 4; ++j)
                mma16816(sc[j], qfh[0], qfh[1], qfh[2], qfh[3], kbh[j][0], kbh[j][1]);
#pragma unroll
            for (int j = 0; j < 4; ++j)
                mma16816(sc[j], qfh[0], qfh[1], qfh[2], qfh[3], kbl[j][0], kbl[j][1]);
#pragma unroll
            for (int j = 0; j < 4; ++j)
                mma16816(sc[j], qfl[0], qfl[1], qfl[2], qfl[3], kbh[j][0], kbh[j][1]);
        }

        bool diag = (kt >= 4 * qt);
#pragma unroll
        for (int j = 0; j < 4; ++j) {
#pragma unroll
            for (int r = 0; r < 4; r++) sc[j][r] *= SM_SCALE;
            if (diag) {
                int col = k0 + j * 8 + colq;
                if (col > rowA)     sc[j][0] = -1e30f;
                if (col + 1 > rowA) sc[j][1] = -1e30f;
                if (col > rowB)     sc[j][2] = -1e30f;
                if (col + 1 > rowB) sc[j][3] = -1e30f;
            }
        }
        float mxa = -1e30f, mxb = -1e30f;
#pragma unroll
        for (int j = 0; j < 4; ++j) {
            mxa = fmaxf(mxa, fmaxf(sc[j][0], sc[j][1]));
            mxb = fmaxf(mxb, fmaxf(sc[j][2], sc[j][3]));
        }
        mxa = fmaxf(mxa, __shfl_xor_sync(0xffffffffu, mxa, 1));
        mxa = fmaxf(mxa, __shfl_xor_sync(0xffffffffu, mxa, 2));
        mxb = fmaxf(mxb, __shfl_xor_sync(0xffffffffu, mxb, 1));
        mxb = fmaxf(mxb, __shfl_xor_sync(0xffffffffu, mxb, 2));
        float mna = fmaxf(mrow[0], mxa), mnb = fmaxf(mrow[1], mxb);
        float ala = __expf(mrow[0] - mna), alb = __expf(mrow[1] - mnb);
        mrow[0] = mna; mrow[1] = mnb;

        float suma = 0.f, sumb = 0.f;
#pragma unroll
        for (int j = 0; j < 4; ++j) {
            sc[j][0] = __expf(sc[j][0] - mna);
            sc[j][1] = __expf(sc[j][1] - mna);
            sc[j][2] = __expf(sc[j][2] - mnb);
            sc[j][3] = __expf(sc[j][3] - mnb);
            suma += sc[j][0] + sc[j][1];
            sumb += sc[j][2] + sc[j][3];
        }
        suma += __shfl_xor_sync(0xffffffffu, suma, 1);
        suma += __shfl_xor_sync(0xffffffffu, suma, 2);
        sumb += __shfl_xor_sync(0xffffffffu, sumb, 1);
        sumb += __shfl_xor_sync(0xffffffffu, sumb, 2);
        lrow[0] = lrow[0] * ala + suma;
        lrow[1] = lrow[1] * alb + sumb;
#pragma unroll
        for (int nb = 0; nb < 16; ++nb) {
            o[nb][0] *= ala; o[nb][1] *= ala;
            o[nb][2] *= alb; o[nb][3] *= alb;
        }

        uint32_t pah[2][4], pal[2][4];
#pragma unroll
        for (int j = 0; j < 2; ++j) {
            split2(sc[2 * j][0],     sc[2 * j][1],     pah[j][0], pal[j][0]);
            split2(sc[2 * j][2],     sc[2 * j][3],     pah[j][1], pal[j][1]);
            split2(sc[2 * j + 1][0], sc[2 * j + 1][1], pah[j][2], pal[j][2]);
            split2(sc[2 * j + 1][2], sc[2 * j + 1][3], pah[j][3], pal[j][3]);
        }

        uint32_t vbase = kvb + 2 * KT_B;
#pragma unroll 1
        for (int j = 0; j < 2; ++j) {
#pragma unroll
            for (int nb2 = 0; nb2 < 8; ++nb2) {
                uint32_t va = vbase + voff + j * 16 * VPADB + nb2 * 32;
                uint32_t h0, h1, h2, h3, l0, l1, l2, l3;
                ldsm4t(h0, h1, h2, h3, va);
                ldsm4t(l0, l1, l2, l3, va + VT_B);
                mma16816(o[2 * nb2],     pah[j][0], pah[j][1], pah[j][2], pah[j][3], h0, h1);
                mma16816(o[2 * nb2 + 1], pah[j][0], pah[j][1], pah[j][2], pah[j][3], h2, h3);
                mma16816(o[2 * nb2],     pah[j][0], pah[j][1], pah[j][2], pah[j][3], l0, l1);
                mma16816(o[2 * nb2 + 1], pah[j][0], pah[j][1], pah[j][2], pah[j][3], l2, l3);
                mma16816(o[2 * nb2],     pal[j][0], pal[j][1], pal[j][2], pal[j][3], h0, h1);
                mma16816(o[2 * nb2 + 1], pal[j][0], pal[j][1], pal[j][2], pal[j][3], h2, h3);
            }
        }
    }

    float inva = 1.0f / lrow[0], invb = 1.0f / lrow[1];
#pragma unroll
    for (int nb = 0; nb < 16; ++nb) {
        int col = h * 128 + nb * 8 + colq;
        uint32_t hA, lA, hB, lB;
        split2(o[nb][0] * inva, o[nb][1] * inva, hA, lA);
        split2(o[nb][2] * invb, o[nb][3] * invb, hB, lB);
        *(uint32_t*)&Oh_g[(long)rowA * 2048 + col] = hA;
        *(uint32_t*)&Ol_g[(long)rowA * 2048 + col] = lA;
        *(uint32_t*)&Oh_g[(long)rowB * 2048 + col] = hB;
        *(uint32_t*)&Ol_g[(long)rowB * 2048 + col] = lB;
    }
}

// ---------------- launch ------------------------------------------------------
extern "C" void kernel_launch(void* const* d_in, const int* in_sizes, int n_in,
                              void* d_out, int out_size)
{
    const float* hidden   = (const float*)d_in[0];
    const int*   pos      = (const int*)d_in[1];
    const float* ln_w     = (const float*)d_in[3];
    const float* wq_a     = (const float*)d_in[4];
    const float* q_a_ln   = (const float*)d_in[5];
    const float* wq_b     = (const float*)d_in[6];
    const float* wkv_a    = (const float*)d_in[7];
    const float* kv_a_ln  = (const float*)d_in[8];
    const float* wkv_b    = (const float*)d_in[9];
    const float* wo       = (const float*)d_in[10];

    float* out   = (float*)d_out;
    float* k_out = out + (long)SEQ * HIDDEN;
    float* v_out = k_out + (long)NHEADS * SEQ * QKD;

    float *p_qackv, *p_q, *p_kv, *p_h, *p_qa, *p_ckvn, *p_wqkva, *p_wqb, *p_wkvb;
    cudaGetSymbolAddress((void**)&p_qackv, g_qackv);
    cudaGetSymbolAddress((void**)&p_q, g_q);
    cudaGetSymbolAddress((void**)&p_kv, g_kv);
    cudaGetSymbolAddress((void**)&p_h, g_h_f);
    cudaGetSymbolAddress((void**)&p_qa, g_qa_f);
    cudaGetSymbolAddress((void**)&p_ckvn, g_ckvn_f);
    cudaGetSymbolAddress((void**)&p_wqkva, g_wqkva_f);
    cudaGetSymbolAddress((void**)&p_wqb, g_wqb_f);
    cudaGetSymbolAddress((void**)&p_wkvb, g_wkvb_f);

    __nv_bfloat16 *attn_hi, *attn_lo, *qf_hi, *qf_lo, *k_hi, *k_lo, *v_hi, *v_lo, *wo_hi, *wo_lo;
    cudaGetSymbolAddress((void**)&attn_hi, g_attn_hi); cudaGetSymbolAddress((void**)&attn_lo, g_attn_lo);
    cudaGetSymbolAddress((void**)&qf_hi, g_qf_hi);     cudaGetSymbolAddress((void**)&qf_lo, g_qf_lo);
    cudaGetSymbolAddress((void**)&k_hi, g_k_hi);       cudaGetSymbolAddress((void**)&k_lo, g_k_lo);
    cudaGetSymbolAddress((void**)&v_hi, g_v_hi);       cudaGetSymbolAddress((void**)&v_lo, g_v_lo);
    cudaGetSymbolAddress((void**)&wo_hi, g_wo_hi);     cudaGetSymbolAddress((void**)&wo_lo, g_wo_lo);

    cudaFuncSetAttribute(gemm_t32, cudaFuncAttributeMaxDynamicSharedMemorySize, GEMM_SMEM);
    cudaFuncSetAttribute(gemm_t32_dual, cudaFuncAttributeMaxDynamicSharedMemorySize, GEMM_SMEM);
    cudaFuncSetAttribute(gemm_mma, cudaFuncAttributeMaxDynamicSharedMemorySize, GEMM_SMEM);
    cudaFuncSetAttribute(flash_mma, cudaFuncAttributeMaxDynamicSharedMemorySize, FLASH_SMEM);

    // tf32-round weights for internal GEMMs (cumulative float4 counts)
    long c0 = (long)QLORA * HIDDEN / 4;
    long c1 = c0 + (long)576 * HIDDEN / 4;
    long c2 = c1 + (long)3072 * QLORA / 4;
    long c3 = c2 + (long)4096 * KVLORA / 4;
    cvt_tf32_multi<<<1184, 256>>>(
        wq_a,  p_wqkva, c0,
        wkv_a, p_wqkva + (long)QLORA * HIDDEN, c1,
        wq_b,  p_wqb, c2,
        wkv_b, p_wkvb, c3);
    // out-proj weight stays bf16 hi/lo
    cvt_b16<<<592, 256>>>(wo, wo_hi, wo_lo, (long)HIDDEN * 2048);

    rmsnorm_f32<<<SEQ, 256>>>(hidden, ln_w, p_h, HIDDEN, HIDDEN, HIDDEN);
    // fused q_a + ckv projection (tf32 single-pass)
    gemm_t32<<<dim3(17, SEQ / 128), 256, GEMM_SMEM>>>(
        p_h, HIDDEN, p_wqkva, p_qackv, SEQ, QKVN, HIDDEN);
    rmsnorm_f32<<<SEQ, 256>>>(p_qackv, q_a_ln, p_qa, QLORA, QKVN, QLORA);
    rmsnorm_f32<<<SEQ, 256>>>(p_qackv + QLORA, kv_a_ln, p_ckvn, KVLORA, QKVN, KVLORA);
    // merged up-projections (tf32 single-pass)
    gemm_t32_dual<<<dim3(24 + 32, SEQ / 128), 256, GEMM_SMEM>>>(
        p_qa, QLORA, p_wqb, p_q, 3072, QLORA,
        p_ckvn, KVLORA, p_wkvb, p_kv, 4096, KVLORA, 24);
    rope_scatter<<<SEQ, 256>>>(p_q, p_qackv, p_kv, pos, qf_hi, qf_lo,
                               k_out, k_hi, k_lo, v_out, v_hi, v_lo);
    flash_mma<<<dim3(SEQ / 128, NHEADS), 256, FLASH_SMEM>>>(
        qf_hi, qf_lo, k_hi, k_lo, v_hi, v_lo, attn_hi, attn_lo);
    // out-proj stays bf16x3 (+ residual)
    gemm_mma<<<dim3(HIDDEN / 128, SEQ / 128), 256, GEMM_SMEM>>>(
        attn_hi, attn_lo, 2048, wo_hi, wo_lo, out, SEQ, HIDDEN, 2048,
        hidden, RESID_SCALE);
}

// round 12
// speedup vs baseline: 1.7776x; 1.0487x over previous
#include <cuda_runtime.h>
#include <cuda_bf16.h>
#include <math.h>
#include <stdint.h>

#define HIDDEN 5120
#define NHEADS 16
#define QLORA  1536
#define KVLORA 512
#define NOPE   128
#define ROPE_D 64
#define QKD    192
#define VDIM   128
#define SEQ    2048
#define QKVN   2112
#define SM_SCALE 0.07216878364870322f  // 192^-0.5
#define RESID_SCALE 0.125f

// ---------------- scratch ----------------------------------------------------
static __device__ float g_qackv[SEQ * QKVN];
static __device__ float g_q[SEQ * NHEADS * QKD];
static __device__ float g_kv[SEQ * 4096];
static __device__ float g_attn_f[SEQ * 2048];

static __device__ float g_h_f[SEQ * HIDDEN];
static __device__ float g_qa_f[SEQ * QLORA];
static __device__ float g_ckvn_f[SEQ * KVLORA];
static __device__ float g_wqkva_f[QKVN * HIDDEN];
static __device__ float g_wqb_f[3072 * QLORA];
static __device__ float g_wkvb_f[4096 * KVLORA];
static __device__ float g_wo_f[HIDDEN * 2048];

static __device__ __nv_bfloat16 g_qf_hi[NHEADS * SEQ * QKD], g_qf_lo[NHEADS * SEQ * QKD];
static __device__ __nv_bfloat16 g_k_hi[NHEADS * SEQ * QKD],  g_k_lo[NHEADS * SEQ * QKD];
static __device__ __nv_bfloat16 g_v_hi[NHEADS * SEQ * VDIM], g_v_lo[NHEADS * SEQ * VDIM];

// ---------------- helpers ----------------------------------------------------
__device__ __forceinline__ uint32_t smem_u32(const void* p) {
    return (uint32_t)__cvta_generic_to_shared(p);
}
__device__ __forceinline__ void cpa16(uint32_t dst, const void* src, int sz) {
    asm volatile("cp.async.cg.shared.global [%0], [%1], 16, %2;"
                 :: "r"(dst), "l"(src), "r"(sz) : "memory");
}
#define CP_COMMIT() asm volatile("cp.async.commit_group;" ::: "memory")
#define CP_WAIT(n)  asm volatile("cp.async.wait_group %0;" :: "n"(n) : "memory")

__device__ __forceinline__ void ldsm4(uint32_t& r0, uint32_t& r1, uint32_t& r2, uint32_t& r3,
                                      uint32_t addr) {
    asm volatile("ldmatrix.sync.aligned.m8n8.x4.shared.b16 {%0,%1,%2,%3}, [%4];"
                 : "=r"(r0), "=r"(r1), "=r"(r2), "=r"(r3) : "r"(addr));
}
__device__ __forceinline__ void ldsm4t(uint32_t& r0, uint32_t& r1, uint32_t& r2, uint32_t& r3,
                                       uint32_t addr) {
    asm volatile("ldmatrix.sync.aligned.m8n8.x4.trans.shared.b16 {%0,%1,%2,%3}, [%4];"
                 : "=r"(r0), "=r"(r1), "=r"(r2), "=r"(r3) : "r"(addr));
}
__device__ __forceinline__ void mma16816(float* c, uint32_t a0, uint32_t a1, uint32_t a2,
                                         uint32_t a3, uint32_t b0, uint32_t b1) {
    asm volatile(
        "mma.sync.aligned.m16n8k16.row.col.f32.bf16.bf16.f32 "
        "{%0,%1,%2,%3}, {%4,%5,%6,%7}, {%8,%9}, {%0,%1,%2,%3};"
        : "+f"(c[0]), "+f"(c[1]), "+f"(c[2]), "+f"(c[3])
        : "r"(a0), "r"(a1), "r"(a2), "r"(a3), "r"(b0), "r"(b1));
}
__device__ __forceinline__ void mma_tf32(float* c, uint32_t a0, uint32_t a1, uint32_t a2,
                                         uint32_t a3, uint32_t b0, uint32_t b1) {
    asm volatile(
        "mma.sync.aligned.m16n8k8.row.col.f32.tf32.tf32.f32 "
        "{%0,%1,%2,%3}, {%4,%5,%6,%7}, {%8,%9}, {%0,%1,%2,%3};"
        : "+f"(c[0]), "+f"(c[1]), "+f"(c[2]), "+f"(c[3])
        : "r"(a0), "r"(a1), "r"(a2), "r"(a3), "r"(b0), "r"(b1));
}
__device__ __forceinline__ float tf32r(float x) {
    uint32_t u;
    asm("cvt.rna.tf32.f32 %0, %1;" : "=r"(u) : "f"(x));
    return __uint_as_float(u);
}
__device__ __forceinline__ void split2(float v0, float v1, uint32_t& hi, uint32_t& lo) {
    __nv_bfloat16 h0 = __float2bfloat16(v0), h1 = __float2bfloat16(v1);
    float r0 = v0 - __bfloat162float(h0), r1 = v1 - __bfloat162float(h1);
    __nv_bfloat162 th; th.x = h0; th.y = h1;
    hi = *reinterpret_cast<uint32_t*>(&th);
    __nv_bfloat162 tl; tl.x = __float2bfloat16(r0); tl.y = __float2bfloat16(r1);
    lo = *reinterpret_cast<uint32_t*>(&tl);
}

// ---------------- weight converter: tf32-round 5 fp32 ranges ------------------
__global__ void cvt_tf32_multi(
    const float* __restrict__ x0, float* __restrict__ y0, long c0,
    const float* __restrict__ x1, float* __restrict__ y1, long c1,
    const float* __restrict__ x2, float* __restrict__ y2, long c2,
    const float* __restrict__ x3, float* __restrict__ y3, long c3,
    const float* __restrict__ x4, float* __restrict__ y4, long c4)
{
    for (long i = (long)blockIdx.x * blockDim.x + threadIdx.x; i < c4;
         i += (long)gridDim.x * blockDim.x) {
        const float4* xp; float4* yp; long base;
        if (i < c0)      { xp = (const float4*)x0; yp = (float4*)y0; base = 0; }
        else if (i < c1) { xp = (const float4*)x1; yp = (float4*)y1; base = c0; }
        else if (i < c2) { xp = (const float4*)x2; yp = (float4*)y2; base = c1; }
        else if (i < c3) { xp = (const float4*)x3; yp = (float4*)y3; base = c2; }
        else             { xp = (const float4*)x4; yp = (float4*)y4; base = c3; }
        long j = i - base;
        float4 v = xp[j];
        v.x = tf32r(v.x); v.y = tf32r(v.y); v.z = tf32r(v.z); v.w = tf32r(v.w);
        yp[j] = v;
    }
}

// rmsnorm -> tf32-rounded fp32
__global__ void rmsnorm_f32(const float* __restrict__ x, const float* __restrict__ w,
                            float* __restrict__ y,
                            int cols, int strideIn, int strideOut)
{
    int row = blockIdx.x;
    int t = threadIdx.x;
    const float4* xr = (const float4*)(x + (long)row * strideIn);
    const float4* w4 = (const float4*)w;
    int c4 = cols >> 2;
    float ss = 0.f;
    for (int c = t; c < c4; c += 256) {
        float4 v = xr[c];
        ss = fmaf(v.x, v.x, fmaf(v.y, v.y, fmaf(v.z, v.z, fmaf(v.w, v.w, ss))));
    }
    __shared__ float red[256];
    red[t] = ss; __syncthreads();
    for (int s = 128; s > 0; s >>= 1) { if (t < s) red[t] += red[t + s]; __syncthreads(); }
    float scale = rsqrtf(red[0] / (float)cols + 1e-6f);
    float4* yr = (float4*)(y + (long)row * strideOut);
    for (int c = t; c < c4; c += 256) {
        float4 v = xr[c];
        float4 wv = w4[c];
        float4 o;
        o.x = tf32r(v.x * scale * wv.x);
        o.y = tf32r(v.y * scale * wv.y);
        o.z = tf32r(v.z * scale * wv.z);
        o.w = tf32r(v.w * scale * wv.w);
        yr[c] = o;
    }
}

// ---------------- tf32 single-pass GEMM: swizzled 128B rows, 3 stages ---------
#define T32_TILE 16384              // 128 rows x 128 B (32 fp32)
#define T32_STAGE (2 * T32_TILE)    // 32768
#define GSTAGES 3
#define GEMM_SMEM (GSTAGES * T32_STAGE)  // 98304; 2 CTAs/SM

__device__ __forceinline__ void gt_fill(uint32_t dstBase, const float* __restrict__ src,
                                        long ld, int rmax, int t)
{
#pragma unroll
    for (int i = 0; i < 4; ++i) {
        int id = t + 256 * i;       // 0..1023
        int row = id >> 3, ch = id & 7;
        bool ok = row < rmax;
        const float* g = src + (long)(ok ? row : 0) * ld + ch * 4;
        uint32_t cs = (uint32_t)(ch ^ (row & 7));
        cpa16(dstBase + row * 128 + cs * 16, g, ok ? 16 : 0);
    }
}

__device__ __forceinline__ void gemm_t32_core(
    const float* __restrict__ A, int lda,
    const float* __restrict__ B,
    float* __restrict__ C, int M, int N, int K,
    const float* __restrict__ D, float beta,
    int bx, int by, char* smem)
{
    uint32_t sb = smem_u32(smem);
    int t = threadIdx.x;
    int warp = t >> 5, lane = t & 31;
    int wm = warp >> 2, wn = warp & 3;
    int n0 = bx * 128, m0 = by * 128;
    int nc = K / 32;
    int x = lane >> 2;
    uint32_t o4 = (lane & 3) * 4;

    float acc[4][4][4];
#pragma unroll
    for (int i = 0; i < 4; i++)
#pragma unroll
        for (int j = 0; j < 4; j++)
#pragma unroll
            for (int r = 0; r < 4; r++) acc[i][j][r] = 0.f;

#pragma unroll
    for (int s = 0; s < 2; ++s) {
        uint32_t b0 = sb + s * T32_STAGE;
        int kc0 = s * 32;
        gt_fill(b0,            A + (long)m0 * lda + kc0, lda, M - m0, t);
        gt_fill(b0 + T32_TILE, B + (long)n0 * K + kc0, K, N - n0, t);
        CP_COMMIT();
    }

    int stage = 0;
    for (int c = 0; c < nc; ++c) {
        CP_WAIT(1);
        __syncthreads();
        if (c + 2 < nc) {
            int ps = stage + 2; if (ps >= GSTAGES) ps -= GSTAGES;
            uint32_t bn = sb + ps * T32_STAGE;
            int kc0 = (c + 2) * 32;
            gt_fill(bn,            A + (long)m0 * lda + kc0, lda, M - m0, t);
            gt_fill(bn + T32_TILE, B + (long)n0 * K + kc0, K, N - n0, t);
        }
        CP_COMMIT();

        const char* base = smem + stage * T32_STAGE;
        const char* baseB = base + T32_TILE;
#pragma unroll
        for (int k8 = 0; k8 < 4; ++k8) {
            uint32_t co0 = (uint32_t)(((2 * k8) ^ x) << 4);
            uint32_t co1 = (uint32_t)(((2 * k8 + 1) ^ x) << 4);
            uint32_t au[4][4];
#pragma unroll
            for (int im = 0; im < 4; ++im) {
                uint32_t r0 = (uint32_t)((wm * 64 + im * 16 + x) * 128) + o4;
                uint32_t r1 = r0 + 8 * 128;
                au[im][0] = *(const uint32_t*)(base + r0 + co0);
                au[im][1] = *(const uint32_t*)(base + r1 + co0);
                au[im][2] = *(const uint32_t*)(base + r0 + co1);
                au[im][3] = *(const uint32_t*)(base + r1 + co1);
            }
            uint32_t bu[4][2];
#pragma unroll
            for (int jn = 0; jn < 4; ++jn) {
                uint32_t rb = (uint32_t)((wn * 32 + jn * 8 + x) * 128) + o4;
                bu[jn][0] = *(const uint32_t*)(baseB + rb + co0);
                bu[jn][1] = *(const uint32_t*)(baseB + rb + co1);
            }
#pragma unroll
            for (int im = 0; im < 4; ++im)
#pragma unroll
                for (int jn = 0; jn < 4; ++jn)
                    mma_tf32(acc[im][jn], au[im][0], au[im][1], au[im][2], au[im][3],
                             bu[jn][0], bu[jn][1]);
        }
        if (++stage >= GSTAGES) stage = 0;
    }

#pragma unroll
    for (int im = 0; im < 4; ++im) {
        int row0 = m0 + wm * 64 + im * 16 + (lane >> 2);
#pragma unroll
        for (int jn = 0; jn < 4; ++jn) {
            int col = n0 + wn * 32 + jn * 8 + (lane & 3) * 2;
            if (col < N) {
                float2 v0 = make_float2(acc[im][jn][0], acc[im][jn][1]);
                float2 v1 = make_float2(acc[im][jn][2], acc[im][jn][3]);
                if (D) {
                    float2 d0 = *(const float2*)&D[(long)row0 * N + col];
                    float2 d1 = *(const float2*)&D[(long)(row0 + 8) * N + col];
                    v0.x = fmaf(beta, d0.x, v0.x); v0.y = fmaf(beta, d0.y, v0.y);
                    v1.x = fmaf(beta, d1.x, v1.x); v1.y = fmaf(beta, d1.y, v1.y);
                }
                *(float2*)&C[(long)row0 * N + col] = v0;
                *(float2*)&C[(long)(row0 + 8) * N + col] = v1;
            }
        }
    }
}

__global__ __launch_bounds__(256, 2)
void gemm_t32(const float* __restrict__ A, int lda, const float* __restrict__ B,
              float* __restrict__ C, int M, int N, int K,
              const float* __restrict__ D, float beta)
{
    extern __shared__ __align__(128) char smem[];
    gemm_t32_core(A, lda, B, C, M, N, K, D, beta, blockIdx.x, blockIdx.y, smem);
}

__global__ __launch_bounds__(256, 2)
void gemm_t32_dual(const float* __restrict__ A1, int lda1, const float* __restrict__ B1,
                   float* __restrict__ C1, int N1, int K1,
                   const float* __restrict__ A2, int lda2, const float* __restrict__ B2,
                   float* __restrict__ C2, int N2, int K2, int split)
{
    extern __shared__ __align__(128) char smem[];
    if ((int)blockIdx.x < split)
        gemm_t32_core(A1, lda1, B1, C1, SEQ, N1, K1, nullptr, 0.f,
                      blockIdx.x, blockIdx.y, smem);
    else
        gemm_t32_core(A2, lda2, B2, C2, SEQ, N2, K2, nullptr, 0.f,
                      blockIdx.x - split, blockIdx.y, smem);
}

// ---------------- RoPE + scatter ----------------------------------------------
__global__ void rope_scatter(const float* __restrict__ qin,    // [s][3072]
                             const float* __restrict__ qackv,  // [s][2112]
                             const float* __restrict__ kvin,   // [s][4096]
                             const int* __restrict__ pos_ids,
                             __nv_bfloat16* __restrict__ qh, __nv_bfloat16* __restrict__ ql,
                             float* __restrict__ kout,
                             __nv_bfloat16* __restrict__ kh, __nv_bfloat16* __restrict__ kl,
                             float* __restrict__ vout,
                             __nv_bfloat16* __restrict__ vh, __nv_bfloat16* __restrict__ vl)
{
    int s = blockIdx.x;
    int t = threadIdx.x;
    __shared__ float cs[32], sn[32], kr[64];
    if (t < 32) {
        double invf = exp(-(double)t * 0.28782313662425575); // ln(10000)/32
        double ang = (double)pos_ids[s] * invf;
        cs[t] = (float)cos(ang);
        sn[t] = (float)sin(ang);
    }
    __syncthreads();
    if (t < 32) {
        float x0 = qackv[(long)s * QKVN + 2048 + 2 * t];
        float x1 = qackv[(long)s * QKVN + 2048 + 2 * t + 1];
        kr[t]      = x0 * cs[t] - x1 * sn[t];
        kr[32 + t] = x1 * cs[t] + x0 * sn[t];
    }
    __syncthreads();
    for (int idx = t; idx < 512; idx += 256) {
        int h = idx >> 5, j = idx & 31;
        const float* qb = qin + (long)s * 3072 + h * 192;
        float x0 = qb[128 + 2 * j], x1 = qb[128 + 2 * j + 1];
        float a = x0 * cs[j] - x1 * sn[j];
        float b = x1 * cs[j] + x0 * sn[j];
        long o = ((long)h * SEQ + s) * 192;
        __nv_bfloat16 ha = __float2bfloat16(a), hb = __float2bfloat16(b);
        qh[o + 128 + j] = ha; ql[o + 128 + j] = __float2bfloat16(a - __bfloat162float(ha));
        qh[o + 160 + j] = hb; ql[o + 160 + j] = __float2bfloat16(b - __bfloat162float(hb));
    }
    for (int idx = t; idx < 2048; idx += 256) {
        int h = idx >> 7, d = idx & 127;
        float v = qin[(long)s * 3072 + h * 192 + d];
        long o = ((long)h * SEQ + s) * 192 + d;
        __nv_bfloat16 hv = __float2bfloat16(v);
        qh[o] = hv; ql[o] = __float2bfloat16(v - __bfloat162float(hv));
    }
    for (int idx = t; idx < 16 * 192; idx += 256) {
        int h = idx / 192, d = idx - h * 192;
        float v = (d < 128) ? kvin[(long)s * 4096 + h * 256 + d] : kr[d - 128];
        long o = ((long)h * SEQ + s) * 192 + d;
        kout[o] = v;
        __nv_bfloat16 hv = __float2bfloat16(v);
        kh[o] = hv; kl[o] = __float2bfloat16(v - __bfloat162float(hv));
    }
    for (int idx = t; idx < 2048; idx += 256) {
        int h = idx >> 7, d = idx & 127;
        float v = kvin[(long)s * 4096 + h * 256 + 128 + d];
        long o = ((long)h * SEQ + s) * 128 + d;
        vout[o] = v;
        __nv_bfloat16 hv = __float2bfloat16(v);
        vh[o] = hv; vl[o] = __float2bfloat16(v - __bfloat162float(hv));
    }
}

// ---------------- flash attention: 128-row Q tile, 32-key stages --------------
#define FPADB 400
#define VPADB 272
#define QT_B (128 * FPADB)
#define KT_B (32 * FPADB)
#define VT_B (32 * VPADB)
#define KV_BASE (2 * QT_B)
#define KV_STAGE (2 * KT_B + 2 * VT_B)
#define FLASH_SMEM (KV_BASE + 2 * KV_STAGE)  // 188416

__device__ __forceinline__ void f_fill_kv(uint32_t dst,
                                          const __nv_bfloat16* __restrict__ Kh,
                                          const __nv_bfloat16* __restrict__ Kl,
                                          const __nv_bfloat16* __restrict__ Vh,
                                          const __nv_bfloat16* __restrict__ Vl,
                                          long k0, int t)
{
#pragma unroll
    for (int i = 0; i < 3; ++i) {
        int id = t + 256 * i;
        int row = id / 24, ch = id % 24;
        cpa16(dst + row * FPADB + ch * 16, Kh + (k0 + row) * 192 + ch * 8, 16);
        cpa16(dst + KT_B + row * FPADB + ch * 16, Kl + (k0 + row) * 192 + ch * 8, 16);
    }
#pragma unroll
    for (int i = 0; i < 2; ++i) {
        int id = t + 256 * i;
        int row = id >> 4, ch = id & 15;
        cpa16(dst + 2 * KT_B + row * VPADB + ch * 16, Vh + (k0 + row) * 128 + ch * 8, 16);
        cpa16(dst + 2 * KT_B + VT_B + row * VPADB + ch * 16, Vl + (k0 + row) * 128 + ch * 8, 16);
    }
}

__global__ __launch_bounds__(256, 1)
void flash_mma(const __nv_bfloat16* __restrict__ Qh_g, const __nv_bfloat16* __restrict__ Ql_g,
               const __nv_bfloat16* __restrict__ Kh_g, const __nv_bfloat16* __restrict__ Kl_g,
               const __nv_bfloat16* __restrict__ Vh_g, const __nv_bfloat16* __restrict__ Vl_g,
               float* __restrict__ O_g)
{
    extern __shared__ __align__(128) char smem[];
    uint32_t sb = smem_u32(smem);
    int qt = (int)gridDim.x - 1 - (int)blockIdx.x;
    int h = blockIdx.y;
    int q0 = qt * 128;
    int t = threadIdx.x;
    int warp = t >> 5, lane = t & 31;

    const __nv_bfloat16* Kgh = Kh_g + (long)h * SEQ * 192;
    const __nv_bfloat16* Kgl = Kl_g + (long)h * SEQ * 192;
    const __nv_bfloat16* Vgh = Vh_g + (long)h * SEQ * 128;
    const __nv_bfloat16* Vgl = Vl_g + (long)h * SEQ * 128;

    {
        const __nv_bfloat16* qg = Qh_g + ((long)h * SEQ + q0) * 192;
        const __nv_bfloat16* qg2 = Ql_g + ((long)h * SEQ + q0) * 192;
#pragma unroll
        for (int i = 0; i < 12; ++i) {
            int id = t + 256 * i;
            int row = id / 24, ch = id % 24;
            cpa16(sb + row * FPADB + ch * 16, qg + (long)row * 192 + ch * 8, 16);
            cpa16(sb + QT_B + row * FPADB + ch * 16, qg2 + (long)row * 192 + ch * 8, 16);
        }
        CP_COMMIT();
    }
    f_fill_kv(sb + KV_BASE, Kgh, Kgl, Vgh, Vgl, 0, t);
    CP_COMMIT();

    float o[16][4];
#pragma unroll
    for (int i = 0; i < 16; i++)
#pragma unroll
        for (int r = 0; r < 4; r++) o[i][r] = 0.f;
    float mrow[2] = {-1e30f, -1e30f};
    float lrow[2] = {0.f, 0.f};

    uint32_t qoff = (uint32_t)((warp * 16 + (lane & 15)) * FPADB + (lane >> 4) * 16);
    uint32_t koff = (uint32_t)(((lane & 7) + ((lane >> 4) << 3)) * FPADB +
                               ((lane >> 3) & 1) * 16);
    uint32_t voff = (uint32_t)(((lane & 7) + (((lane >> 3) & 1) << 3)) * VPADB +
                               ((lane >> 4) << 3) * 2);

    int rA = (lane >> 2);
    int colq = (lane & 3) * 2;
    int rowA = q0 + warp * 16 + rA;
    int rowB = rowA + 8;
    int nkt = 4 * qt + 4;

    for (int kt = 0; kt < nkt; ++kt) {
        __syncthreads();
        if (kt + 1 < nkt)
            f_fill_kv(sb + KV_BASE + ((kt + 1) & 1) * KV_STAGE, Kgh, Kgl, Vgh, Vgl,
                      (long)(kt + 1) * 32, t);
        CP_COMMIT();
        CP_WAIT(1);
        __syncthreads();

        int k0 = kt * 32;
        uint32_t kvb = sb + KV_BASE + (kt & 1) * KV_STAGE;

        float sc[4][4];
#pragma unroll
        for (int j = 0; j < 4; j++)
#pragma unroll
            for (int r = 0; r < 4; r++) sc[j][r] = 0.f;

#pragma unroll 1
        for (int k16 = 0; k16 < 12; ++k16) {
            uint32_t qfh[4], qfl[4];
            uint32_t addr = sb + qoff + k16 * 32;
            ldsm4(qfh[0], qfh[1], qfh[2], qfh[3], addr);
            ldsm4(qfl[0], qfl[1], qfl[2], qfl[3], addr + QT_B);
            uint32_t kbh[4][2], kbl[4][2];
#pragma unroll
            for (int j2 = 0; j2 < 2; ++j2) {
                uint32_t ka = kvb + koff + j2 * 16 * FPADB + k16 * 32;
                uint32_t r0, r1, r2, r3;
                ldsm4(r0, r1, r2, r3, ka);
                kbh[2 * j2][0] = r0; kbh[2 * j2][1] = r1;
                kbh[2 * j2 + 1][0] = r2; kbh[2 * j2 + 1][1] = r3;
                ldsm4(r0, r1, r2, r3, ka + KT_B);
                kbl[2 * j2][0] = r0; kbl[2 * j2][1] = r1;
                kbl[2 * j2 + 1][0] = r2; kbl[2 * j2 + 1][1] = r3;
            }
#pragma unroll
            for (int j = 0; j < 4; ++j)
                mma16816(sc[j], qfh[0], qfh[1], qfh[2], qfh[3], kbh[j][0], kbh[j][1]);
#pragma unroll
            for (int j = 0; j < 4; ++j)
                mma16816(sc[j], qfh[0], qfh[1], qfh[2], qfh[3], kbl[j][0], kbl[j][1]);
#pragma unroll
            for (int j = 0; j < 4; ++j)
                mma16816(sc[j], qfl[0], qfl[1], qfl[2], qfl[3], kbh[j][0], kbh[j][1]);
        }

        bool diag = (kt >= 4 * qt);
#pragma unroll
        for (int j = 0; j < 4; ++j) {
#pragma unroll
            for (int r = 0; r < 4; r++) sc[j][r] *= SM_SCALE;
            if (diag) {
                int col = k0 + j * 8 + colq;
                if (col > rowA)     sc[j][0] = -1e30f;
                if (col + 1 > rowA) sc[j][1] = -1e30f;
                if (col > rowB)     sc[j][2] = -1e30f;
                if (col + 1 > rowB) sc[j][3] = -1e30f;
            }
        }
        float mxa = -1e30f, mxb = -1e30f;
#pragma unroll
        for (int j = 0; j < 4; ++j) {
            mxa = fmaxf(mxa, fmaxf(sc[j][0], sc[j][1]));
            mxb = fmaxf(mxb, fmaxf(sc[j][2], sc[j][3]));
        }
        mxa = fmaxf(mxa, __shfl_xor_sync(0xffffffffu, mxa, 1));
        mxa = fmaxf(mxa, __shfl_xor_sync(0xffffffffu, mxa, 2));
        mxb = fmaxf(mxb, __shfl_xor_sync(0xffffffffu, mxb, 1));
        mxb = fmaxf(mxb, __shfl_xor_sync(0xffffffffu, mxb, 2));
        float mna = fmaxf(mrow[0], mxa), mnb = fmaxf(mrow[1], mxb);
        float ala = __expf(mrow[0] - mna), alb = __expf(mrow[1] - mnb);
        mrow[0] = mna; mrow[1] = mnb;

        float suma = 0.f, sumb = 0.f;
#pragma unroll
        for (int j = 0; j < 4; ++j) {
            sc[j][0] = __expf(sc[j][0] - mna);
            sc[j][1] = __expf(sc[j][1] - mna);
            sc[j][2] = __expf(sc[j][2] - mnb);
            sc[j][3] = __expf(sc[j][3] - mnb);
            suma += sc[j][0] + sc[j][1];
            sumb += sc[j][2] + sc[j][3];
        }
        suma += __shfl_xor_sync(0xffffffffu, suma, 1);
        suma += __shfl_xor_sync(0xffffffffu, suma, 2);
        sumb += __shfl_xor_sync(0xffffffffu, sumb, 1);
        sumb += __shfl_xor_sync(0xffffffffu, sumb, 2);
        lrow[0] = lrow[0] * ala + suma;
        lrow[1] = lrow[1] * alb + sumb;
#pragma unroll
        for (int nb = 0; nb < 16; ++nb) {
            o[nb][0] *= ala; o[nb][1] *= ala;
            o[nb][2] *= alb; o[nb][3] *= alb;
        }

        uint32_t pah[2][4], pal[2][4];
#pragma unroll
        for (int j = 0; j < 2; ++j) {
            split2(sc[2 * j][0],     sc[2 * j][1],     pah[j][0], pal[j][0]);
            split2(sc[2 * j][2],     sc[2 * j][3],     pah[j][1], pal[j][1]);
            split2(sc[2 * j + 1][0], sc[2 * j + 1][1], pah[j][2], pal[j][2]);
            split2(sc[2 * j + 1][2], sc[2 * j + 1][3], pah[j][3], pal[j][3]);
        }

        uint32_t vbase = kvb + 2 * KT_B;
#pragma unroll 1
        for (int j = 0; j < 2; ++j) {
#pragma unroll
            for (int nb2 = 0; nb2 < 8; ++nb2) {
                uint32_t va = vbase + voff + j * 16 * VPADB + nb2 * 32;
                uint32_t h0, h1, h2, h3, l0, l1, l2, l3;
                ldsm4t(h0, h1, h2, h3, va);
                ldsm4t(l0, l1, l2, l3, va + VT_B);
                mma16816(o[2 * nb2],     pah[j][0], pah[j][1], pah[j][2], pah[j][3], h0, h1);
                mma16816(o[2 * nb2 + 1], pah[j][0], pah[j][1], pah[j][2], pah[j][3], h2, h3);
                mma16816(o[2 * nb2],     pah[j][0], pah[j][1], pah[j][2], pah[j][3], l0, l1);
                mma16816(o[2 * nb2 + 1], pah[j][0], pah[j][1], pah[j][2], pah[j][3], l2, l3);
                mma16816(o[2 * nb2],     pal[j][0], pal[j][1], pal[j][2], pal[j][3], h0, h1);
                mma16816(o[2 * nb2 + 1], pal[j][0], pal[j][1], pal[j][2], pal[j][3], h2, h3);
            }
        }
    }

    // epilogue: normalize and store tf32-rounded fp32 into [s][2048]
    float inva = 1.0f / lrow[0], invb = 1.0f / lrow[1];
#pragma unroll
    for (int nb = 0; nb < 16; ++nb) {
        int col = h * 128 + nb * 8 + colq;
        float2 vA = make_float2(tf32r(o[nb][0] * inva), tf32r(o[nb][1] * inva));
        float2 vB = make_float2(tf32r(o[nb][2] * invb), tf32r(o[nb][3] * invb));
        *(float2*)&O_g[(long)rowA * 2048 + col] = vA;
        *(float2*)&O_g[(long)rowB * 2048 + col] = vB;
    }
}

// ---------------- launch ------------------------------------------------------
extern "C" void kernel_launch(void* const* d_in, const int* in_sizes, int n_in,
                              void* d_out, int out_size)
{
    const float* hidden   = (const float*)d_in[0];
    const int*   pos      = (const int*)d_in[1];
    const float* ln_w     = (const float*)d_in[3];
    const float* wq_a     = (const float*)d_in[4];
    const float* q_a_ln   = (const float*)d_in[5];
    const float* wq_b     = (const float*)d_in[6];
    const float* wkv_a    = (const float*)d_in[7];
    const float* kv_a_ln  = (const float*)d_in[8];
    const float* wkv_b    = (const float*)d_in[9];
    const float* wo       = (const float*)d_in[10];

    float* out   = (float*)d_out;
    float* k_out = out + (long)SEQ * HIDDEN;
    float* v_out = k_out + (long)NHEADS * SEQ * QKD;

    float *p_qackv, *p_q, *p_kv, *p_attn, *p_h, *p_qa, *p_ckvn;
    float *p_wqkva, *p_wqb, *p_wkvb, *p_wo;
    cudaGetSymbolAddress((void**)&p_qackv, g_qackv);
    cudaGetSymbolAddress((void**)&p_q, g_q);
    cudaGetSymbolAddress((void**)&p_kv, g_kv);
    cudaGetSymbolAddress((void**)&p_attn, g_attn_f);
    cudaGetSymbolAddress((void**)&p_h, g_h_f);
    cudaGetSymbolAddress((void**)&p_qa, g_qa_f);
    cudaGetSymbolAddress((void**)&p_ckvn, g_ckvn_f);
    cudaGetSymbolAddress((void**)&p_wqkva, g_wqkva_f);
    cudaGetSymbolAddress((void**)&p_wqb, g_wqb_f);
    cudaGetSymbolAddress((void**)&p_wkvb, g_wkvb_f);
    cudaGetSymbolAddress((void**)&p_wo, g_wo_f);

    __nv_bfloat16 *qf_hi, *qf_lo, *k_hi, *k_lo, *v_hi, *v_lo;
    cudaGetSymbolAddress((void**)&qf_hi, g_qf_hi);     cudaGetSymbolAddress((void**)&qf_lo, g_qf_lo);
    cudaGetSymbolAddress((void**)&k_hi, g_k_hi);       cudaGetSymbolAddress((void**)&k_lo, g_k_lo);
    cudaGetSymbolAddress((void**)&v_hi, g_v_hi);       cudaGetSymbolAddress((void**)&v_lo, g_v_lo);

    cudaFuncSetAttribute(gemm_t32, cudaFuncAttributeMaxDynamicSharedMemorySize, GEMM_SMEM);
    cudaFuncSetAttribute(gemm_t32_dual, cudaFuncAttributeMaxDynamicSharedMemorySize, GEMM_SMEM);
    cudaFuncSetAttribute(flash_mma, cudaFuncAttributeMaxDynamicSharedMemorySize, FLASH_SMEM);

    // tf32-round all weights (cumulative float4 counts)
    long c0 = (long)QLORA * HIDDEN / 4;
    long c1 = c0 + (long)576 * HIDDEN / 4;
    long c2 = c1 + (long)3072 * QLORA / 4;
    long c3 = c2 + (long)4096 * KVLORA / 4;
    long c4 = c3 + (long)HIDDEN * 2048 / 4;
    cvt_tf32_multi<<<1184, 256>>>(
        wq_a,  p_wqkva, c0,
        wkv_a, p_wqkva + (long)QLORA * HIDDEN, c1,
        wq_b,  p_wqb, c2,
        wkv_b, p_wkvb, c3,
        wo,    p_wo, c4);

    rmsnorm_f32<<<SEQ, 256>>>(hidden, ln_w, p_h, HIDDEN, HIDDEN, HIDDEN);
    gemm_t32<<<dim3(17, SEQ / 128), 256, GEMM_SMEM>>>(
        p_h, HIDDEN, p_wqkva, p_qackv, SEQ, QKVN, HIDDEN, nullptr, 0.f);
    rmsnorm_f32<<<SEQ, 256>>>(p_qackv, q_a_ln, p_qa, QLORA, QKVN, QLORA);
    rmsnorm_f32<<<SEQ, 256>>>(p_qackv + QLORA, kv_a_ln, p_ckvn, KVLORA, QKVN, KVLORA);
    gemm_t32_dual<<<dim3(24 + 32, SEQ / 128), 256, GEMM_SMEM>>>(
        p_qa, QLORA, p_wqb, p_q, 3072, QLORA,
        p_ckvn, KVLORA, p_wkvb, p_kv, 4096, KVLORA, 24);
    rope_scatter<<<SEQ, 256>>>(p_q, p_qackv, p_kv, pos, qf_hi, qf_lo,
                               k_out, k_hi, k_lo, v_out, v_hi, v_lo);
    flash_mma<<<dim3(SEQ / 128, NHEADS), 256, FLASH_SMEM>>>(
        qf_hi, qf_lo, k_hi, k_lo, v_hi, v_lo, p_attn);
    // out-proj tf32 single-pass + residual
    gemm_t32<<<dim3(HIDDEN / 128, SEQ / 128), 256, GEMM_SMEM>>>(
        p_attn, 2048, p_wo, out, SEQ, HIDDEN, 2048, hidden, RESID_SCALE);
}

// round 13
// speedup vs baseline: 1.9048x; 1.0715x over previous
#include <cuda_runtime.h>
#include <cuda_bf16.h>
#include <math.h>
#include <stdint.h>

#define HIDDEN 5120
#define NHEADS 16
#define QLORA  1536
#define KVLORA 512
#define NOPE   128
#define ROPE_D 64
#define QKD    192
#define VDIM   128
#define SEQ    2048
#define QKVN   2112
#define SM_SCALE 0.07216878364870322f  // 192^-0.5
#define RESID_SCALE 0.125f

// ---------------- scratch ----------------------------------------------------
static __device__ float g_qackv[SEQ * QKVN];
static __device__ float g_q[SEQ * NHEADS * QKD];
static __device__ float g_kv[SEQ * 4096];
static __device__ float g_attn_f[SEQ * 2048];

static __device__ float g_h_f[SEQ * HIDDEN];
static __device__ float g_qa_f[SEQ * QLORA];
static __device__ float g_ckvn_f[SEQ * KVLORA];
static __device__ float g_wqkva_f[QKVN * HIDDEN];
static __device__ float g_wqb_f[3072 * QLORA];
static __device__ float g_wkvb_f[4096 * KVLORA];
static __device__ float g_wo_f[HIDDEN * 2048];

static __device__ __nv_bfloat16 g_qf_hi[NHEADS * SEQ * QKD], g_qf_lo[NHEADS * SEQ * QKD];
static __device__ __nv_bfloat16 g_k_hi[NHEADS * SEQ * QKD],  g_k_lo[NHEADS * SEQ * QKD];
static __device__ __nv_bfloat16 g_v_hi[NHEADS * SEQ * VDIM], g_v_lo[NHEADS * SEQ * VDIM];

// ---------------- helpers ----------------------------------------------------
__device__ __forceinline__ uint32_t smem_u32(const void* p) {
    return (uint32_t)__cvta_generic_to_shared(p);
}
__device__ __forceinline__ void cpa16(uint32_t dst, const void* src, int sz) {
    asm volatile("cp.async.cg.shared.global [%0], [%1], 16, %2;"
                 :: "r"(dst), "l"(src), "r"(sz) : "memory");
}
#define CP_COMMIT() asm volatile("cp.async.commit_group;" ::: "memory")
#define CP_WAIT(n)  asm volatile("cp.async.wait_group %0;" :: "n"(n) : "memory")

__device__ __forceinline__ void ldsm4(uint32_t& r0, uint32_t& r1, uint32_t& r2, uint32_t& r3,
                                      uint32_t addr) {
    asm volatile("ldmatrix.sync.aligned.m8n8.x4.shared.b16 {%0,%1,%2,%3}, [%4];"
                 : "=r"(r0), "=r"(r1), "=r"(r2), "=r"(r3) : "r"(addr));
}
__device__ __forceinline__ void ldsm4t(uint32_t& r0, uint32_t& r1, uint32_t& r2, uint32_t& r3,
                                       uint32_t addr) {
    asm volatile("ldmatrix.sync.aligned.m8n8.x4.trans.shared.b16 {%0,%1,%2,%3}, [%4];"
                 : "=r"(r0), "=r"(r1), "=r"(r2), "=r"(r3) : "r"(addr));
}
__device__ __forceinline__ void mma16816(float* c, uint32_t a0, uint32_t a1, uint32_t a2,
                                         uint32_t a3, uint32_t b0, uint32_t b1) {
    asm volatile(
        "mma.sync.aligned.m16n8k16.row.col.f32.bf16.bf16.f32 "
        "{%0,%1,%2,%3}, {%4,%5,%6,%7}, {%8,%9}, {%0,%1,%2,%3};"
        : "+f"(c[0]), "+f"(c[1]), "+f"(c[2]), "+f"(c[3])
        : "r"(a0), "r"(a1), "r"(a2), "r"(a3), "r"(b0), "r"(b1));
}
__device__ __forceinline__ void mma_tf32(float* c, uint32_t a0, uint32_t a1, uint32_t a2,
                                         uint32_t a3, uint32_t b0, uint32_t b1) {
    asm volatile(
        "mma.sync.aligned.m16n8k8.row.col.f32.tf32.tf32.f32 "
        "{%0,%1,%2,%3}, {%4,%5,%6,%7}, {%8,%9}, {%0,%1,%2,%3};"
        : "+f"(c[0]), "+f"(c[1]), "+f"(c[2]), "+f"(c[3])
        : "r"(a0), "r"(a1), "r"(a2), "r"(a3), "r"(b0), "r"(b1));
}
__device__ __forceinline__ float tf32r(float x) {
    uint32_t u;
    asm("cvt.rna.tf32.f32 %0, %1;" : "=r"(u) : "f"(x));
    return __uint_as_float(u);
}
__device__ __forceinline__ void split2(float v0, float v1, uint32_t& hi, uint32_t& lo) {
    __nv_bfloat16 h0 = __float2bfloat16(v0), h1 = __float2bfloat16(v1);
    float r0 = v0 - __bfloat162float(h0), r1 = v1 - __bfloat162float(h1);
    __nv_bfloat162 th; th.x = h0; th.y = h1;
    hi = *reinterpret_cast<uint32_t*>(&th);
    __nv_bfloat162 tl; tl.x = __float2bfloat16(r0); tl.y = __float2bfloat16(r1);
    lo = *reinterpret_cast<uint32_t*>(&tl);
}

// ---------------- weight converter: tf32-round 5 fp32 ranges ------------------
__global__ void cvt_tf32_multi(
    const float* __restrict__ x0, float* __restrict__ y0, long c0,
    const float* __restrict__ x1, float* __restrict__ y1, long c1,
    const float* __restrict__ x2, float* __restrict__ y2, long c2,
    const float* __restrict__ x3, float* __restrict__ y3, long c3,
    const float* __restrict__ x4, float* __restrict__ y4, long c4)
{
    for (long i = (long)blockIdx.x * blockDim.x + threadIdx.x; i < c4;
         i += (long)gridDim.x * blockDim.x) {
        const float4* xp; float4* yp; long base;
        if (i < c0)      { xp = (const float4*)x0; yp = (float4*)y0; base = 0; }
        else if (i < c1) { xp = (const float4*)x1; yp = (float4*)y1; base = c0; }
        else if (i < c2) { xp = (const float4*)x2; yp = (float4*)y2; base = c1; }
        else if (i < c3) { xp = (const float4*)x3; yp = (float4*)y3; base = c2; }
        else             { xp = (const float4*)x4; yp = (float4*)y4; base = c3; }
        long j = i - base;
        float4 v = xp[j];
        v.x = tf32r(v.x); v.y = tf32r(v.y); v.z = tf32r(v.z); v.w = tf32r(v.w);
        yp[j] = v;
    }
}

// rmsnorm -> tf32-rounded fp32
__global__ void rmsnorm_f32(const float* __restrict__ x, const float* __restrict__ w,
                            float* __restrict__ y,
                            int cols, int strideIn, int strideOut)
{
    int row = blockIdx.x;
    int t = threadIdx.x;
    const float4* xr = (const float4*)(x + (long)row * strideIn);
    const float4* w4 = (const float4*)w;
    int c4 = cols >> 2;
    float ss = 0.f;
    for (int c = t; c < c4; c += 256) {
        float4 v = xr[c];
        ss = fmaf(v.x, v.x, fmaf(v.y, v.y, fmaf(v.z, v.z, fmaf(v.w, v.w, ss))));
    }
    __shared__ float red[256];
    red[t] = ss; __syncthreads();
    for (int s = 128; s > 0; s >>= 1) { if (t < s) red[t] += red[t + s]; __syncthreads(); }
    float scale = rsqrtf(red[0] / (float)cols + 1e-6f);
    float4* yr = (float4*)(y + (long)row * strideOut);
    for (int c = t; c < c4; c += 256) {
        float4 v = xr[c];
        float4 wv = w4[c];
        float4 o;
        o.x = tf32r(v.x * scale * wv.x);
        o.y = tf32r(v.y * scale * wv.y);
        o.z = tf32r(v.z * scale * wv.z);
        o.w = tf32r(v.w * scale * wv.w);
        yr[c] = o;
    }
}

// ---------------- tf32 single-pass GEMM (ldmatrix frags), 3 stages ------------
#define T32_TILE 16384              // 128 rows x 128 B (32 fp32)
#define T32_STAGE (2 * T32_TILE)    // 32768
#define GSTAGES 3
#define GEMM_SMEM (GSTAGES * T32_STAGE)  // 98304; 2 CTAs/SM

__device__ __forceinline__ void gt_fill(uint32_t dstBase, const float* __restrict__ src,
                                        long ld, int rmax, int t)
{
#pragma unroll
    for (int i = 0; i < 4; ++i) {
        int id = t + 256 * i;       // 0..1023
        int row = id >> 3, ch = id & 7;
        bool ok = row < rmax;
        const float* g = src + (long)(ok ? row : 0) * ld + ch * 4;
        uint32_t cs = (uint32_t)(ch ^ (row & 7));
        cpa16(dstBase + row * 128 + cs * 16, g, ok ? 16 : 0);
    }
}

__device__ __forceinline__ void gemm_t32_core(
    const float* __restrict__ A, int lda,
    const float* __restrict__ B,
    float* __restrict__ C, int M, int N, int K,
    const float* __restrict__ D, float beta,
    int bx, int by, char* smem)
{
    uint32_t sb = smem_u32(smem);
    int t = threadIdx.x;
    int warp = t >> 5, lane = t & 31;
    int wm = warp >> 2, wn = warp & 3;
    int n0 = bx * 128, m0 = by * 128;
    int nc = K / 32;
    int q = lane >> 3, lr = lane & 7;

    // per-lane ldmatrix row byte-offsets (row multiples of 8 => xor index = lr)
    uint32_t aRow[4];
#pragma unroll
    for (int im = 0; im < 4; ++im)
        aRow[im] = (uint32_t)((wm * 64 + im * 16 + ((q & 1) << 3) + lr) * 128);
    uint32_t bRow[2];
#pragma unroll
    for (int p = 0; p < 2; ++p)
        bRow[p] = (uint32_t)((wn * 32 + ((2 * p + (q >> 1)) << 3) + lr) * 128) + T32_TILE;

    float acc[4][4][4];
#pragma unroll
    for (int i = 0; i < 4; i++)
#pragma unroll
        for (int j = 0; j < 4; j++)
#pragma unroll
            for (int r = 0; r < 4; r++) acc[i][j][r] = 0.f;

#pragma unroll
    for (int s = 0; s < 2; ++s) {
        uint32_t b0 = sb + s * T32_STAGE;
        int kc0 = s * 32;
        gt_fill(b0,            A + (long)m0 * lda + kc0, lda, M - m0, t);
        gt_fill(b0 + T32_TILE, B + (long)n0 * K + kc0, K, N - n0, t);
        CP_COMMIT();
    }

    int stage = 0;
    for (int c = 0; c < nc; ++c) {
        CP_WAIT(1);
        __syncthreads();
        if (c + 2 < nc) {
            int ps = stage + 2; if (ps >= GSTAGES) ps -= GSTAGES;
            uint32_t bn = sb + ps * T32_STAGE;
            int kc0 = (c + 2) * 32;
            gt_fill(bn,            A + (long)m0 * lda + kc0, lda, M - m0, t);
            gt_fill(bn + T32_TILE, B + (long)n0 * K + kc0, K, N - n0, t);
        }
        CP_COMMIT();

        uint32_t sbase = sb + stage * T32_STAGE;
#pragma unroll
        for (int k8 = 0; k8 < 4; ++k8) {
            uint32_t swA = (uint32_t)(((2 * k8 + (q >> 1)) ^ lr) << 4);
            uint32_t swB = (uint32_t)(((2 * k8 + (q & 1)) ^ lr) << 4);
            uint32_t au[4][4];
#pragma unroll
            for (int im = 0; im < 4; ++im)
                ldsm4(au[im][0], au[im][1], au[im][2], au[im][3],
                      sbase + aRow[im] + swA);
            uint32_t bu[4][2];
#pragma unroll
            for (int p = 0; p < 2; ++p) {
                uint32_t r0, r1, r2, r3;
                ldsm4(r0, r1, r2, r3, sbase + bRow[p] + swB);
                bu[2 * p][0] = r0;     bu[2 * p][1] = r1;
                bu[2 * p + 1][0] = r2; bu[2 * p + 1][1] = r3;
            }
#pragma unroll
            for (int im = 0; im < 4; ++im)
#pragma unroll
                for (int jn = 0; jn < 4; ++jn)
                    mma_tf32(acc[im][jn], au[im][0], au[im][1], au[im][2], au[im][3],
                             bu[jn][0], bu[jn][1]);
        }
        if (++stage >= GSTAGES) stage = 0;
    }

#pragma unroll
    for (int im = 0; im < 4; ++im) {
        int row0 = m0 + wm * 64 + im * 16 + (lane >> 2);
#pragma unroll
        for (int jn = 0; jn < 4; ++jn) {
            int col = n0 + wn * 32 + jn * 8 + (lane & 3) * 2;
            if (col < N) {
                float2 v0 = make_float2(acc[im][jn][0], acc[im][jn][1]);
                float2 v1 = make_float2(acc[im][jn][2], acc[im][jn][3]);
                if (D) {
                    float2 d0 = *(const float2*)&D[(long)row0 * N + col];
                    float2 d1 = *(const float2*)&D[(long)(row0 + 8) * N + col];
                    v0.x = fmaf(beta, d0.x, v0.x); v0.y = fmaf(beta, d0.y, v0.y);
                    v1.x = fmaf(beta, d1.x, v1.x); v1.y = fmaf(beta, d1.y, v1.y);
                }
                *(float2*)&C[(long)row0 * N + col] = v0;
                *(float2*)&C[(long)(row0 + 8) * N + col] = v1;
            }
        }
    }
}

__global__ __launch_bounds__(256, 2)
void gemm_t32(const float* __restrict__ A, int lda, const float* __restrict__ B,
              float* __restrict__ C, int M, int N, int K,
              const float* __restrict__ D, float beta)
{
    extern __shared__ __align__(128) char smem[];
    gemm_t32_core(A, lda, B, C, M, N, K, D, beta, blockIdx.x, blockIdx.y, smem);
}

__global__ __launch_bounds__(256, 2)
void gemm_t32_dual(const float* __restrict__ A1, int lda1, const float* __restrict__ B1,
                   float* __restrict__ C1, int N1, int K1,
                   const float* __restrict__ A2, int lda2, const float* __restrict__ B2,
                   float* __restrict__ C2, int N2, int K2, int split)
{
    extern __shared__ __align__(128) char smem[];
    if ((int)blockIdx.x < split)
        gemm_t32_core(A1, lda1, B1, C1, SEQ, N1, K1, nullptr, 0.f,
                      blockIdx.x, blockIdx.y, smem);
    else
        gemm_t32_core(A2, lda2, B2, C2, SEQ, N2, K2, nullptr, 0.f,
                      blockIdx.x - split, blockIdx.y, smem);
}

// ---------------- RoPE + scatter ----------------------------------------------
__global__ void rope_scatter(const float* __restrict__ qin,    // [s][3072]
                             const float* __restrict__ qackv,  // [s][2112]
                             const float* __restrict__ kvin,   // [s][4096]
                             const int* __restrict__ pos_ids,
                             __nv_bfloat16* __restrict__ qh, __nv_bfloat16* __restrict__ ql,
                             float* __restrict__ kout,
                             __nv_bfloat16* __restrict__ kh, __nv_bfloat16* __restrict__ kl,
                             float* __restrict__ vout,
                             __nv_bfloat16* __restrict__ vh, __nv_bfloat16* __restrict__ vl)
{
    int s = blockIdx.x;
    int t = threadIdx.x;
    __shared__ float cs[32], sn[32], kr[64];
    if (t < 32) {
        double invf = exp(-(double)t * 0.28782313662425575); // ln(10000)/32
        double ang = (double)pos_ids[s] * invf;
        cs[t] = (float)cos(ang);
        sn[t] = (float)sin(ang);
    }
    __syncthreads();
    if (t < 32) {
        float x0 = qackv[(long)s * QKVN + 2048 + 2 * t];
        float x1 = qackv[(long)s * QKVN + 2048 + 2 * t + 1];
        kr[t]      = x0 * cs[t] - x1 * sn[t];
        kr[32 + t] = x1 * cs[t] + x0 * sn[t];
    }
    __syncthreads();
    for (int idx = t; idx < 512; idx += 256) {
        int h = idx >> 5, j = idx & 31;
        const float* qb = qin + (long)s * 3072 + h * 192;
        float x0 = qb[128 + 2 * j], x1 = qb[128 + 2 * j + 1];
        float a = x0 * cs[j] - x1 * sn[j];
        float b = x1 * cs[j] + x0 * sn[j];
        long o = ((long)h * SEQ + s) * 192;
        __nv_bfloat16 ha = __float2bfloat16(a), hb = __float2bfloat16(b);
        qh[o + 128 + j] = ha; ql[o + 128 + j] = __float2bfloat16(a - __bfloat162float(ha));
        qh[o + 160 + j] = hb; ql[o + 160 + j] = __float2bfloat16(b - __bfloat162float(hb));
    }
    for (int idx = t; idx < 2048; idx += 256) {
        int h = idx >> 7, d = idx & 127;
        float v = qin[(long)s * 3072 + h * 192 + d];
        long o = ((long)h * SEQ + s) * 192 + d;
        __nv_bfloat16 hv = __float2bfloat16(v);
        qh[o] = hv; ql[o] = __float2bfloat16(v - __bfloat162float(hv));
    }
    for (int idx = t; idx < 16 * 192; idx += 256) {
        int h = idx / 192, d = idx - h * 192;
        float v = (d < 128) ? kvin[(long)s * 4096 + h * 256 + d] : kr[d - 128];
        long o = ((long)h * SEQ + s) * 192 + d;
        kout[o] = v;
        __nv_bfloat16 hv = __float2bfloat16(v);
        kh[o] = hv; kl[o] = __float2bfloat16(v - __bfloat162float(hv));
    }
    for (int idx = t; idx < 2048; idx += 256) {
        int h = idx >> 7, d = idx & 127;
        float v = kvin[(long)s * 4096 + h * 256 + 128 + d];
        long o = ((long)h * SEQ + s) * 128 + d;
        vout[o] = v;
        __nv_bfloat16 hv = __float2bfloat16(v);
        vh[o] = hv; vl[o] = __float2bfloat16(v - __bfloat162float(hv));
    }
}

// ---------------- flash attention: 128-row Q tile, 32-key stages --------------
#define FPADB 400
#define VPADB 272
#define QT_B (128 * FPADB)
#define KT_B (32 * FPADB)
#define VT_B (32 * VPADB)
#define KV_BASE (2 * QT_B)
#define KV_STAGE (2 * KT_B + 2 * VT_B)
#define FLASH_SMEM (KV_BASE + 2 * KV_STAGE)  // 188416

__device__ __forceinline__ void f_fill_kv(uint32_t dst,
                                          const __nv_bfloat16* __restrict__ Kh,
                                          const __nv_bfloat16* __restrict__ Kl,
                                          const __nv_bfloat16* __restrict__ Vh,
                                          const __nv_bfloat16* __restrict__ Vl,
                                          long k0, int t)
{
#pragma unroll
    for (int i = 0; i < 3; ++i) {
        int id = t + 256 * i;
        int row = id / 24, ch = id % 24;
        cpa16(dst + row * FPADB + ch * 16, Kh + (k0 + row) * 192 + ch * 8, 16);
        cpa16(dst + KT_B + row * FPADB + ch * 16, Kl + (k0 + row) * 192 + ch * 8, 16);
    }
#pragma unroll
    for (int i = 0; i < 2; ++i) {
        int id = t + 256 * i;
        int row = id >> 4, ch = id & 15;
        cpa16(dst + 2 * KT_B + row * VPADB + ch * 16, Vh + (k0 + row) * 128 + ch * 8, 16);
        cpa16(dst + 2 * KT_B + VT_B + row * VPADB + ch * 16, Vl + (k0 + row) * 128 + ch * 8, 16);
    }
}

__global__ __launch_bounds__(256, 1)
void flash_mma(const __nv_bfloat16* __restrict__ Qh_g, const __nv_bfloat16* __restrict__ Ql_g,
               const __nv_bfloat16* __restrict__ Kh_g, const __nv_bfloat16* __restrict__ Kl_g,
               const __nv_bfloat16* __restrict__ Vh_g, const __nv_bfloat16* __restrict__ Vl_g,
               float* __restrict__ O_g)
{
    extern __shared__ __align__(128) char smem[];
    uint32_t sb = smem_u32(smem);
    int qt = (int)gridDim.x - 1 - (int)blockIdx.x;
    int h = blockIdx.y;
    int q0 = qt * 128;
    int t = threadIdx.x;
    int warp = t >> 5, lane = t & 31;

    const __nv_bfloat16* Kgh = Kh_g + (long)h * SEQ * 192;
    const __nv_bfloat16* Kgl = Kl_g + (long)h * SEQ * 192;
    const __nv_bfloat16* Vgh = Vh_g + (long)h * SEQ * 128;
    const __nv_bfloat16* Vgl = Vl_g + (long)h * SEQ * 128;

    {
        const __nv_bfloat16* qg = Qh_g + ((long)h * SEQ + q0) * 192;
        const __nv_bfloat16* qg2 = Ql_g + ((long)h * SEQ + q0) * 192;
#pragma unroll
        for (int i = 0; i < 12; ++i) {
            int id = t + 256 * i;
            int row = id / 24, ch = id % 24;
            cpa16(sb + row * FPADB + ch * 16, qg + (long)row * 192 + ch * 8, 16);
            cpa16(sb + QT_B + row * FPADB + ch * 16, qg2 + (long)row * 192 + ch * 8, 16);
        }
        CP_COMMIT();
    }
    f_fill_kv(sb + KV_BASE, Kgh, Kgl, Vgh, Vgl, 0, t);
    CP_COMMIT();

    float o[16][4];
#pragma unroll
    for (int i = 0; i < 16; i++)
#pragma unroll
        for (int r = 0; r < 4; r++) o[i][r] = 0.f;
    float mrow[2] = {-1e30f, -1e30f};
    float lrow[2] = {0.f, 0.f};

    uint32_t qoff = (uint32_t)((warp * 16 + (lane & 15)) * FPADB + (lane >> 4) * 16);
    uint32_t koff = (uint32_t)(((lane & 7) + ((lane >> 4) << 3)) * FPADB +
                               ((lane >> 3) & 1) * 16);
    uint32_t voff = (uint32_t)(((lane & 7) + (((lane >> 3) & 1) << 3)) * VPADB +
                               ((lane >> 4) << 3) * 2);

    int rA = (lane >> 2);
    int colq = (lane & 3) * 2;
    int rowA = q0 + warp * 16 + rA;
    int rowB = rowA + 8;
    int nkt = 4 * qt + 4;

    for (int kt = 0; kt < nkt; ++kt) {
        __syncthreads();
        if (kt + 1 < nkt)
            f_fill_kv(sb + KV_BASE + ((kt + 1) & 1) * KV_STAGE, Kgh, Kgl, Vgh, Vgl,
                      (long)(kt + 1) * 32, t);
        CP_COMMIT();
        CP_WAIT(1);
        __syncthreads();

        int k0 = kt * 32;
        uint32_t kvb = sb + KV_BASE + (kt & 1) * KV_STAGE;

        float sc[4][4];
#pragma unroll
        for (int j = 0; j < 4; j++)
#pragma unroll
            for (int r = 0; r < 4; r++) sc[j][r] = 0.f;

#pragma unroll 1
        for (int k16 = 0; k16 < 12; ++k16) {
            uint32_t qfh[4], qfl[4];
            uint32_t addr = sb + qoff + k16 * 32;
            ldsm4(qfh[0], qfh[1], qfh[2], qfh[3], addr);
            ldsm4(qfl[0], qfl[1], qfl[2], qfl[3], addr + QT_B);
            uint32_t kbh[4][2], kbl[4][2];
#pragma unroll
            for (int j2 = 0; j2 < 2; ++j2) {
                uint32_t ka = kvb + koff + j2 * 16 * FPADB + k16 * 32;
                uint32_t r0, r1, r2, r3;
                ldsm4(r0, r1, r2, r3, ka);
                kbh[2 * j2][0] = r0; kbh[2 * j2][1] = r1;
                kbh[2 * j2 + 1][0] = r2; kbh[2 * j2 + 1][1] = r3;
                ldsm4(r0, r1, r2, r3, ka + KT_B);
                kbl[2 * j2][0] = r0; kbl[2 * j2][1] = r1;
                kbl[2 * j2 + 1][0] = r2; kbl[2 * j2 + 1][1] = r3;
            }
#pragma unroll
            for (int j = 0; j < 4; ++j)
                mma16816(sc[j], qfh[0], qfh[1], qfh[2], qfh[3], kbh[j][0], kbh[j][1]);
#pragma unroll
            for (int j = 0; j < 4; ++j)
                mma16816(sc[j], qfh[0], qfh[1], qfh[2], qfh[3], kbl[j][0], kbl[j][1]);
#pragma unroll
            for (int j = 0; j < 4; ++j)
                mma16816(sc[j], qfl[0], qfl[1], qfl[2], qfl[3], kbh[j][0], kbh[j][1]);
        }

        bool diag = (kt >= 4 * qt);
#pragma unroll
        for (int j = 0; j < 4; ++j) {
#pragma unroll
            for (int r = 0; r < 4; r++) sc[j][r] *= SM_SCALE;
            if (diag) {
                int col = k0 + j * 8 + colq;
                if (col > rowA)     sc[j][0] = -1e30f;
                if (col + 1 > rowA) sc[j][1] = -1e30f;
                if (col > rowB)     sc[j][2] = -1e30f;
                if (col + 1 > rowB) sc[j][3] = -1e30f;
            }
        }
        float mxa = -1e30f, mxb = -1e30f;
#pragma unroll
        for (int j = 0; j < 4; ++j) {
            mxa = fmaxf(mxa, fmaxf(sc[j][0], sc[j][1]));
            mxb = fmaxf(mxb, fmaxf(sc[j][2], sc[j][3]));
        }
        mxa = fmaxf(mxa, __shfl_xor_sync(0xffffffffu, mxa, 1));
        mxa = fmaxf(mxa, __shfl_xor_sync(0xffffffffu, mxa, 2));
        mxb = fmaxf(mxb, __shfl_xor_sync(0xffffffffu, mxb, 1));
        mxb = fmaxf(mxb, __shfl_xor_sync(0xffffffffu, mxb, 2));
        float mna = fmaxf(mrow[0], mxa), mnb = fmaxf(mrow[1], mxb);
        float ala = __expf(mrow[0] - mna), alb = __expf(mrow[1] - mnb);
        mrow[0] = mna; mrow[1] = mnb;

        float suma = 0.f, sumb = 0.f;
#pragma unroll
        for (int j = 0; j < 4; ++j) {
            sc[j][0] = __expf(sc[j][0] - mna);
            sc[j][1] = __expf(sc[j][1] - mna);
            sc[j][2] = __expf(sc[j][2] - mnb);
            sc[j][3] = __expf(sc[j][3] - mnb);
            suma += sc[j][0] + sc[j][1];
            sumb += sc[j][2] + sc[j][3];
        }
        suma += __shfl_xor_sync(0xffffffffu, suma, 1);
        suma += __shfl_xor_sync(0xffffffffu, suma, 2);
        sumb += __shfl_xor_sync(0xffffffffu, sumb, 1);
        sumb += __shfl_xor_sync(0xffffffffu, sumb, 2);
        lrow[0] = lrow[0] * ala + suma;
        lrow[1] = lrow[1] * alb + sumb;
#pragma unroll
        for (int nb = 0; nb < 16; ++nb) {
            o[nb][0] *= ala; o[nb][1] *= ala;
            o[nb][2] *= alb; o[nb][3] *= alb;
        }

        uint32_t pah[2][4], pal[2][4];
#pragma unroll
        for (int j = 0; j < 2; ++j) {
            split2(sc[2 * j][0],     sc[2 * j][1],     pah[j][0], pal[j][0]);
            split2(sc[2 * j][2],     sc[2 * j][3],     pah[j][1], pal[j][1]);
            split2(sc[2 * j + 1][0], sc[2 * j + 1][1], pah[j][2], pal[j][2]);
            split2(sc[2 * j + 1][2], sc[2 * j + 1][3], pah[j][3], pal[j][3]);
        }

        uint32_t vbase = kvb + 2 * KT_B;
#pragma unroll 1
        for (int j = 0; j < 2; ++j) {
#pragma unroll
            for (int nb2 = 0; nb2 < 8; ++nb2) {
                uint32_t va = vbase + voff + j * 16 * VPADB + nb2 * 32;
                uint32_t h0, h1, h2, h3, l0, l1, l2, l3;
                ldsm4t(h0, h1, h2, h3, va);
                ldsm4t(l0, l1, l2, l3, va + VT_B);
                mma16816(o[2 * nb2],     pah[j][0], pah[j][1], pah[j][2], pah[j][3], h0, h1);
                mma16816(o[2 * nb2 + 1], pah[j][0], pah[j][1], pah[j][2], pah[j][3], h2, h3);
                mma16816(o[2 * nb2],     pah[j][0], pah[j][1], pah[j][2], pah[j][3], l0, l1);
                mma16816(o[2 * nb2 + 1], pah[j][0], pah[j][1], pah[j][2], pah[j][3], l2, l3);
                mma16816(o[2 * nb2],     pal[j][0], pal[j][1], pal[j][2], pal[j][3], h0, h1);
                mma16816(o[2 * nb2 + 1], pal[j][0], pal[j][1], pal[j][2], pal[j][3], h2, h3);
            }
        }
    }

    // epilogue: normalize and store tf32-rounded fp32 into [s][2048]
    float inva = 1.0f / lrow[0], invb = 1.0f / lrow[1];
#pragma unroll
    for (int nb = 0; nb < 16; ++nb) {
        int col = h * 128 + nb * 8 + colq;
        float2 vA = make_float2(tf32r(o[nb][0] * inva), tf32r(o[nb][1] * inva));
        float2 vB = make_float2(tf32r(o[nb][2] * invb), tf32r(o[nb][3] * invb));
        *(float2*)&O_g[(long)rowA * 2048 + col] = vA;
        *(float2*)&O_g[(long)rowB * 2048 + col] = vB;
    }
}

// ---------------- launch ------------------------------------------------------
extern "C" void kernel_launch(void* const* d_in, const int* in_sizes, int n_in,
                              void* d_out, int out_size)
{
    const float* hidden   = (const float*)d_in[0];
    const int*   pos      = (const int*)d_in[1];
    const float* ln_w     = (const float*)d_in[3];
    const float* wq_a     = (const float*)d_in[4];
    const float* q_a_ln   = (const float*)d_in[5];
    const float* wq_b     = (const float*)d_in[6];
    const float* wkv_a    = (const float*)d_in[7];
    const float* kv_a_ln  = (const float*)d_in[8];
    const float* wkv_b    = (const float*)d_in[9];
    const float* wo       = (const float*)d_in[10];

    float* out   = (float*)d_out;
    float* k_out = out + (long)SEQ * HIDDEN;
    float* v_out = k_out + (long)NHEADS * SEQ * QKD;

    float *p_qackv, *p_q, *p_kv, *p_attn, *p_h, *p_qa, *p_ckvn;
    float *p_wqkva, *p_wqb, *p_wkvb, *p_wo;
    cudaGetSymbolAddress((void**)&p_qackv, g_qackv);
    cudaGetSymbolAddress((void**)&p_q, g_q);
    cudaGetSymbolAddress((void**)&p_kv, g_kv);
    cudaGetSymbolAddress((void**)&p_attn, g_attn_f);
    cudaGetSymbolAddress((void**)&p_h, g_h_f);
    cudaGetSymbolAddress((void**)&p_qa, g_qa_f);
    cudaGetSymbolAddress((void**)&p_ckvn, g_ckvn_f);
    cudaGetSymbolAddress((void**)&p_wqkva, g_wqkva_f);
    cudaGetSymbolAddress((void**)&p_wqb, g_wqb_f);
    cudaGetSymbolAddress((void**)&p_wkvb, g_wkvb_f);
    cudaGetSymbolAddress((void**)&p_wo, g_wo_f);

    __nv_bfloat16 *qf_hi, *qf_lo, *k_hi, *k_lo, *v_hi, *v_lo;
    cudaGetSymbolAddress((void**)&qf_hi, g_qf_hi);     cudaGetSymbolAddress((void**)&qf_lo, g_qf_lo);
    cudaGetSymbolAddress((void**)&k_hi, g_k_hi);       cudaGetSymbolAddress((void**)&k_lo, g_k_lo);
    cudaGetSymbolAddress((void**)&v_hi, g_v_hi);       cudaGetSymbolAddress((void**)&v_lo, g_v_lo);

    cudaFuncSetAttribute(gemm_t32, cudaFuncAttributeMaxDynamicSharedMemorySize, GEMM_SMEM);
    cudaFuncSetAttribute(gemm_t32_dual, cudaFuncAttributeMaxDynamicSharedMemorySize, GEMM_SMEM);
    cudaFuncSetAttribute(flash_mma, cudaFuncAttributeMaxDynamicSharedMemorySize, FLASH_SMEM);

    long c0 = (long)QLORA * HIDDEN / 4;
    long c1 = c0 + (long)576 * HIDDEN / 4;
    long c2 = c1 + (long)3072 * QLORA / 4;
    long c3 = c2 + (long)4096 * KVLORA / 4;
    long c4 = c3 + (long)HIDDEN * 2048 / 4;
    cvt_tf32_multi<<<1184, 256>>>(
        wq_a,  p_wqkva, c0,
        wkv_a, p_wqkva + (long)QLORA * HIDDEN, c1,
        wq_b,  p_wqb, c2,
        wkv_b, p_wkvb, c3,
        wo,    p_wo, c4);

    rmsnorm_f32<<<SEQ, 256>>>(hidden, ln_w, p_h, HIDDEN, HIDDEN, HIDDEN);
    gemm_t32<<<dim3(17, SEQ / 128), 256, GEMM_SMEM>>>(
        p_h, HIDDEN, p_wqkva, p_qackv, SEQ, QKVN, HIDDEN, nullptr, 0.f);
    rmsnorm_f32<<<SEQ, 256>>>(p_qackv, q_a_ln, p_qa, QLORA, QKVN, QLORA);
    rmsnorm_f32<<<SEQ, 256>>>(p_qackv + QLORA, kv_a_ln, p_ckvn, KVLORA, QKVN, KVLORA);
    gemm_t32_dual<<<dim3(24 + 32, SEQ / 128), 256, GEMM_SMEM>>>(
        p_qa, QLORA, p_wqb, p_q, 3072, QLORA,
        p_ckvn, KVLORA, p_wkvb, p_kv, 4096, KVLORA, 24);
    rope_scatter<<<SEQ, 256>>>(p_q, p_qackv, p_kv, pos, qf_hi, qf_lo,
                               k_out, k_hi, k_lo, v_out, v_hi, v_lo);
    flash_mma<<<dim3(SEQ / 128, NHEADS), 256, FLASH_SMEM>>>(
        qf_hi, qf_lo, k_hi, k_lo, v_hi, v_lo, p_attn);
    gemm_t32<<<dim3(HIDDEN / 128, SEQ / 128), 256, GEMM_SMEM>>>(
        p_attn, 2048, p_wo, out, SEQ, HIDDEN, 2048, hidden, RESID_SCALE);
}

// round 14
// speedup vs baseline: 1.9359x; 1.0164x over previous
#include <cuda_runtime.h>
#include <cuda_bf16.h>
#include <math.h>
#include <stdint.h>

#define HIDDEN 5120
#define NHEADS 16
#define QLORA  1536
#define KVLORA 512
#define NOPE   128
#define ROPE_D 64
#define QKD    192
#define VDIM   128
#define SEQ    2048
#define QKVN   2112
#define SM_SCALE 0.07216878364870322f  // 192^-0.5
#define RESID_SCALE 0.125f

// ---------------- scratch ----------------------------------------------------
static __device__ float g_qackv[SEQ * QKVN];
static __device__ float g_q[SEQ * NHEADS * QKD];
static __device__ float g_kv[SEQ * 4096];
static __device__ float g_attn_f[SEQ * 2048];

static __device__ float g_h_f[SEQ * HIDDEN];
static __device__ float g_qa_f[SEQ * QLORA];
static __device__ float g_ckvn_f[SEQ * KVLORA];
static __device__ float g_wqkva_f[QKVN * HIDDEN];
static __device__ float g_wqb_f[3072 * QLORA];
static __device__ float g_wkvb_f[4096 * KVLORA];
static __device__ float g_wo_f[HIDDEN * 2048];

static __device__ __nv_bfloat16 g_qf_hi[NHEADS * SEQ * QKD], g_qf_lo[NHEADS * SEQ * QKD];
static __device__ __nv_bfloat16 g_k_hi[NHEADS * SEQ * QKD],  g_k_lo[NHEADS * SEQ * QKD];
static __device__ __nv_bfloat16 g_v_hi[NHEADS * SEQ * VDIM], g_v_lo[NHEADS * SEQ * VDIM];

// ---------------- helpers ----------------------------------------------------
__device__ __forceinline__ uint32_t smem_u32(const void* p) {
    return (uint32_t)__cvta_generic_to_shared(p);
}
__device__ __forceinline__ void cpa16(uint32_t dst, const void* src, int sz) {
    asm volatile("cp.async.cg.shared.global [%0], [%1], 16, %2;"
                 :: "r"(dst), "l"(src), "r"(sz) : "memory");
}
#define CP_COMMIT() asm volatile("cp.async.commit_group;" ::: "memory")
#define CP_WAIT(n)  asm volatile("cp.async.wait_group %0;" :: "n"(n) : "memory")

__device__ __forceinline__ void ldsm4(uint32_t& r0, uint32_t& r1, uint32_t& r2, uint32_t& r3,
                                      uint32_t addr) {
    asm volatile("ldmatrix.sync.aligned.m8n8.x4.shared.b16 {%0,%1,%2,%3}, [%4];"
                 : "=r"(r0), "=r"(r1), "=r"(r2), "=r"(r3) : "r"(addr));
}
__device__ __forceinline__ void ldsm4t(uint32_t& r0, uint32_t& r1, uint32_t& r2, uint32_t& r3,
                                       uint32_t addr) {
    asm volatile("ldmatrix.sync.aligned.m8n8.x4.trans.shared.b16 {%0,%1,%2,%3}, [%4];"
                 : "=r"(r0), "=r"(r1), "=r"(r2), "=r"(r3) : "r"(addr));
}
__device__ __forceinline__ void mma16816(float* c, uint32_t a0, uint32_t a1, uint32_t a2,
                                         uint32_t a3, uint32_t b0, uint32_t b1) {
    asm volatile(
        "mma.sync.aligned.m16n8k16.row.col.f32.bf16.bf16.f32 "
        "{%0,%1,%2,%3}, {%4,%5,%6,%7}, {%8,%9}, {%0,%1,%2,%3};"
        : "+f"(c[0]), "+f"(c[1]), "+f"(c[2]), "+f"(c[3])
        : "r"(a0), "r"(a1), "r"(a2), "r"(a3), "r"(b0), "r"(b1));
}
__device__ __forceinline__ void mma_tf32(float* c, uint32_t a0, uint32_t a1, uint32_t a2,
                                         uint32_t a3, uint32_t b0, uint32_t b1) {
    asm volatile(
        "mma.sync.aligned.m16n8k8.row.col.f32.tf32.tf32.f32 "
        "{%0,%1,%2,%3}, {%4,%5,%6,%7}, {%8,%9}, {%0,%1,%2,%3};"
        : "+f"(c[0]), "+f"(c[1]), "+f"(c[2]), "+f"(c[3])
        : "r"(a0), "r"(a1), "r"(a2), "r"(a3), "r"(b0), "r"(b1));
}
__device__ __forceinline__ float tf32r(float x) {
    uint32_t u;
    asm("cvt.rna.tf32.f32 %0, %1;" : "=r"(u) : "f"(x));
    return __uint_as_float(u);
}
__device__ __forceinline__ void split2(float v0, float v1, uint32_t& hi, uint32_t& lo) {
    __nv_bfloat16 h0 = __float2bfloat16(v0), h1 = __float2bfloat16(v1);
    float r0 = v0 - __bfloat162float(h0), r1 = v1 - __bfloat162float(h1);
    __nv_bfloat162 th; th.x = h0; th.y = h1;
    hi = *reinterpret_cast<uint32_t*>(&th);
    __nv_bfloat162 tl; tl.x = __float2bfloat16(r0); tl.y = __float2bfloat16(r1);
    lo = *reinterpret_cast<uint32_t*>(&tl);
}

// ---------------- shared elementwise bodies -----------------------------------
__device__ __forceinline__ void cvt_body(const float* __restrict__ src, float* __restrict__ dst,
                                         long n4, long bid, long nb)
{
    const float4* s4 = (const float4*)src;
    float4* d4 = (float4*)dst;
    for (long i = bid * 256 + threadIdx.x; i < n4; i += nb * 256) {
        float4 v = s4[i];
        v.x = tf32r(v.x); v.y = tf32r(v.y); v.z = tf32r(v.z); v.w = tf32r(v.w);
        d4[i] = v;
    }
}

__device__ __forceinline__ void rms_body(const float* __restrict__ x, const float* __restrict__ w,
                                         float* __restrict__ y,
                                         int cols, int strideIn, int strideOut, int row)
{
    __shared__ float red[256];
    int t = threadIdx.x;
    const float4* xr = (const float4*)(x + (long)row * strideIn);
    const float4* w4 = (const float4*)w;
    int c4 = cols >> 2;
    float ss = 0.f;
    for (int c = t; c < c4; c += 256) {
        float4 v = xr[c];
        ss = fmaf(v.x, v.x, fmaf(v.y, v.y, fmaf(v.z, v.z, fmaf(v.w, v.w, ss))));
    }
    red[t] = ss; __syncthreads();
    for (int s = 128; s > 0; s >>= 1) { if (t < s) red[t] += red[t + s]; __syncthreads(); }
    float scale = rsqrtf(red[0] / (float)cols + 1e-6f);
    float4* yr = (float4*)(y + (long)row * strideOut);
    for (int c = t; c < c4; c += 256) {
        float4 v = xr[c];
        float4 wv = w4[c];
        float4 o;
        o.x = tf32r(v.x * scale * wv.x);
        o.y = tf32r(v.y * scale * wv.y);
        o.z = tf32r(v.z * scale * wv.z);
        o.w = tf32r(v.w * scale * wv.w);
        yr[c] = o;
    }
}

// A: rmsnorm(hidden) + tf32-round wq_a and wkv_a (extra blocks, 2 ranges)
__global__ void rms_cvt_A(const float* __restrict__ x, const float* __restrict__ w,
                          float* __restrict__ y,
                          const float* __restrict__ ws1, float* __restrict__ wd1, long n1,
                          const float* __restrict__ ws2, float* __restrict__ wd2, long n2)
{
    if ((int)blockIdx.x < SEQ)
        rms_body(x, w, y, HIDDEN, HIDDEN, HIDDEN, blockIdx.x);
    else {
        long bid = blockIdx.x - SEQ, nb = gridDim.x - SEQ;
        cvt_body(ws1, wd1, n1, bid, nb);
        cvt_body(ws2, wd2, n2, bid, nb);
    }
}

// B: rmsnorm(qa) + rmsnorm(ckv) + tf32-round wqb & wkvb (extra blocks)
__global__ void rms_cvt_B(const float* __restrict__ qackv,
                          const float* __restrict__ qw, float* __restrict__ qy,
                          const float* __restrict__ cw, float* __restrict__ cy,
                          const float* __restrict__ ws1, float* __restrict__ wd1, long n1,
                          const float* __restrict__ ws2, float* __restrict__ wd2, long n2)
{
    if ((int)blockIdx.x < SEQ)
        rms_body(qackv, qw, qy, QLORA, QKVN, QLORA, blockIdx.x);
    else if ((int)blockIdx.x < 2 * SEQ)
        rms_body(qackv + QLORA, cw, cy, KVLORA, QKVN, KVLORA, blockIdx.x - SEQ);
    else {
        long bid = blockIdx.x - 2 * SEQ, nb = gridDim.x - 2 * SEQ;
        cvt_body(ws1, wd1, n1, bid, nb);
        cvt_body(ws2, wd2, n2, bid, nb);
    }
}

// ---------------- tf32 single-pass GEMM (ldmatrix frags), 3 stages ------------
#define T32_TILE 16384
#define T32_STAGE (2 * T32_TILE)
#define GSTAGES 3
#define GEMM_SMEM (GSTAGES * T32_STAGE)  // 98304; 2 CTAs/SM

__device__ __forceinline__ void gt_fill(uint32_t dstBase, const float* __restrict__ src,
                                        long ld, int rmax, int t)
{
#pragma unroll
    for (int i = 0; i < 4; ++i) {
        int id = t + 256 * i;
        int row = id >> 3, ch = id & 7;
        bool ok = row < rmax;
        const float* g = src + (long)(ok ? row : 0) * ld + ch * 4;
        uint32_t cs = (uint32_t)(ch ^ (row & 7));
        cpa16(dstBase + row * 128 + cs * 16, g, ok ? 16 : 0);
    }
}

__device__ __forceinline__ void gemm_t32_core(
    const float* __restrict__ A, int lda,
    const float* __restrict__ B,
    float* __restrict__ C, int M, int N, int K,
    const float* __restrict__ D, float beta,
    int bx, int by, char* smem)
{
    uint32_t sb = smem_u32(smem);
    int t = threadIdx.x;
    int warp = t >> 5, lane = t & 31;
    int wm = warp >> 2, wn = warp & 3;
    int n0 = bx * 128, m0 = by * 128;
    int nc = K / 32;
    int q = lane >> 3, lr = lane & 7;

    uint32_t aRow[4];
#pragma unroll
    for (int im = 0; im < 4; ++im)
        aRow[im] = (uint32_t)((wm * 64 + im * 16 + ((q & 1) << 3) + lr) * 128);
    uint32_t bRow[2];
#pragma unroll
    for (int p = 0; p < 2; ++p)
        bRow[p] = (uint32_t)((wn * 32 + ((2 * p + (q >> 1)) << 3) + lr) * 128) + T32_TILE;

    float acc[4][4][4];
#pragma unroll
    for (int i = 0; i < 4; i++)
#pragma unroll
        for (int j = 0; j < 4; j++)
#pragma unroll
            for (int r = 0; r < 4; r++) acc[i][j][r] = 0.f;

#pragma unroll
    for (int s = 0; s < 2; ++s) {
        uint32_t b0 = sb + s * T32_STAGE;
        int kc0 = s * 32;
        gt_fill(b0,            A + (long)m0 * lda + kc0, lda, M - m0, t);
        gt_fill(b0 + T32_TILE, B + (long)n0 * K + kc0, K, N - n0, t);
        CP_COMMIT();
    }

    int stage = 0;
    for (int c = 0; c < nc; ++c) {
        CP_WAIT(1);
        __syncthreads();
        if (c + 2 < nc) {
            int ps = stage + 2; if (ps >= GSTAGES) ps -= GSTAGES;
            uint32_t bn = sb + ps * T32_STAGE;
            int kc0 = (c + 2) * 32;
            gt_fill(bn,            A + (long)m0 * lda + kc0, lda, M - m0, t);
            gt_fill(bn + T32_TILE, B + (long)n0 * K + kc0, K, N - n0, t);
        }
        CP_COMMIT();

        uint32_t sbase = sb + stage * T32_STAGE;
#pragma unroll
        for (int k8 = 0; k8 < 4; ++k8) {
            uint32_t swA = (uint32_t)(((2 * k8 + (q >> 1)) ^ lr) << 4);
            uint32_t swB = (uint32_t)(((2 * k8 + (q & 1)) ^ lr) << 4);
            uint32_t au[4][4];
#pragma unroll
            for (int im = 0; im < 4; ++im)
                ldsm4(au[im][0], au[im][1], au[im][2], au[im][3],
                      sbase + aRow[im] + swA);
            uint32_t bu[4][2];
#pragma unroll
            for (int p = 0; p < 2; ++p) {
                uint32_t r0, r1, r2, r3;
                ldsm4(r0, r1, r2, r3, sbase + bRow[p] + swB);
                bu[2 * p][0] = r0;     bu[2 * p][1] = r1;
                bu[2 * p + 1][0] = r2; bu[2 * p + 1][1] = r3;
            }
#pragma unroll
            for (int im = 0; im < 4; ++im)
#pragma unroll
                for (int jn = 0; jn < 4; ++jn)
                    mma_tf32(acc[im][jn], au[im][0], au[im][1], au[im][2], au[im][3],
                             bu[jn][0], bu[jn][1]);
        }
        if (++stage >= GSTAGES) stage = 0;
    }

#pragma unroll
    for (int im = 0; im < 4; ++im) {
        int row0 = m0 + wm * 64 + im * 16 + (lane >> 2);
#pragma unroll
        for (int jn = 0; jn < 4; ++jn) {
            int col = n0 + wn * 32 + jn * 8 + (lane & 3) * 2;
            if (col < N) {
                float2 v0 = make_float2(acc[im][jn][0], acc[im][jn][1]);
                float2 v1 = make_float2(acc[im][jn][2], acc[im][jn][3]);
                if (D) {
                    float2 d0 = *(const float2*)&D[(long)row0 * N + col];
                    float2 d1 = *(const float2*)&D[(long)(row0 + 8) * N + col];
                    v0.x = fmaf(beta, d0.x, v0.x); v0.y = fmaf(beta, d0.y, v0.y);
                    v1.x = fmaf(beta, d1.x, v1.x); v1.y = fmaf(beta, d1.y, v1.y);
                }
                *(float2*)&C[(long)row0 * N + col] = v0;
                *(float2*)&C[(long)(row0 + 8) * N + col] = v1;
            }
        }
    }
}

__global__ __launch_bounds__(256, 2)
void gemm_t32(const float* __restrict__ A, int lda, const float* __restrict__ B,
              float* __restrict__ C, int M, int N, int K,
              const float* __restrict__ D, float beta)
{
    extern __shared__ __align__(128) char smem[];
    gemm_t32_core(A, lda, B, C, M, N, K, D, beta, blockIdx.x, blockIdx.y, smem);
}

__global__ __launch_bounds__(256, 2)
void gemm_t32_dual(const float* __restrict__ A1, int lda1, const float* __restrict__ B1,
                   float* __restrict__ C1, int N1, int K1,
                   const float* __restrict__ A2, int lda2, const float* __restrict__ B2,
                   float* __restrict__ C2, int N2, int K2, int split)
{
    extern __shared__ __align__(128) char smem[];
    if ((int)blockIdx.x < split)
        gemm_t32_core(A1, lda1, B1, C1, SEQ, N1, K1, nullptr, 0.f,
                      blockIdx.x, blockIdx.y, smem);
    else
        gemm_t32_core(A2, lda2, B2, C2, SEQ, N2, K2, nullptr, 0.f,
                      blockIdx.x - split, blockIdx.y, smem);
}

// ---------------- RoPE + scatter (vectorized) + wo tf32-round -----------------
__global__ void rope_scatter_cvt(const float* __restrict__ qin,
                                 const float* __restrict__ qackv,
                                 const float* __restrict__ kvin,
                                 const int* __restrict__ pos_ids,
                                 __nv_bfloat16* __restrict__ qh, __nv_bfloat16* __restrict__ ql,
                                 float* __restrict__ kout,
                                 __nv_bfloat16* __restrict__ kh, __nv_bfloat16* __restrict__ kl,
                                 float* __restrict__ vout,
                                 __nv_bfloat16* __restrict__ vh, __nv_bfloat16* __restrict__ vl,
                                 const float* __restrict__ ws, float* __restrict__ wd, long n4)
{
    if ((int)blockIdx.x >= SEQ) {
        cvt_body(ws, wd, n4, blockIdx.x - SEQ, gridDim.x - SEQ);
        return;
    }
    int s = blockIdx.x;
    int t = threadIdx.x;
    __shared__ float cs[32], sn[32], kr[64];
    if (t < 32) {
        double invf = exp(-(double)t * 0.28782313662425575); // ln(10000)/32
        double ang = (double)pos_ids[s] * invf;
        cs[t] = (float)cos(ang);
        sn[t] = (float)sin(ang);
    }
    __syncthreads();
    if (t < 32) {
        float x0 = qackv[(long)s * QKVN + 2048 + 2 * t];
        float x1 = qackv[(long)s * QKVN + 2048 + 2 * t + 1];
        kr[t]      = x0 * cs[t] - x1 * sn[t];
        kr[32 + t] = x1 * cs[t] + x0 * sn[t];
    }
    __syncthreads();
    // q pe: 256 ids = (h, j-pair)
    {
        int h = t >> 4, j2 = t & 15;
        int j0 = 2 * j2, j1 = j0 + 1;
        const float* qb = qin + (long)s * 3072 + h * 192;
        float x0 = qb[128 + 2 * j0], x1 = qb[128 + 2 * j0 + 1];
        float x2 = qb[128 + 2 * j1], x3 = qb[128 + 2 * j1 + 1];
        float a0 = x0 * cs[j0] - x1 * sn[j0];
        float b0 = x1 * cs[j0] + x0 * sn[j0];
        float a1 = x2 * cs[j1] - x3 * sn[j1];
        float b1 = x3 * cs[j1] + x2 * sn[j1];
        long o = ((long)h * SEQ + s) * 192;
        uint32_t hi, lo;
        split2(a0, a1, hi, lo);
        *(uint32_t*)&qh[o + 128 + j0] = hi; *(uint32_t*)&ql[o + 128 + j0] = lo;
        split2(b0, b1, hi, lo);
        *(uint32_t*)&qh[o + 160 + j0] = hi; *(uint32_t*)&ql[o + 160 + j0] = lo;
    }
    // q nope: 1024 pairs
    for (int idx = t; idx < 1024; idx += 256) {
        int h = idx >> 6, d = (idx & 63) * 2;
        float2 v = *(const float2*)&qin[(long)s * 3072 + h * 192 + d];
        long o = ((long)h * SEQ + s) * 192 + d;
        uint32_t hi, lo;
        split2(v.x, v.y, hi, lo);
        *(uint32_t*)&qh[o] = hi; *(uint32_t*)&ql[o] = lo;
    }
    // k: 1536 pairs
    for (int idx = t; idx < 1536; idx += 256) {
        int h = idx / 96, d = (idx - h * 96) * 2;
        float2 v;
        if (d < 128) v = *(const float2*)&kvin[(long)s * 4096 + h * 256 + d];
        else         v = make_float2(kr[d - 128], kr[d - 127]);
        long o = ((long)h * SEQ + s) * 192 + d;
        *(float2*)&kout[o] = v;
        uint32_t hi, lo;
        split2(v.x, v.y, hi, lo);
        *(uint32_t*)&kh[o] = hi; *(uint32_t*)&kl[o] = lo;
    }
    // v: 1024 pairs
    for (int idx = t; idx < 1024; idx += 256) {
        int h = idx >> 6, d = (idx & 63) * 2;
        float2 v = *(const float2*)&kvin[(long)s * 4096 + h * 256 + 128 + d];
        long o = ((long)h * SEQ + s) * 128 + d;
        *(float2*)&vout[o] = v;
        uint32_t hi, lo;
        split2(v.x, v.y, hi, lo);
        *(uint32_t*)&vh[o] = hi; *(uint32_t*)&vl[o] = lo;
    }
}

// ---------------- flash attention: 128-row Q tile, 32-key stages --------------
#define FPADB 400
#define VPADB 272
#define QT_B (128 * FPADB)
#define KT_B (32 * FPADB)
#define VT_B (32 * VPADB)
#define KV_BASE (2 * QT_B)
#define KV_STAGE (2 * KT_B + 2 * VT_B)
#define FLASH_SMEM (KV_BASE + 2 * KV_STAGE)  // 188416

__device__ __forceinline__ void f_fill_kv(uint32_t dst,
                                          const __nv_bfloat16* __restrict__ Kh,
                                          const __nv_bfloat16* __restrict__ Kl,
                                          const __nv_bfloat16* __restrict__ Vh,
                                          const __nv_bfloat16* __restrict__ Vl,
                                          long k0, int t)
{
#pragma unroll
    for (int i = 0; i < 3; ++i) {
        int id = t + 256 * i;
        int row = id / 24, ch = id % 24;
        cpa16(dst + row * FPADB + ch * 16, Kh + (k0 + row) * 192 + ch * 8, 16);
        cpa16(dst + KT_B + row * FPADB + ch * 16, Kl + (k0 + row) * 192 + ch * 8, 16);
    }
#pragma unroll
    for (int i = 0; i < 2; ++i) {
        int id = t + 256 * i;
        int row = id >> 4, ch = id & 15;
        cpa16(dst + 2 * KT_B + row * VPADB + ch * 16, Vh + (k0 + row) * 128 + ch * 8, 16);
        cpa16(dst + 2 * KT_B + VT_B + row * VPADB + ch * 16, Vl + (k0 + row) * 128 + ch * 8, 16);
    }
}

__global__ __launch_bounds__(256, 1)
void flash_mma(const __nv_bfloat16* __restrict__ Qh_g, const __nv_bfloat16* __restrict__ Ql_g,
               const __nv_bfloat16* __restrict__ Kh_g, const __nv_bfloat16* __restrict__ Kl_g,
               const __nv_bfloat16* __restrict__ Vh_g, const __nv_bfloat16* __restrict__ Vl_g,
               float* __restrict__ O_g)
{
    extern __shared__ __align__(128) char smem[];
    uint32_t sb = smem_u32(smem);
    int qt = (int)gridDim.x - 1 - (int)blockIdx.x;
    int h = blockIdx.y;
    int q0 = qt * 128;
    int t = threadIdx.x;
    int warp = t >> 5, lane = t & 31;

    const __nv_bfloat16* Kgh = Kh_g + (long)h * SEQ * 192;
    const __nv_bfloat16* Kgl = Kl_g + (long)h * SEQ * 192;
    const __nv_bfloat16* Vgh = Vh_g + (long)h * SEQ * 128;
    const __nv_bfloat16* Vgl = Vl_g + (long)h * SEQ * 128;

    {
        const __nv_bfloat16* qg = Qh_g + ((long)h * SEQ + q0) * 192;
        const __nv_bfloat16* qg2 = Ql_g + ((long)h * SEQ + q0) * 192;
#pragma unroll
        for (int i = 0; i < 12; ++i) {
            int id = t + 256 * i;
            int row = id / 24, ch = id % 24;
            cpa16(sb + row * FPADB + ch * 16, qg + (long)row * 192 + ch * 8, 16);
            cpa16(sb + QT_B + row * FPADB + ch * 16, qg2 + (long)row * 192 + ch * 8, 16);
        }
        CP_COMMIT();
    }
    f_fill_kv(sb + KV_BASE, Kgh, Kgl, Vgh, Vgl, 0, t);
    CP_COMMIT();

    float o[16][4];
#pragma unroll
    for (int i = 0; i < 16; i++)
#pragma unroll
        for (int r = 0; r < 4; r++) o[i][r] = 0.f;
    float mrow[2] = {-1e30f, -1e30f};
    float lrow[2] = {0.f, 0.f};

    uint32_t qoff = (uint32_t)((warp * 16 + (lane & 15)) * FPADB + (lane >> 4) * 16);
    uint32_t koff = (uint32_t)(((lane & 7) + ((lane >> 4) << 3)) * FPADB +
                               ((lane >> 3) & 1) * 16);
    uint32_t voff = (uint32_t)(((lane & 7) + (((lane >> 3) & 1) << 3)) * VPADB +
                               ((lane >> 4) << 3) * 2);

    int rA = (lane >> 2);
    int colq = (lane & 3) * 2;
    int rowA = q0 + warp * 16 + rA;
    int rowB = rowA + 8;
    int nkt = 4 * qt + 4;

    for (int kt = 0; kt < nkt; ++kt) {
        __syncthreads();
        if (kt + 1 < nkt)
            f_fill_kv(sb + KV_BASE + ((kt + 1) & 1) * KV_STAGE, Kgh, Kgl, Vgh, Vgl,
                      (long)(kt + 1) * 32, t);
        CP_COMMIT();
        CP_WAIT(1);
        __syncthreads();

        int k0 = kt * 32;
        uint32_t kvb = sb + KV_BASE + (kt & 1) * KV_STAGE;

        float sc[4][4];
#pragma unroll
        for (int j = 0; j < 4; j++)
#pragma unroll
            for (int r = 0; r < 4; r++) sc[j][r] = 0.f;

#pragma unroll 1
        for (int k16 = 0; k16 < 12; ++k16) {
            uint32_t qfh[4], qfl[4];
            uint32_t addr = sb + qoff + k16 * 32;
            ldsm4(qfh[0], qfh[1], qfh[2], qfh[3], addr);
            ldsm4(qfl[0], qfl[1], qfl[2], qfl[3], addr + QT_B);
            uint32_t kbh[4][2], kbl[4][2];
#pragma unroll
            for (int j2 = 0; j2 < 2; ++j2) {
                uint32_t ka = kvb + koff + j2 * 16 * FPADB + k16 * 32;
                uint32_t r0, r1, r2, r3;
                ldsm4(r0, r1, r2, r3, ka);
                kbh[2 * j2][0] = r0; kbh[2 * j2][1] = r1;
                kbh[2 * j2 + 1][0] = r2; kbh[2 * j2 + 1][1] = r3;
                ldsm4(r0, r1, r2, r3, ka + KT_B);
                kbl[2 * j2][0] = r0; kbl[2 * j2][1] = r1;
                kbl[2 * j2 + 1][0] = r2; kbl[2 * j2 + 1][1] = r3;
            }
#pragma unroll
            for (int j = 0; j < 4; ++j)
                mma16816(sc[j], qfh[0], qfh[1], qfh[2], qfh[3], kbh[j][0], kbh[j][1]);
#pragma unroll
            for (int j = 0; j < 4; ++j)
                mma16816(sc[j], qfh[0], qfh[1], qfh[2], qfh[3], kbl[j][0], kbl[j][1]);
#pragma unroll
            for (int j = 0; j < 4; ++j)
                mma16816(sc[j], qfl[0], qfl[1], qfl[2], qfl[3], kbh[j][0], kbh[j][1]);
        }

        bool diag = (kt >= 4 * qt);
#pragma unroll
        for (int j = 0; j < 4; ++j) {
#pragma unroll
            for (int r = 0; r < 4; r++) sc[j][r] *= SM_SCALE;
            if (diag) {
                int col = k0 + j * 8 + colq;
                if (col > rowA)     sc[j][0] = -1e30f;
                if (col + 1 > rowA) sc[j][1] = -1e30f;
                if (col > rowB)     sc[j][2] = -1e30f;
                if (col + 1 > rowB) sc[j][3] = -1e30f;
            }
        }
        float mxa = -1e30f, mxb = -1e30f;
#pragma unroll
        for (int j = 0; j < 4; ++j) {
            mxa = fmaxf(mxa, fmaxf(sc[j][0], sc[j][1]));
            mxb = fmaxf(mxb, fmaxf(sc[j][2], sc[j][3]));
        }
        mxa = fmaxf(mxa, __shfl_xor_sync(0xffffffffu, mxa, 1));
        mxa = fmaxf(mxa, __shfl_xor_sync(0xffffffffu, mxa, 2));
        mxb = fmaxf(mxb, __shfl_xor_sync(0xffffffffu, mxb, 1));
        mxb = fmaxf(mxb, __shfl_xor_sync(0xffffffffu, mxb, 2));
        float mna = fmaxf(mrow[0], mxa), mnb = fmaxf(mrow[1], mxb);
        float ala = __expf(mrow[0] - mna), alb = __expf(mrow[1] - mnb);
        mrow[0] = mna; mrow[1] = mnb;

        float suma = 0.f, sumb = 0.f;
#pragma unroll
        for (int j = 0; j < 4; ++j) {
            sc[j][0] = __expf(sc[j][0] - mna);
            sc[j][1] = __expf(sc[j][1] - mna);
            sc[j][2] = __expf(sc[j][2] - mnb);
            sc[j][3] = __expf(sc[j][3] - mnb);
            suma += sc[j][0] + sc[j][1];
            sumb += sc[j][2] + sc[j][3];
        }
        suma += __shfl_xor_sync(0xffffffffu, suma, 1);
        suma += __shfl_xor_sync(0xffffffffu, suma, 2);
        sumb += __shfl_xor_sync(0xffffffffu, sumb, 1);
        sumb += __shfl_xor_sync(0xffffffffu, sumb, 2);
        lrow[0] = lrow[0] * ala + suma;
        lrow[1] = lrow[1] * alb + sumb;
#pragma unroll
        for (int nb = 0; nb < 16; ++nb) {
            o[nb][0] *= ala; o[nb][1] *= ala;
            o[nb][2] *= alb; o[nb][3] *= alb;
        }

        uint32_t pah[2][4], pal[2][4];
#pragma unroll
        for (int j = 0; j < 2; ++j) {
            split2(sc[2 * j][0],     sc[2 * j][1],     pah[j][0], pal[j][0]);
            split2(sc[2 * j][2],     sc[2 * j][3],     pah[j][1], pal[j][1]);
            split2(sc[2 * j + 1][0], sc[2 * j + 1][1], pah[j][2], pal[j][2]);
            split2(sc[2 * j + 1][2], sc[2 * j + 1][3], pah[j][3], pal[j][3]);
        }

        uint32_t vbase = kvb + 2 * KT_B;
#pragma unroll 1
        for (int j = 0; j < 2; ++j) {
#pragma unroll
            for (int nb2 = 0; nb2 < 8; ++nb2) {
                uint32_t va = vbase + voff + j * 16 * VPADB + nb2 * 32;
                uint32_t h0, h1, h2, h3, l0, l1, l2, l3;
                ldsm4t(h0, h1, h2, h3, va);
                ldsm4t(l0, l1, l2, l3, va + VT_B);
                mma16816(o[2 * nb2],     pah[j][0], pah[j][1], pah[j][2], pah[j][3], h0, h1);
                mma16816(o[2 * nb2 + 1], pah[j][0], pah[j][1], pah[j][2], pah[j][3], h2, h3);
                mma16816(o[2 * nb2],     pah[j][0], pah[j][1], pah[j][2], pah[j][3], l0, l1);
                mma16816(o[2 * nb2 + 1], pah[j][0], pah[j][1], pah[j][2], pah[j][3], l2, l3);
                mma16816(o[2 * nb2],     pal[j][0], pal[j][1], pal[j][2], pal[j][3], h0, h1);
                mma16816(o[2 * nb2 + 1], pal[j][0], pal[j][1], pal[j][2], pal[j][3], h2, h3);
            }
        }
    }

    float inva = 1.0f / lrow[0], invb = 1.0f / lrow[1];
#pragma unroll
    for (int nb = 0; nb < 16; ++nb) {
        int col = h * 128 + nb * 8 + colq;
        float2 vA = make_float2(tf32r(o[nb][0] * inva), tf32r(o[nb][1] * inva));
        float2 vB = make_float2(tf32r(o[nb][2] * invb), tf32r(o[nb][3] * invb));
        *(float2*)&O_g[(long)rowA * 2048 + col] = vA;
        *(float2*)&O_g[(long)rowB * 2048 + col] = vB;
    }
}

// ---------------- launch ------------------------------------------------------
extern "C" void kernel_launch(void* const* d_in, const int* in_sizes, int n_in,
                              void* d_out, int out_size)
{
    const float* hidden   = (const float*)d_in[0];
    const int*   pos      = (const int*)d_in[1];
    const float* ln_w     = (const float*)d_in[3];
    const float* wq_a     = (const float*)d_in[4];
    const float* q_a_ln   = (const float*)d_in[5];
    const float* wq_b     = (const float*)d_in[6];
    const float* wkv_a    = (const float*)d_in[7];
    const float* kv_a_ln  = (const float*)d_in[8];
    const float* wkv_b    = (const float*)d_in[9];
    const float* wo       = (const float*)d_in[10];

    float* out   = (float*)d_out;
    float* k_out = out + (long)SEQ * HIDDEN;
    float* v_out = k_out + (long)NHEADS * SEQ * QKD;

    float *p_qackv, *p_q, *p_kv, *p_attn, *p_h, *p_qa, *p_ckvn;
    float *p_wqkva, *p_wqb, *p_wkvb, *p_wo;
    cudaGetSymbolAddress((void**)&p_qackv, g_qackv);
    cudaGetSymbolAddress((void**)&p_q, g_q);
    cudaGetSymbolAddress((void**)&p_kv, g_kv);
    cudaGetSymbolAddress((void**)&p_attn, g_attn_f);
    cudaGetSymbolAddress((void**)&p_h, g_h_f);
    cudaGetSymbolAddress((void**)&p_qa, g_qa_f);
    cudaGetSymbolAddress((void**)&p_ckvn, g_ckvn_f);
    cudaGetSymbolAddress((void**)&p_wqkva, g_wqkva_f);
    cudaGetSymbolAddress((void**)&p_wqb, g_wqb_f);
    cudaGetSymbolAddress((void**)&p_wkvb, g_wkvb_f);
    cudaGetSymbolAddress((void**)&p_wo, g_wo_f);

    __nv_bfloat16 *qf_hi, *qf_lo, *k_hi, *k_lo, *v_hi, *v_lo;
    cudaGetSymbolAddress((void**)&qf_hi, g_qf_hi);     cudaGetSymbolAddress((void**)&qf_lo, g_qf_lo);
    cudaGetSymbolAddress((void**)&k_hi, g_k_hi);       cudaGetSymbolAddress((void**)&k_lo, g_k_lo);
    cudaGetSymbolAddress((void**)&v_hi, g_v_hi);       cudaGetSymbolAddress((void**)&v_lo, g_v_lo);

    cudaFuncSetAttribute(gemm_t32, cudaFuncAttributeMaxDynamicSharedMemorySize, GEMM_SMEM);
    cudaFuncSetAttribute(gemm_t32_dual, cudaFuncAttributeMaxDynamicSharedMemorySize, GEMM_SMEM);
    cudaFuncSetAttribute(flash_mma, cudaFuncAttributeMaxDynamicSharedMemorySize, FLASH_SMEM);

    // A: rmsnorm(hidden) + round wq_a and wkv_a
    rms_cvt_A<<<SEQ + 1184, 256>>>(
        hidden, ln_w, p_h,
        wq_a, p_wqkva, (long)QLORA * HIDDEN / 4,
        wkv_a, p_wqkva + (long)QLORA * HIDDEN, (long)576 * HIDDEN / 4);
    // gemm1: fused q_a + ckv projection
    gemm_t32<<<dim3(17, SEQ / 128), 256, GEMM_SMEM>>>(
        p_h, HIDDEN, p_wqkva, p_qackv, SEQ, QKVN, HIDDEN, nullptr, 0.f);
    // B: rmsnorm(qa) + rmsnorm(ckv) + round wqb & wkvb
    rms_cvt_B<<<2 * SEQ + 1184, 256>>>(
        p_qackv, q_a_ln, p_qa, kv_a_ln, p_ckvn,
        wq_b, p_wqb, (long)3072 * QLORA / 4,
        wkv_b, p_wkvb, (long)4096 * KVLORA / 4);
    gemm_t32_dual<<<dim3(24 + 32, SEQ / 128), 256, GEMM_SMEM>>>(
        p_qa, QLORA, p_wqb, p_q, 3072, QLORA,
        p_ckvn, KVLORA, p_wkvb, p_kv, 4096, KVLORA, 24);
    // C: rope+scatter + round wo
    rope_scatter_cvt<<<SEQ + 1184, 256>>>(
        p_q, p_qackv, p_kv, pos, qf_hi, qf_lo,
        k_out, k_hi, k_lo, v_out, v_hi, v_lo,
        wo, p_wo, (long)HIDDEN * 2048 / 4);
    flash_mma<<<dim3(SEQ / 128, NHEADS), 256, FLASH_SMEM>>>(
        qf_hi, qf_lo, k_hi, k_lo, v_hi, v_lo, p_attn);
    gemm_t32<<<dim3(HIDDEN / 128, SEQ / 128), 256, GEMM_SMEM>>>(
        p_attn, 2048, p_wo, out, SEQ, HIDDEN, 2048, hidden, RESID_SCALE);
}

// round 15
// speedup vs baseline: 1.9432x; 1.0037x over previous
#include <cuda_runtime.h>
#include <cuda_bf16.h>
#include <math.h>
#include <stdint.h>

#define HIDDEN 5120
#define NHEADS 16
#define QLORA  1536
#define KVLORA 512
#define NOPE   128
#define ROPE_D 64
#define QKD    192
#define VDIM   128
#define SEQ    2048
#define QKVN   2112
#define SM_SCALE 0.07216878364870322f  // 192^-0.5
#define RESID_SCALE 0.125f
#define PERS_GRID 296   // 2 CTAs/SM x 148 SMs

// ---------------- scratch ----------------------------------------------------
static __device__ float g_qackv[SEQ * QKVN];
static __device__ float g_q[SEQ * NHEADS * QKD];
static __device__ float g_kv[SEQ * 4096];
static __device__ float g_attn_f[SEQ * 2048];

static __device__ float g_h_f[SEQ * HIDDEN];
static __device__ float g_qa_f[SEQ * QLORA];
static __device__ float g_ckvn_f[SEQ * KVLORA];
static __device__ float g_wqkva_f[QKVN * HIDDEN];
static __device__ float g_wqb_f[3072 * QLORA];
static __device__ float g_wkvb_f[4096 * KVLORA];
static __device__ float g_wo_f[HIDDEN * 2048];

static __device__ __nv_bfloat16 g_qf_hi[NHEADS * SEQ * QKD], g_qf_lo[NHEADS * SEQ * QKD];
static __device__ __nv_bfloat16 g_k_hi[NHEADS * SEQ * QKD],  g_k_lo[NHEADS * SEQ * QKD];
static __device__ __nv_bfloat16 g_v_hi[NHEADS * SEQ * VDIM], g_v_lo[NHEADS * SEQ * VDIM];

// ---------------- helpers ----------------------------------------------------
__device__ __forceinline__ uint32_t smem_u32(const void* p) {
    return (uint32_t)__cvta_generic_to_shared(p);
}
__device__ __forceinline__ void cpa16(uint32_t dst, const void* src, int sz) {
    asm volatile("cp.async.cg.shared.global [%0], [%1], 16, %2;"
                 :: "r"(dst), "l"(src), "r"(sz) : "memory");
}
#define CP_COMMIT() asm volatile("cp.async.commit_group;" ::: "memory")
#define CP_WAIT(n)  asm volatile("cp.async.wait_group %0;" :: "n"(n) : "memory")

__device__ __forceinline__ void ldsm4(uint32_t& r0, uint32_t& r1, uint32_t& r2, uint32_t& r3,
                                      uint32_t addr) {
    asm volatile("ldmatrix.sync.aligned.m8n8.x4.shared.b16 {%0,%1,%2,%3}, [%4];"
                 : "=r"(r0), "=r"(r1), "=r"(r2), "=r"(r3) : "r"(addr));
}
__device__ __forceinline__ void ldsm4t(uint32_t& r0, uint32_t& r1, uint32_t& r2, uint32_t& r3,
                                       uint32_t addr) {
    asm volatile("ldmatrix.sync.aligned.m8n8.x4.trans.shared.b16 {%0,%1,%2,%3}, [%4];"
                 : "=r"(r0), "=r"(r1), "=r"(r2), "=r"(r3) : "r"(addr));
}
__device__ __forceinline__ void mma16816(float* c, uint32_t a0, uint32_t a1, uint32_t a2,
                                         uint32_t a3, uint32_t b0, uint32_t b1) {
    asm volatile(
        "mma.sync.aligned.m16n8k16.row.col.f32.bf16.bf16.f32 "
        "{%0,%1,%2,%3}, {%4,%5,%6,%7}, {%8,%9}, {%0,%1,%2,%3};"
        : "+f"(c[0]), "+f"(c[1]), "+f"(c[2]), "+f"(c[3])
        : "r"(a0), "r"(a1), "r"(a2), "r"(a3), "r"(b0), "r"(b1));
}
__device__ __forceinline__ void mma_tf32(float* c, uint32_t a0, uint32_t a1, uint32_t a2,
                                         uint32_t a3, uint32_t b0, uint32_t b1) {
    asm volatile(
        "mma.sync.aligned.m16n8k8.row.col.f32.tf32.tf32.f32 "
        "{%0,%1,%2,%3}, {%4,%5,%6,%7}, {%8,%9}, {%0,%1,%2,%3};"
        : "+f"(c[0]), "+f"(c[1]), "+f"(c[2]), "+f"(c[3])
        : "r"(a0), "r"(a1), "r"(a2), "r"(a3), "r"(b0), "r"(b1));
}
__device__ __forceinline__ float tf32r(float x) {
    uint32_t u;
    asm("cvt.rna.tf32.f32 %0, %1;" : "=r"(u) : "f"(x));
    return __uint_as_float(u);
}
__device__ __forceinline__ void split2(float v0, float v1, uint32_t& hi, uint32_t& lo) {
    __nv_bfloat16 h0 = __float2bfloat16(v0), h1 = __float2bfloat16(v1);
    float r0 = v0 - __bfloat162float(h0), r1 = v1 - __bfloat162float(h1);
    __nv_bfloat162 th; th.x = h0; th.y = h1;
    hi = *reinterpret_cast<uint32_t*>(&th);
    __nv_bfloat162 tl; tl.x = __float2bfloat16(r0); tl.y = __float2bfloat16(r1);
    lo = *reinterpret_cast<uint32_t*>(&tl);
}

// ---------------- shared elementwise bodies -----------------------------------
__device__ __forceinline__ void cvt_body(const float* __restrict__ src, float* __restrict__ dst,
                                         long n4, long bid, long nb)
{
    const float4* s4 = (const float4*)src;
    float4* d4 = (float4*)dst;
    for (long i = bid * 256 + threadIdx.x; i < n4; i += nb * 256) {
        float4 v = s4[i];
        v.x = tf32r(v.x); v.y = tf32r(v.y); v.z = tf32r(v.z); v.w = tf32r(v.w);
        d4[i] = v;
    }
}

__device__ __forceinline__ void rms_body(const float* __restrict__ x, const float* __restrict__ w,
                                         float* __restrict__ y,
                                         int cols, int strideIn, int strideOut, int row)
{
    __shared__ float red[256];
    int t = threadIdx.x;
    const float4* xr = (const float4*)(x + (long)row * strideIn);
    const float4* w4 = (const float4*)w;
    int c4 = cols >> 2;
    float ss = 0.f;
    for (int c = t; c < c4; c += 256) {
        float4 v = xr[c];
        ss = fmaf(v.x, v.x, fmaf(v.y, v.y, fmaf(v.z, v.z, fmaf(v.w, v.w, ss))));
    }
    red[t] = ss; __syncthreads();
    for (int s = 128; s > 0; s >>= 1) { if (t < s) red[t] += red[t + s]; __syncthreads(); }
    float scale = rsqrtf(red[0] / (float)cols + 1e-6f);
    float4* yr = (float4*)(y + (long)row * strideOut);
    for (int c = t; c < c4; c += 256) {
        float4 v = xr[c];
        float4 wv = w4[c];
        float4 o;
        o.x = tf32r(v.x * scale * wv.x);
        o.y = tf32r(v.y * scale * wv.y);
        o.z = tf32r(v.z * scale * wv.z);
        o.w = tf32r(v.w * scale * wv.w);
        yr[c] = o;
    }
}

// A: rmsnorm(hidden) + tf32-round wq_a and wkv_a (extra blocks, 2 ranges)
__global__ void rms_cvt_A(const float* __restrict__ x, const float* __restrict__ w,
                          float* __restrict__ y,
                          const float* __restrict__ ws1, float* __restrict__ wd1, long n1,
                          const float* __restrict__ ws2, float* __restrict__ wd2, long n2)
{
    if ((int)blockIdx.x < SEQ)
        rms_body(x, w, y, HIDDEN, HIDDEN, HIDDEN, blockIdx.x);
    else {
        long bid = blockIdx.x - SEQ, nb = gridDim.x - SEQ;
        cvt_body(ws1, wd1, n1, bid, nb);
        cvt_body(ws2, wd2, n2, bid, nb);
    }
}

// B: rmsnorm(qa) + rmsnorm(ckv) + tf32-round wqb & wkvb (extra blocks)
__global__ void rms_cvt_B(const float* __restrict__ qackv,
                          const float* __restrict__ qw, float* __restrict__ qy,
                          const float* __restrict__ cw, float* __restrict__ cy,
                          const float* __restrict__ ws1, float* __restrict__ wd1, long n1,
                          const float* __restrict__ ws2, float* __restrict__ wd2, long n2)
{
    if ((int)blockIdx.x < SEQ)
        rms_body(qackv, qw, qy, QLORA, QKVN, QLORA, blockIdx.x);
    else if ((int)blockIdx.x < 2 * SEQ)
        rms_body(qackv + QLORA, cw, cy, KVLORA, QKVN, KVLORA, blockIdx.x - SEQ);
    else {
        long bid = blockIdx.x - 2 * SEQ, nb = gridDim.x - 2 * SEQ;
        cvt_body(ws1, wd1, n1, bid, nb);
        cvt_body(ws2, wd2, n2, bid, nb);
    }
}

// ---------------- tf32 single-pass GEMM (ldmatrix frags), 3 stages ------------
#define T32_TILE 16384
#define T32_STAGE (2 * T32_TILE)
#define GSTAGES 3
#define GEMM_SMEM (GSTAGES * T32_STAGE)  // 98304; 2 CTAs/SM

__device__ __forceinline__ void gt_fill(uint32_t dstBase, const float* __restrict__ src,
                                        long ld, int rmax, int t)
{
#pragma unroll
    for (int i = 0; i < 4; ++i) {
        int id = t + 256 * i;
        int row = id >> 3, ch = id & 7;
        bool ok = row < rmax;
        const float* g = src + (long)(ok ? row : 0) * ld + ch * 4;
        uint32_t cs = (uint32_t)(ch ^ (row & 7));
        cpa16(dstBase + row * 128 + cs * 16, g, ok ? 16 : 0);
    }
}

__device__ __forceinline__ void gemm_t32_core(
    const float* __restrict__ A, int lda,
    const float* __restrict__ B,
    float* __restrict__ C, int M, int N, int K,
    const float* __restrict__ D, float beta,
    int bx, int by, char* smem)
{
    uint32_t sb = smem_u32(smem);
    int t = threadIdx.x;
    int warp = t >> 5, lane = t & 31;
    int wm = warp >> 2, wn = warp & 3;
    int n0 = bx * 128, m0 = by * 128;
    int nc = K / 32;
    int q = lane >> 3, lr = lane & 7;

    uint32_t aRow[4];
#pragma unroll
    for (int im = 0; im < 4; ++im)
        aRow[im] = (uint32_t)((wm * 64 + im * 16 + ((q & 1) << 3) + lr) * 128);
    uint32_t bRow[2];
#pragma unroll
    for (int p = 0; p < 2; ++p)
        bRow[p] = (uint32_t)((wn * 32 + ((2 * p + (q >> 1)) << 3) + lr) * 128) + T32_TILE;

    float acc[4][4][4];
#pragma unroll
    for (int i = 0; i < 4; i++)
#pragma unroll
        for (int j = 0; j < 4; j++)
#pragma unroll
            for (int r = 0; r < 4; r++) acc[i][j][r] = 0.f;

#pragma unroll
    for (int s = 0; s < 2; ++s) {
        uint32_t b0 = sb + s * T32_STAGE;
        int kc0 = s * 32;
        gt_fill(b0,            A + (long)m0 * lda + kc0, lda, M - m0, t);
        gt_fill(b0 + T32_TILE, B + (long)n0 * K + kc0, K, N - n0, t);
        CP_COMMIT();
    }

    int stage = 0;
    for (int c = 0; c < nc; ++c) {
        CP_WAIT(1);
        __syncthreads();
        if (c + 2 < nc) {
            int ps = stage + 2; if (ps >= GSTAGES) ps -= GSTAGES;
            uint32_t bn = sb + ps * T32_STAGE;
            int kc0 = (c + 2) * 32;
            gt_fill(bn,            A + (long)m0 * lda + kc0, lda, M - m0, t);
            gt_fill(bn + T32_TILE, B + (long)n0 * K + kc0, K, N - n0, t);
        }
        CP_COMMIT();

        uint32_t sbase = sb + stage * T32_STAGE;
#pragma unroll
        for (int k8 = 0; k8 < 4; ++k8) {
            uint32_t swA = (uint32_t)(((2 * k8 + (q >> 1)) ^ lr) << 4);
            uint32_t swB = (uint32_t)(((2 * k8 + (q & 1)) ^ lr) << 4);
            uint32_t au[4][4];
#pragma unroll
            for (int im = 0; im < 4; ++im)
                ldsm4(au[im][0], au[im][1], au[im][2], au[im][3],
                      sbase + aRow[im] + swA);
            uint32_t bu[4][2];
#pragma unroll
            for (int p = 0; p < 2; ++p) {
                uint32_t r0, r1, r2, r3;
                ldsm4(r0, r1, r2, r3, sbase + bRow[p] + swB);
                bu[2 * p][0] = r0;     bu[2 * p][1] = r1;
                bu[2 * p + 1][0] = r2; bu[2 * p + 1][1] = r3;
            }
#pragma unroll
            for (int im = 0; im < 4; ++im)
#pragma unroll
                for (int jn = 0; jn < 4; ++jn)
                    mma_tf32(acc[im][jn], au[im][0], au[im][1], au[im][2], au[im][3],
                             bu[jn][0], bu[jn][1]);
        }
        if (++stage >= GSTAGES) stage = 0;
    }

#pragma unroll
    for (int im = 0; im < 4; ++im) {
        int row0 = m0 + wm * 64 + im * 16 + (lane >> 2);
#pragma unroll
        for (int jn = 0; jn < 4; ++jn) {
            int col = n0 + wn * 32 + jn * 8 + (lane & 3) * 2;
            if (col < N) {
                float2 v0 = make_float2(acc[im][jn][0], acc[im][jn][1]);
                float2 v1 = make_float2(acc[im][jn][2], acc[im][jn][3]);
                if (D) {
                    float2 d0 = *(const float2*)&D[(long)row0 * N + col];
                    float2 d1 = *(const float2*)&D[(long)(row0 + 8) * N + col];
                    v0.x = fmaf(beta, d0.x, v0.x); v0.y = fmaf(beta, d0.y, v0.y);
                    v1.x = fmaf(beta, d1.x, v1.x); v1.y = fmaf(beta, d1.y, v1.y);
                }
                *(float2*)&C[(long)row0 * N + col] = v0;
                *(float2*)&C[(long)(row0 + 8) * N + col] = v1;
            }
        }
    }
}

__global__ __launch_bounds__(256, 2)
void gemm_t32(const float* __restrict__ A, int lda, const float* __restrict__ B,
              float* __restrict__ C, int M, int N, int K,
              const float* __restrict__ D, float beta)
{
    extern __shared__ __align__(128) char smem[];
    gemm_t32_core(A, lda, B, C, M, N, K, D, beta, blockIdx.x, blockIdx.y, smem);
}

// persistent single-GEMM: CTAs loop over tiles (kills tail-wave waste)
__global__ __launch_bounds__(256, 2)
void gemm_t32_pers(const float* __restrict__ A, int lda, const float* __restrict__ B,
                   float* __restrict__ C, int M, int N, int K,
                   const float* __restrict__ D, float beta, int nbx, int ntiles)
{
    extern __shared__ __align__(128) char smem[];
    for (int tile = blockIdx.x; tile < ntiles; tile += gridDim.x) {
        gemm_t32_core(A, lda, B, C, M, N, K, D, beta, tile % nbx, tile / nbx, smem);
        __syncthreads();   // smem handoff between tile iterations
    }
}

// persistent dual-GEMM: job1 (long K) tiles enumerated first (LPT)
__global__ __launch_bounds__(256, 2)
void gemm_t32_dual_pers(const float* __restrict__ A1, int lda1, const float* __restrict__ B1,
                        float* __restrict__ C1, int N1, int K1, int nbx1,
                        const float* __restrict__ A2, int lda2, const float* __restrict__ B2,
                        float* __restrict__ C2, int N2, int K2, int nbx2,
                        int ntiles1, int ntiles)
{
    extern __shared__ __align__(128) char smem[];
    for (int tile = blockIdx.x; tile < ntiles; tile += gridDim.x) {
        if (tile < ntiles1)
            gemm_t32_core(A1, lda1, B1, C1, SEQ, N1, K1, nullptr, 0.f,
                          tile % nbx1, tile / nbx1, smem);
        else {
            int t2 = tile - ntiles1;
            gemm_t32_core(A2, lda2, B2, C2, SEQ, N2, K2, nullptr, 0.f,
                          t2 % nbx2, t2 / nbx2, smem);
        }
        __syncthreads();
    }
}

// ---------------- RoPE + scatter (vectorized) + wo tf32-round -----------------
__global__ void rope_scatter_cvt(const float* __restrict__ qin,
                                 const float* __restrict__ qackv,
                                 const float* __restrict__ kvin,
                                 const int* __restrict__ pos_ids,
                                 __nv_bfloat16* __restrict__ qh, __nv_bfloat16* __restrict__ ql,
                                 float* __restrict__ kout,
                                 __nv_bfloat16* __restrict__ kh, __nv_bfloat16* __restrict__ kl,
                                 float* __restrict__ vout,
                                 __nv_bfloat16* __restrict__ vh, __nv_bfloat16* __restrict__ vl,
                                 const float* __restrict__ ws, float* __restrict__ wd, long n4)
{
    if ((int)blockIdx.x >= SEQ) {
        cvt_body(ws, wd, n4, blockIdx.x - SEQ, gridDim.x - SEQ);
        return;
    }
    int s = blockIdx.x;
    int t = threadIdx.x;
    __shared__ float cs[32], sn[32], kr[64];
    if (t < 32) {
        double invf = exp(-(double)t * 0.28782313662425575); // ln(10000)/32
        double ang = (double)pos_ids[s] * invf;
        cs[t] = (float)cos(ang);
        sn[t] = (float)sin(ang);
    }
    __syncthreads();
    if (t < 32) {
        float x0 = qackv[(long)s * QKVN + 2048 + 2 * t];
        float x1 = qackv[(long)s * QKVN + 2048 + 2 * t + 1];
        kr[t]      = x0 * cs[t] - x1 * sn[t];
        kr[32 + t] = x1 * cs[t] + x0 * sn[t];
    }
    __syncthreads();
    {
        int h = t >> 4, j2 = t & 15;
        int j0 = 2 * j2, j1 = j0 + 1;
        const float* qb = qin + (long)s * 3072 + h * 192;
        float x0 = qb[128 + 2 * j0], x1 = qb[128 + 2 * j0 + 1];
        float x2 = qb[128 + 2 * j1], x3 = qb[128 + 2 * j1 + 1];
        float a0 = x0 * cs[j0] - x1 * sn[j0];
        float b0 = x1 * cs[j0] + x0 * sn[j0];
        float a1 = x2 * cs[j1] - x3 * sn[j1];
        float b1 = x3 * cs[j1] + x2 * sn[j1];
        long o = ((long)h * SEQ + s) * 192;
        uint32_t hi, lo;
        split2(a0, a1, hi, lo);
        *(uint32_t*)&qh[o + 128 + j0] = hi; *(uint32_t*)&ql[o + 128 + j0] = lo;
        split2(b0, b1, hi, lo);
        *(uint32_t*)&qh[o + 160 + j0] = hi; *(uint32_t*)&ql[o + 160 + j0] = lo;
    }
    for (int idx = t; idx < 1024; idx += 256) {
        int h = idx >> 6, d = (idx & 63) * 2;
        float2 v = *(const float2*)&qin[(long)s * 3072 + h * 192 + d];
        long o = ((long)h * SEQ + s) * 192 + d;
        uint32_t hi, lo;
        split2(v.x, v.y, hi, lo);
        *(uint32_t*)&qh[o] = hi; *(uint32_t*)&ql[o] = lo;
    }
    for (int idx = t; idx < 1536; idx += 256) {
        int h = idx / 96, d = (idx - h * 96) * 2;
        float2 v;
        if (d < 128) v = *(const float2*)&kvin[(long)s * 4096 + h * 256 + d];
        else         v = make_float2(kr[d - 128], kr[d - 127]);
        long o = ((long)h * SEQ + s) * 192 + d;
        *(float2*)&kout[o] = v;
        uint32_t hi, lo;
        split2(v.x, v.y, hi, lo);
        *(uint32_t*)&kh[o] = hi; *(uint32_t*)&kl[o] = lo;
    }
    for (int idx = t; idx < 1024; idx += 256) {
        int h = idx >> 6, d = (idx & 63) * 2;
        float2 v = *(const float2*)&kvin[(long)s * 4096 + h * 256 + 128 + d];
        long o = ((long)h * SEQ + s) * 128 + d;
        *(float2*)&vout[o] = v;
        uint32_t hi, lo;
        split2(v.x, v.y, hi, lo);
        *(uint32_t*)&vh[o] = hi; *(uint32_t*)&vl[o] = lo;
    }
}

// ---------------- flash attention: 128-row Q tile, 32-key stages --------------
#define FPADB 400
#define VPADB 272
#define QT_B (128 * FPADB)
#define KT_B (32 * FPADB)
#define VT_B (32 * VPADB)
#define KV_BASE (2 * QT_B)
#define KV_STAGE (2 * KT_B + 2 * VT_B)
#define FLASH_SMEM (KV_BASE + 2 * KV_STAGE)  // 188416

__device__ __forceinline__ void f_fill_kv(uint32_t dst,
                                          const __nv_bfloat16* __restrict__ Kh,
                                          const __nv_bfloat16* __restrict__ Kl,
                                          const __nv_bfloat16* __restrict__ Vh,
                                          const __nv_bfloat16* __restrict__ Vl,
                                          long k0, int t)
{
#pragma unroll
    for (int i = 0; i < 3; ++i) {
        int id = t + 256 * i;
        int row = id / 24, ch = id % 24;
        cpa16(dst + row * FPADB + ch * 16, Kh + (k0 + row) * 192 + ch * 8, 16);
        cpa16(dst + KT_B + row * FPADB + ch * 16, Kl + (k0 + row) * 192 + ch * 8, 16);
    }
#pragma unroll
    for (int i = 0; i < 2; ++i) {
        int id = t + 256 * i;
        int row = id >> 4, ch = id & 15;
        cpa16(dst + 2 * KT_B + row * VPADB + ch * 16, Vh + (k0 + row) * 128 + ch * 8, 16);
        cpa16(dst + 2 * KT_B + VT_B + row * VPADB + ch * 16, Vl + (k0 + row) * 128 + ch * 8, 16);
    }
}

__global__ __launch_bounds__(256, 1)
void flash_mma(const __nv_bfloat16* __restrict__ Qh_g, const __nv_bfloat16* __restrict__ Ql_g,
               const __nv_bfloat16* __restrict__ Kh_g, const __nv_bfloat16* __restrict__ Kl_g,
               const __nv_bfloat16* __restrict__ Vh_g, const __nv_bfloat16* __restrict__ Vl_g,
               float* __restrict__ O_g)
{
    extern __shared__ __align__(128) char smem[];
    uint32_t sb = smem_u32(smem);
    int qt = (int)gridDim.x - 1 - (int)blockIdx.x;
    int h = blockIdx.y;
    int q0 = qt * 128;
    int t = threadIdx.x;
    int warp = t >> 5, lane = t & 31;

    const __nv_bfloat16* Kgh = Kh_g + (long)h * SEQ * 192;
    const __nv_bfloat16* Kgl = Kl_g + (long)h * SEQ * 192;
    const __nv_bfloat16* Vgh = Vh_g + (long)h * SEQ * 128;
    const __nv_bfloat16* Vgl = Vl_g + (long)h * SEQ * 128;

    {
        const __nv_bfloat16* qg = Qh_g + ((long)h * SEQ + q0) * 192;
        const __nv_bfloat16* qg2 = Ql_g + ((long)h * SEQ + q0) * 192;
#pragma unroll
        for (int i = 0; i < 12; ++i) {
            int id = t + 256 * i;
            int row = id / 24, ch = id % 24;
            cpa16(sb + row * FPADB + ch * 16, qg + (long)row * 192 + ch * 8, 16);
            cpa16(sb + QT_B + row * FPADB + ch * 16, qg2 + (long)row * 192 + ch * 8, 16);
        }
        CP_COMMIT();
    }
    f_fill_kv(sb + KV_BASE, Kgh, Kgl, Vgh, Vgl, 0, t);
    CP_COMMIT();

    float o[16][4];
#pragma unroll
    for (int i = 0; i < 16; i++)
#pragma unroll
        for (int r = 0; r < 4; r++) o[i][r] = 0.f;
    float mrow[2] = {-1e30f, -1e30f};
    float lrow[2] = {0.f, 0.f};

    uint32_t qoff = (uint32_t)((warp * 16 + (lane & 15)) * FPADB + (lane >> 4) * 16);
    uint32_t koff = (uint32_t)(((lane & 7) + ((lane >> 4) << 3)) * FPADB +
                               ((lane >> 3) & 1) * 16);
    uint32_t voff = (uint32_t)(((lane & 7) + (((lane >> 3) & 1) << 3)) * VPADB +
                               ((lane >> 4) << 3) * 2);

    int rA = (lane >> 2);
    int colq = (lane & 3) * 2;
    int rowA = q0 + warp * 16 + rA;
    int rowB = rowA + 8;
    int nkt = 4 * qt + 4;

    for (int kt = 0; kt < nkt; ++kt) {
        __syncthreads();
        if (kt + 1 < nkt)
            f_fill_kv(sb + KV_BASE + ((kt + 1) & 1) * KV_STAGE, Kgh, Kgl, Vgh, Vgl,
                      (long)(kt + 1) * 32, t);
        CP_COMMIT();
        CP_WAIT(1);
        __syncthreads();

        int k0 = kt * 32;
        uint32_t kvb = sb + KV_BASE + (kt & 1) * KV_STAGE;

        float sc[4][4];
#pragma unroll
        for (int j = 0; j < 4; j++)
#pragma unroll
            for (int r = 0; r < 4; r++) sc[j][r] = 0.f;

#pragma unroll 1
        for (int k16 = 0; k16 < 12; ++k16) {
            uint32_t qfh[4], qfl[4];
            uint32_t addr = sb + qoff + k16 * 32;
            ldsm4(qfh[0], qfh[1], qfh[2], qfh[3], addr);
            ldsm4(qfl[0], qfl[1], qfl[2], qfl[3], addr + QT_B);
            uint32_t kbh[4][2], kbl[4][2];
#pragma unroll
            for (int j2 = 0; j2 < 2; ++j2) {
                uint32_t ka = kvb + koff + j2 * 16 * FPADB + k16 * 32;
                uint32_t r0, r1, r2, r3;
                ldsm4(r0, r1, r2, r3, ka);
                kbh[2 * j2][0] = r0; kbh[2 * j2][1] = r1;
                kbh[2 * j2 + 1][0] = r2; kbh[2 * j2 + 1][1] = r3;
                ldsm4(r0, r1, r2, r3, ka + KT_B);
                kbl[2 * j2][0] = r0; kbl[2 * j2][1] = r1;
                kbl[2 * j2 + 1][0] = r2; kbl[2 * j2 + 1][1] = r3;
            }
#pragma unroll
            for (int j = 0; j < 4; ++j)
                mma16816(sc[j], qfh[0], qfh[1], qfh[2], qfh[3], kbh[j][0], kbh[j][1]);
#pragma unroll
            for (int j = 0; j < 4; ++j)
                mma16816(sc[j], qfh[0], qfh[1], qfh[2], qfh[3], kbl[j][0], kbl[j][1]);
#pragma unroll
            for (int j = 0; j < 4; ++j)
                mma16816(sc[j], qfl[0], qfl[1], qfl[2], qfl[3], kbh[j][0], kbh[j][1]);
        }

        bool diag = (kt >= 4 * qt);
#pragma unroll
        for (int j = 0; j < 4; ++j) {
#pragma unroll
            for (int r = 0; r < 4; r++) sc[j][r] *= SM_SCALE;
            if (diag) {
                int col = k0 + j * 8 + colq;
                if (col > rowA)     sc[j][0] = -1e30f;
                if (col + 1 > rowA) sc[j][1] = -1e30f;
                if (col > rowB)     sc[j][2] = -1e30f;
                if (col + 1 > rowB) sc[j][3] = -1e30f;
            }
        }
        float mxa = -1e30f, mxb = -1e30f;
#pragma unroll
        for (int j = 0; j < 4; ++j) {
            mxa = fmaxf(mxa, fmaxf(sc[j][0], sc[j][1]));
            mxb = fmaxf(mxb, fmaxf(sc[j][2], sc[j][3]));
        }
        mxa = fmaxf(mxa, __shfl_xor_sync(0xffffffffu, mxa, 1));
        mxa = fmaxf(mxa, __shfl_xor_sync(0xffffffffu, mxa, 2));
        mxb = fmaxf(mxb, __shfl_xor_sync(0xffffffffu, mxb, 1));
        mxb = fmaxf(mxb, __shfl_xor_sync(0xffffffffu, mxb, 2));
        float mna = fmaxf(mrow[0], mxa), mnb = fmaxf(mrow[1], mxb);
        float ala = __expf(mrow[0] - mna), alb = __expf(mrow[1] - mnb);
        mrow[0] = mna; mrow[1] = mnb;

        float suma = 0.f, sumb = 0.f;
#pragma unroll
        for (int j = 0; j < 4; ++j) {
            sc[j][0] = __expf(sc[j][0] - mna);
            sc[j][1] = __expf(sc[j][1] - mna);
            sc[j][2] = __expf(sc[j][2] - mnb);
            sc[j][3] = __expf(sc[j][3] - mnb);
            suma += sc[j][0] + sc[j][1];
            sumb += sc[j][2] + sc[j][3];
        }
        suma += __shfl_xor_sync(0xffffffffu, suma, 1);
        suma += __shfl_xor_sync(0xffffffffu, suma, 2);
        sumb += __shfl_xor_sync(0xffffffffu, sumb, 1);
        sumb += __shfl_xor_sync(0xffffffffu, sumb, 2);
        lrow[0] = lrow[0] * ala + suma;
        lrow[1] = lrow[1] * alb + sumb;
#pragma unroll
        for (int nb = 0; nb < 16; ++nb) {
            o[nb][0] *= ala; o[nb][1] *= ala;
            o[nb][2] *= alb; o[nb][3] *= alb;
        }

        uint32_t pah[2][4], pal[2][4];
#pragma unroll
        for (int j = 0; j < 2; ++j) {
            split2(sc[2 * j][0],     sc[2 * j][1],     pah[j][0], pal[j][0]);
            split2(sc[2 * j][2],     sc[2 * j][3],     pah[j][1], pal[j][1]);
            split2(sc[2 * j + 1][0], sc[2 * j + 1][1], pah[j][2], pal[j][2]);
            split2(sc[2 * j + 1][2], sc[2 * j + 1][3], pah[j][3], pal[j][3]);
        }

        uint32_t vbase = kvb + 2 * KT_B;
#pragma unroll 1
        for (int j = 0; j < 2; ++j) {
#pragma unroll
            for (int nb2 = 0; nb2 < 8; ++nb2) {
                uint32_t va = vbase + voff + j * 16 * VPADB + nb2 * 32;
                uint32_t h0, h1, h2, h3, l0, l1, l2, l3;
                ldsm4t(h0, h1, h2, h3, va);
                ldsm4t(l0, l1, l2, l3, va + VT_B);
                mma16816(o[2 * nb2],     pah[j][0], pah[j][1], pah[j][2], pah[j][3], h0, h1);
                mma16816(o[2 * nb2 + 1], pah[j][0], pah[j][1], pah[j][2], pah[j][3], h2, h3);
                mma16816(o[2 * nb2],     pah[j][0], pah[j][1], pah[j][2], pah[j][3], l0, l1);
                mma16816(o[2 * nb2 + 1], pah[j][0], pah[j][1], pah[j][2], pah[j][3], l2, l3);
                mma16816(o[2 * nb2],     pal[j][0], pal[j][1], pal[j][2], pal[j][3], h0, h1);
                mma16816(o[2 * nb2 + 1], pal[j][0], pal[j][1], pal[j][2], pal[j][3], h2, h3);
            }
        }
    }

    float inva = 1.0f / lrow[0], invb = 1.0f / lrow[1];
#pragma unroll
    for (int nb = 0; nb < 16; ++nb) {
        int col = h * 128 + nb * 8 + colq;
        float2 vA = make_float2(tf32r(o[nb][0] * inva), tf32r(o[nb][1] * inva));
        float2 vB = make_float2(tf32r(o[nb][2] * invb), tf32r(o[nb][3] * invb));
        *(float2*)&O_g[(long)rowA * 2048 + col] = vA;
        *(float2*)&O_g[(long)rowB * 2048 + col] = vB;
    }
}

// ---------------- launch ------------------------------------------------------
extern "C" void kernel_launch(void* const* d_in, const int* in_sizes, int n_in,
                              void* d_out, int out_size)
{
    const float* hidden   = (const float*)d_in[0];
    const int*   pos      = (const int*)d_in[1];
    const float* ln_w     = (const float*)d_in[3];
    const float* wq_a     = (const float*)d_in[4];
    const float* q_a_ln   = (const float*)d_in[5];
    const float* wq_b     = (const float*)d_in[6];
    const float* wkv_a    = (const float*)d_in[7];
    const float* kv_a_ln  = (const float*)d_in[8];
    const float* wkv_b    = (const float*)d_in[9];
    const float* wo       = (const float*)d_in[10];

    float* out   = (float*)d_out;
    float* k_out = out + (long)SEQ * HIDDEN;
    float* v_out = k_out + (long)NHEADS * SEQ * QKD;

    float *p_qackv, *p_q, *p_kv, *p_attn, *p_h, *p_qa, *p_ckvn;
    float *p_wqkva, *p_wqb, *p_wkvb, *p_wo;
    cudaGetSymbolAddress((void**)&p_qackv, g_qackv);
    cudaGetSymbolAddress((void**)&p_q, g_q);
    cudaGetSymbolAddress((void**)&p_kv, g_kv);
    cudaGetSymbolAddress((void**)&p_attn, g_attn_f);
    cudaGetSymbolAddress((void**)&p_h, g_h_f);
    cudaGetSymbolAddress((void**)&p_qa, g_qa_f);
    cudaGetSymbolAddress((void**)&p_ckvn, g_ckvn_f);
    cudaGetSymbolAddress((void**)&p_wqkva, g_wqkva_f);
    cudaGetSymbolAddress((void**)&p_wqb, g_wqb_f);
    cudaGetSymbolAddress((void**)&p_wkvb, g_wkvb_f);
    cudaGetSymbolAddress((void**)&p_wo, g_wo_f);

    __nv_bfloat16 *qf_hi, *qf_lo, *k_hi, *k_lo, *v_hi, *v_lo;
    cudaGetSymbolAddress((void**)&qf_hi, g_qf_hi);     cudaGetSymbolAddress((void**)&qf_lo, g_qf_lo);
    cudaGetSymbolAddress((void**)&k_hi, g_k_hi);       cudaGetSymbolAddress((void**)&k_lo, g_k_lo);
    cudaGetSymbolAddress((void**)&v_hi, g_v_hi);       cudaGetSymbolAddress((void**)&v_lo, g_v_lo);

    cudaFuncSetAttribute(gemm_t32, cudaFuncAttributeMaxDynamicSharedMemorySize, GEMM_SMEM);
    cudaFuncSetAttribute(gemm_t32_pers, cudaFuncAttributeMaxDynamicSharedMemorySize, GEMM_SMEM);
    cudaFuncSetAttribute(gemm_t32_dual_pers, cudaFuncAttributeMaxDynamicSharedMemorySize, GEMM_SMEM);
    cudaFuncSetAttribute(flash_mma, cudaFuncAttributeMaxDynamicSharedMemorySize, FLASH_SMEM);

    // A: rmsnorm(hidden) + round wq_a and wkv_a
    rms_cvt_A<<<SEQ + 1184, 256>>>(
        hidden, ln_w, p_h,
        wq_a, p_wqkva, (long)QLORA * HIDDEN / 4,
        wkv_a, p_wqkva + (long)QLORA * HIDDEN, (long)576 * HIDDEN / 4);
    // gemm1: fused q_a + ckv projection (272 tiles < 296 slots: plain launch)
    gemm_t32<<<dim3(17, SEQ / 128), 256, GEMM_SMEM>>>(
        p_h, HIDDEN, p_wqkva, p_qackv, SEQ, QKVN, HIDDEN, nullptr, 0.f);
    // B: rmsnorm(qa) + rmsnorm(ckv) + round wqb & wkvb
    rms_cvt_B<<<2 * SEQ + 1184, 256>>>(
        p_qackv, q_a_ln, p_qa, kv_a_ln, p_ckvn,
        wq_b, p_wqb, (long)3072 * QLORA / 4,
        wkv_b, p_wkvb, (long)4096 * KVLORA / 4);
    // merged up-projections: persistent over 384 (q, K=1536) + 512 (kv) tiles
    gemm_t32_dual_pers<<<PERS_GRID, 256, GEMM_SMEM>>>(
        p_qa, QLORA, p_wqb, p_q, 3072, QLORA, 24,
        p_ckvn, KVLORA, p_wkvb, p_kv, 4096, KVLORA, 32,
        24 * 16, 24 * 16 + 32 * 16);
    // C: rope+scatter + round wo
    rope_scatter_cvt<<<SEQ + 1184, 256>>>(
        p_q, p_qackv, p_kv, pos, qf_hi, qf_lo,
        k_out, k_hi, k_lo, v_out, v_hi, v_lo,
        wo, p_wo, (long)HIDDEN * 2048 / 4);
    flash_mma<<<dim3(SEQ / 128, NHEADS), 256, FLASH_SMEM>>>(
        qf_hi, qf_lo, k_hi, k_lo, v_hi, v_lo, p_attn);
    // out-proj: persistent over 40x16 = 640 tiles
    gemm_t32_pers<<<PERS_GRID, 256, GEMM_SMEM>>>(
        p_attn, 2048, p_wo, out, SEQ, HIDDEN, 2048, hidden, RESID_SCALE,
        40, 640);
}

// round 16
// speedup vs baseline: 1.9778x; 1.0178x over previous
#include <cuda_runtime.h>
#include <cuda_bf16.h>
#include <math.h>
#include <stdint.h>

#define HIDDEN 5120
#define NHEADS 16
#define QLORA  1536
#define KVLORA 512
#define NOPE   128
#define ROPE_D 64
#define QKD    192
#define VDIM   128
#define SEQ    2048
#define QKVN   2112
#define SM_SCALE 0.07216878364870322f  // 192^-0.5
#define RESID_SCALE 0.125f
#define PERS_GRID 296   // 2 CTAs/SM x 148 SMs

// ---------------- scratch ----------------------------------------------------
static __device__ float g_qackv[SEQ * QKVN];
static __device__ float g_q[SEQ * NHEADS * QKD];
static __device__ float g_kv[SEQ * 4096];
static __device__ float g_attn_f[SEQ * 2048];

static __device__ float g_h_f[SEQ * HIDDEN];
static __device__ float g_qa_f[SEQ * QLORA];
static __device__ float g_ckvn_f[SEQ * KVLORA];
static __device__ float g_wqkva_f[QKVN * HIDDEN];
static __device__ float g_wqb_f[3072 * QLORA];
static __device__ float g_wkvb_f[4096 * KVLORA];
static __device__ float g_wo_f[HIDDEN * 2048];

static __device__ float g_qf_f[NHEADS * SEQ * QKD];   // tf32-rounded Q [h][s][192]
static __device__ float g_k_f[NHEADS * SEQ * QKD];    // tf32-rounded K [h][s][192]
static __device__ __nv_bfloat16 g_v_hi[NHEADS * SEQ * VDIM], g_v_lo[NHEADS * SEQ * VDIM];

// ---------------- helpers ----------------------------------------------------
__device__ __forceinline__ uint32_t smem_u32(const void* p) {
    return (uint32_t)__cvta_generic_to_shared(p);
}
__device__ __forceinline__ void cpa16(uint32_t dst, const void* src, int sz) {
    asm volatile("cp.async.cg.shared.global [%0], [%1], 16, %2;"
                 :: "r"(dst), "l"(src), "r"(sz) : "memory");
}
#define CP_COMMIT() asm volatile("cp.async.commit_group;" ::: "memory")
#define CP_WAIT(n)  asm volatile("cp.async.wait_group %0;" :: "n"(n) : "memory")

__device__ __forceinline__ void ldsm4(uint32_t& r0, uint32_t& r1, uint32_t& r2, uint32_t& r3,
                                      uint32_t addr) {
    asm volatile("ldmatrix.sync.aligned.m8n8.x4.shared.b16 {%0,%1,%2,%3}, [%4];"
                 : "=r"(r0), "=r"(r1), "=r"(r2), "=r"(r3) : "r"(addr));
}
__device__ __forceinline__ void ldsm4t(uint32_t& r0, uint32_t& r1, uint32_t& r2, uint32_t& r3,
                                       uint32_t addr) {
    asm volatile("ldmatrix.sync.aligned.m8n8.x4.trans.shared.b16 {%0,%1,%2,%3}, [%4];"
                 : "=r"(r0), "=r"(r1), "=r"(r2), "=r"(r3) : "r"(addr));
}
__device__ __forceinline__ void mma16816(float* c, uint32_t a0, uint32_t a1, uint32_t a2,
                                         uint32_t a3, uint32_t b0, uint32_t b1) {
    asm volatile(
        "mma.sync.aligned.m16n8k16.row.col.f32.bf16.bf16.f32 "
        "{%0,%1,%2,%3}, {%4,%5,%6,%7}, {%8,%9}, {%0,%1,%2,%3};"
        : "+f"(c[0]), "+f"(c[1]), "+f"(c[2]), "+f"(c[3])
        : "r"(a0), "r"(a1), "r"(a2), "r"(a3), "r"(b0), "r"(b1));
}
__device__ __forceinline__ void mma_tf32(float* c, uint32_t a0, uint32_t a1, uint32_t a2,
                                         uint32_t a3, uint32_t b0, uint32_t b1) {
    asm volatile(
        "mma.sync.aligned.m16n8k8.row.col.f32.tf32.tf32.f32 "
        "{%0,%1,%2,%3}, {%4,%5,%6,%7}, {%8,%9}, {%0,%1,%2,%3};"
        : "+f"(c[0]), "+f"(c[1]), "+f"(c[2]), "+f"(c[3])
        : "r"(a0), "r"(a1), "r"(a2), "r"(a3), "r"(b0), "r"(b1));
}
__device__ __forceinline__ float tf32r(float x) {
    uint32_t u;
    asm("cvt.rna.tf32.f32 %0, %1;" : "=r"(u) : "f"(x));
    return __uint_as_float(u);
}
__device__ __forceinline__ void split2(float v0, float v1, uint32_t& hi, uint32_t& lo) {
    __nv_bfloat16 h0 = __float2bfloat16(v0), h1 = __float2bfloat16(v1);
    float r0 = v0 - __bfloat162float(h0), r1 = v1 - __bfloat162float(h1);
    __nv_bfloat162 th; th.x = h0; th.y = h1;
    hi = *reinterpret_cast<uint32_t*>(&th);
    __nv_bfloat162 tl; tl.x = __float2bfloat16(r0); tl.y = __float2bfloat16(r1);
    lo = *reinterpret_cast<uint32_t*>(&tl);
}

// ---------------- shared elementwise bodies -----------------------------------
__device__ __forceinline__ void cvt_body(const float* __restrict__ src, float* __restrict__ dst,
                                         long n4, long bid, long nb)
{
    const float4* s4 = (const float4*)src;
    float4* d4 = (float4*)dst;
    for (long i = bid * 256 + threadIdx.x; i < n4; i += nb * 256) {
        float4 v = s4[i];
        v.x = tf32r(v.x); v.y = tf32r(v.y); v.z = tf32r(v.z); v.w = tf32r(v.w);
        d4[i] = v;
    }
}

__device__ __forceinline__ void rms_body(const float* __restrict__ x, const float* __restrict__ w,
                                         float* __restrict__ y,
                                         int cols, int strideIn, int strideOut, int row)
{
    __shared__ float red[256];
    int t = threadIdx.x;
    const float4* xr = (const float4*)(x + (long)row * strideIn);
    const float4* w4 = (const float4*)w;
    int c4 = cols >> 2;
    float ss = 0.f;
    for (int c = t; c < c4; c += 256) {
        float4 v = xr[c];
        ss = fmaf(v.x, v.x, fmaf(v.y, v.y, fmaf(v.z, v.z, fmaf(v.w, v.w, ss))));
    }
    red[t] = ss; __syncthreads();
    for (int s = 128; s > 0; s >>= 1) { if (t < s) red[t] += red[t + s]; __syncthreads(); }
    float scale = rsqrtf(red[0] / (float)cols + 1e-6f);
    float4* yr = (float4*)(y + (long)row * strideOut);
    for (int c = t; c < c4; c += 256) {
        float4 v = xr[c];
        float4 wv = w4[c];
        float4 o;
        o.x = tf32r(v.x * scale * wv.x);
        o.y = tf32r(v.y * scale * wv.y);
        o.z = tf32r(v.z * scale * wv.z);
        o.w = tf32r(v.w * scale * wv.w);
        yr[c] = o;
    }
}

__global__ void rms_cvt_A(const float* __restrict__ x, const float* __restrict__ w,
                          float* __restrict__ y,
                          const float* __restrict__ ws1, float* __restrict__ wd1, long n1,
                          const float* __restrict__ ws2, float* __restrict__ wd2, long n2)
{
    if ((int)blockIdx.x < SEQ)
        rms_body(x, w, y, HIDDEN, HIDDEN, HIDDEN, blockIdx.x);
    else {
        long bid = blockIdx.x - SEQ, nb = gridDim.x - SEQ;
        cvt_body(ws1, wd1, n1, bid, nb);
        cvt_body(ws2, wd2, n2, bid, nb);
    }
}

__global__ void rms_cvt_B(const float* __restrict__ qackv,
                          const float* __restrict__ qw, float* __restrict__ qy,
                          const float* __restrict__ cw, float* __restrict__ cy,
                          const float* __restrict__ ws1, float* __restrict__ wd1, long n1,
                          const float* __restrict__ ws2, float* __restrict__ wd2, long n2)
{
    if ((int)blockIdx.x < SEQ)
        rms_body(qackv, qw, qy, QLORA, QKVN, QLORA, blockIdx.x);
    else if ((int)blockIdx.x < 2 * SEQ)
        rms_body(qackv + QLORA, cw, cy, KVLORA, QKVN, KVLORA, blockIdx.x - SEQ);
    else {
        long bid = blockIdx.x - 2 * SEQ, nb = gridDim.x - 2 * SEQ;
        cvt_body(ws1, wd1, n1, bid, nb);
        cvt_body(ws2, wd2, n2, bid, nb);
    }
}

// ---------------- tf32 single-pass GEMM (ldmatrix frags), 3 stages ------------
#define T32_TILE 16384
#define T32_STAGE (2 * T32_TILE)
#define GSTAGES 3
#define GEMM_SMEM (GSTAGES * T32_STAGE)  // 98304; 2 CTAs/SM

__device__ __forceinline__ void gt_fill(uint32_t dstBase, const float* __restrict__ src,
                                        long ld, int rmax, int t)
{
#pragma unroll
    for (int i = 0; i < 4; ++i) {
        int id = t + 256 * i;
        int row = id >> 3, ch = id & 7;
        bool ok = row < rmax;
        const float* g = src + (long)(ok ? row : 0) * ld + ch * 4;
        uint32_t cs = (uint32_t)(ch ^ (row & 7));
        cpa16(dstBase + row * 128 + cs * 16, g, ok ? 16 : 0);
    }
}

__device__ __forceinline__ void gemm_t32_core(
    const float* __restrict__ A, int lda,
    const float* __restrict__ B,
    float* __restrict__ C, int M, int N, int K,
    const float* __restrict__ D, float beta,
    int bx, int by, char* smem)
{
    uint32_t sb = smem_u32(smem);
    int t = threadIdx.x;
    int warp = t >> 5, lane = t & 31;
    int wm = warp >> 2, wn = warp & 3;
    int n0 = bx * 128, m0 = by * 128;
    int nc = K / 32;
    int q = lane >> 3, lr = lane & 7;

    uint32_t aRow[4];
#pragma unroll
    for (int im = 0; im < 4; ++im)
        aRow[im] = (uint32_t)((wm * 64 + im * 16 + ((q & 1) << 3) + lr) * 128);
    uint32_t bRow[2];
#pragma unroll
    for (int p = 0; p < 2; ++p)
        bRow[p] = (uint32_t)((wn * 32 + ((2 * p + (q >> 1)) << 3) + lr) * 128) + T32_TILE;

    float acc[4][4][4];
#pragma unroll
    for (int i = 0; i < 4; i++)
#pragma unroll
        for (int j = 0; j < 4; j++)
#pragma unroll
            for (int r = 0; r < 4; r++) acc[i][j][r] = 0.f;

#pragma unroll
    for (int s = 0; s < 2; ++s) {
        uint32_t b0 = sb + s * T32_STAGE;
        int kc0 = s * 32;
        gt_fill(b0,            A + (long)m0 * lda + kc0, lda, M - m0, t);
        gt_fill(b0 + T32_TILE, B + (long)n0 * K + kc0, K, N - n0, t);
        CP_COMMIT();
    }

    int stage = 0;
    for (int c = 0; c < nc; ++c) {
        CP_WAIT(1);
        __syncthreads();
        if (c + 2 < nc) {
            int ps = stage + 2; if (ps >= GSTAGES) ps -= GSTAGES;
            uint32_t bn = sb + ps * T32_STAGE;
            int kc0 = (c + 2) * 32;
            gt_fill(bn,            A + (long)m0 * lda + kc0, lda, M - m0, t);
            gt_fill(bn + T32_TILE, B + (long)n0 * K + kc0, K, N - n0, t);
        }
        CP_COMMIT();

        uint32_t sbase = sb + stage * T32_STAGE;
#pragma unroll
        for (int k8 = 0; k8 < 4; ++k8) {
            uint32_t swA = (uint32_t)(((2 * k8 + (q >> 1)) ^ lr) << 4);
            uint32_t swB = (uint32_t)(((2 * k8 + (q & 1)) ^ lr) << 4);
            uint32_t au[4][4];
#pragma unroll
            for (int im = 0; im < 4; ++im)
                ldsm4(au[im][0], au[im][1], au[im][2], au[im][3],
                      sbase + aRow[im] + swA);
            uint32_t bu[4][2];
#pragma unroll
            for (int p = 0; p < 2; ++p) {
                uint32_t r0, r1, r2, r3;
                ldsm4(r0, r1, r2, r3, sbase + bRow[p] + swB);
                bu[2 * p][0] = r0;     bu[2 * p][1] = r1;
                bu[2 * p + 1][0] = r2; bu[2 * p + 1][1] = r3;
            }
#pragma unroll
            for (int im = 0; im < 4; ++im)
#pragma unroll
                for (int jn = 0; jn < 4; ++jn)
                    mma_tf32(acc[im][jn], au[im][0], au[im][1], au[im][2], au[im][3],
                             bu[jn][0], bu[jn][1]);
        }
        if (++stage >= GSTAGES) stage = 0;
    }

#pragma unroll
    for (int im = 0; im < 4; ++im) {
        int row0 = m0 + wm * 64 + im * 16 + (lane >> 2);
#pragma unroll
        for (int jn = 0; jn < 4; ++jn) {
            int col = n0 + wn * 32 + jn * 8 + (lane & 3) * 2;
            if (col < N) {
                float2 v0 = make_float2(acc[im][jn][0], acc[im][jn][1]);
                float2 v1 = make_float2(acc[im][jn][2], acc[im][jn][3]);
                if (D) {
                    float2 d0 = *(const float2*)&D[(long)row0 * N + col];
                    float2 d1 = *(const float2*)&D[(long)(row0 + 8) * N + col];
                    v0.x = fmaf(beta, d0.x, v0.x); v0.y = fmaf(beta, d0.y, v0.y);
                    v1.x = fmaf(beta, d1.x, v1.x); v1.y = fmaf(beta, d1.y, v1.y);
                }
                *(float2*)&C[(long)row0 * N + col] = v0;
                *(float2*)&C[(long)(row0 + 8) * N + col] = v1;
            }
        }
    }
}

__global__ __launch_bounds__(256, 2)
void gemm_t32(const float* __restrict__ A, int lda, const float* __restrict__ B,
              float* __restrict__ C, int M, int N, int K,
              const float* __restrict__ D, float beta)
{
    extern __shared__ __align__(128) char smem[];
    gemm_t32_core(A, lda, B, C, M, N, K, D, beta, blockIdx.x, blockIdx.y, smem);
}

__global__ __launch_bounds__(256, 2)
void gemm_t32_pers(const float* __restrict__ A, int lda, const float* __restrict__ B,
                   float* __restrict__ C, int M, int N, int K,
                   const float* __restrict__ D, float beta, int nbx, int ntiles)
{
    extern __shared__ __align__(128) char smem[];
    for (int tile = blockIdx.x; tile < ntiles; tile += gridDim.x) {
        gemm_t32_core(A, lda, B, C, M, N, K, D, beta, tile % nbx, tile / nbx, smem);
        __syncthreads();
    }
}

__global__ __launch_bounds__(256, 2)
void gemm_t32_dual_pers(const float* __restrict__ A1, int lda1, const float* __restrict__ B1,
                        float* __restrict__ C1, int N1, int K1, int nbx1,
                        const float* __restrict__ A2, int lda2, const float* __restrict__ B2,
                        float* __restrict__ C2, int N2, int K2, int nbx2,
                        int ntiles1, int ntiles)
{
    extern __shared__ __align__(128) char smem[];
    for (int tile = blockIdx.x; tile < ntiles; tile += gridDim.x) {
        if (tile < ntiles1)
            gemm_t32_core(A1, lda1, B1, C1, SEQ, N1, K1, nullptr, 0.f,
                          tile % nbx1, tile / nbx1, smem);
        else {
            int t2 = tile - ntiles1;
            gemm_t32_core(A2, lda2, B2, C2, SEQ, N2, K2, nullptr, 0.f,
                          t2 % nbx2, t2 / nbx2, smem);
        }
        __syncthreads();
    }
}

// ---------------- RoPE + scatter (tf32 Q/K for flash) + wo tf32-round ---------
__global__ void rope_scatter_cvt(const float* __restrict__ qin,
                                 const float* __restrict__ qackv,
                                 const float* __restrict__ kvin,
                                 const int* __restrict__ pos_ids,
                                 float* __restrict__ qf,           // tf32 Q [h][s][192]
                                 float* __restrict__ kout,         // exact K (d_out)
                                 float* __restrict__ kf,           // tf32 K [h][s][192]
                                 float* __restrict__ vout,         // exact V (d_out)
                                 __nv_bfloat16* __restrict__ vh, __nv_bfloat16* __restrict__ vl,
                                 const float* __restrict__ ws, float* __restrict__ wd, long n4)
{
    if ((int)blockIdx.x >= SEQ) {
        cvt_body(ws, wd, n4, blockIdx.x - SEQ, gridDim.x - SEQ);
        return;
    }
    int s = blockIdx.x;
    int t = threadIdx.x;
    __shared__ float cs[32], sn[32], kr[64];
    if (t < 32) {
        double invf = exp(-(double)t * 0.28782313662425575); // ln(10000)/32
        double ang = (double)pos_ids[s] * invf;
        cs[t] = (float)cos(ang);
        sn[t] = (float)sin(ang);
    }
    __syncthreads();
    if (t < 32) {
        float x0 = qackv[(long)s * QKVN + 2048 + 2 * t];
        float x1 = qackv[(long)s * QKVN + 2048 + 2 * t + 1];
        kr[t]      = x0 * cs[t] - x1 * sn[t];
        kr[32 + t] = x1 * cs[t] + x0 * sn[t];
    }
    __syncthreads();
    // q pe
    {
        int h = t >> 4, j2 = t & 15;
        int j0 = 2 * j2, j1 = j0 + 1;
        const float* qb = qin + (long)s * 3072 + h * 192;
        float x0 = qb[128 + 2 * j0], x1 = qb[128 + 2 * j0 + 1];
        float x2 = qb[128 + 2 * j1], x3 = qb[128 + 2 * j1 + 1];
        float a0 = x0 * cs[j0] - x1 * sn[j0];
        float b0 = x1 * cs[j0] + x0 * sn[j0];
        float a1 = x2 * cs[j1] - x3 * sn[j1];
        float b1 = x3 * cs[j1] + x2 * sn[j1];
        long o = ((long)h * SEQ + s) * 192;
        *(float2*)&qf[o + 128 + j0] = make_float2(tf32r(a0), tf32r(a1));
        *(float2*)&qf[o + 160 + j0] = make_float2(tf32r(b0), tf32r(b1));
    }
    // q nope
    for (int idx = t; idx < 1024; idx += 256) {
        int h = idx >> 6, d = (idx & 63) * 2;
        float2 v = *(const float2*)&qin[(long)s * 3072 + h * 192 + d];
        long o = ((long)h * SEQ + s) * 192 + d;
        *(float2*)&qf[o] = make_float2(tf32r(v.x), tf32r(v.y));
    }
    // k: exact out + tf32 flash operand
    for (int idx = t; idx < 1536; idx += 256) {
        int h = idx / 96, d = (idx - h * 96) * 2;
        float2 v;
        if (d < 128) v = *(const float2*)&kvin[(long)s * 4096 + h * 256 + d];
        else         v = make_float2(kr[d - 128], kr[d - 127]);
        long o = ((long)h * SEQ + s) * 192 + d;
        *(float2*)&kout[o] = v;
        *(float2*)&kf[o] = make_float2(tf32r(v.x), tf32r(v.y));
    }
    // v: exact out + bf16 hi/lo for PV
    for (int idx = t; idx < 1024; idx += 256) {
        int h = idx >> 6, d = (idx & 63) * 2;
        float2 v = *(const float2*)&kvin[(long)s * 4096 + h * 256 + 128 + d];
        long o = ((long)h * SEQ + s) * 128 + d;
        *(float2*)&vout[o] = v;
        uint32_t hi, lo;
        split2(v.x, v.y, hi, lo);
        *(uint32_t*)&vh[o] = hi; *(uint32_t*)&vl[o] = lo;
    }
}

// ---------------- flash attention: tf32 QK, bf16x3 PV -------------------------
#define VPADB 272
#define FQ_B (128 * 768)            // Q: 128 rows x 192 fp32 (swizzled)
#define FK_B (32 * 768)             // K stage: 32 rows x 192 fp32
#define VT_B (32 * VPADB)           // V hi or lo stage
#define KV_BASE FQ_B                // 98304
#define KV_STAGE (FK_B + 2 * VT_B)  // 41984
#define FLASH_SMEM (KV_BASE + 2 * KV_STAGE)  // 182272

__device__ __forceinline__ void f_fill_kv(uint32_t dst,
                                          const float* __restrict__ Kf,
                                          const __nv_bfloat16* __restrict__ Vh,
                                          const __nv_bfloat16* __restrict__ Vl,
                                          long k0, int t)
{
#pragma unroll
    for (int i = 0; i < 6; ++i) {               // K: 32 rows x 48 chunks (16B)
        int id = t + 256 * i;
        int row = id / 48, c = id % 48;
        uint32_t cp = (uint32_t)((c & ~7) | ((c ^ row) & 7));
        cpa16(dst + row * 768 + cp * 16, Kf + (k0 + row) * 192 + c * 4, 16);
    }
#pragma unroll
    for (int i = 0; i < 2; ++i) {               // V: 32 rows x 16 chunks
        int id = t + 256 * i;
        int row = id >> 4, ch = id & 15;
        cpa16(dst + FK_B + row * VPADB + ch * 16, Vh + (k0 + row) * 128 + ch * 8, 16);
        cpa16(dst + FK_B + VT_B + row * VPADB + ch * 16, Vl + (k0 + row) * 128 + ch * 8, 16);
    }
}

__global__ __launch_bounds__(256, 1)
void flash_mma(const float* __restrict__ Qf_g, const float* __restrict__ Kf_g,
               const __nv_bfloat16* __restrict__ Vh_g, const __nv_bfloat16* __restrict__ Vl_g,
               float* __restrict__ O_g)
{
    extern __shared__ __align__(128) char smem[];
    uint32_t sb = smem_u32(smem);
    int qt = (int)gridDim.x - 1 - (int)blockIdx.x;
    int h = blockIdx.y;
    int q0 = qt * 128;
    int t = threadIdx.x;
    int warp = t >> 5, lane = t & 31;

    const float* Kgf = Kf_g + (long)h * SEQ * 192;
    const __nv_bfloat16* Vgh = Vh_g + (long)h * SEQ * 128;
    const __nv_bfloat16* Vgl = Vl_g + (long)h * SEQ * 128;

    // Q tile: 128 rows x 192 fp32, swizzled 768B rows
    {
        const float* qg = Qf_g + ((long)h * SEQ + q0) * 192;
#pragma unroll
        for (int i = 0; i < 24; ++i) {          // 6144 ids
            int id = t + 256 * i;
            int row = id / 48, c = id % 48;
            uint32_t cp = (uint32_t)((c & ~7) | ((c ^ row) & 7));
            cpa16(sb + row * 768 + cp * 16, qg + (long)row * 192 + c * 4, 16);
        }
        CP_COMMIT();
    }
    f_fill_kv(sb + KV_BASE, Kgf, Vgh, Vgl, 0, t);
    CP_COMMIT();

    float o[16][4];
#pragma unroll
    for (int i = 0; i < 16; i++)
#pragma unroll
        for (int r = 0; r < 4; r++) o[i][r] = 0.f;
    float mrow[2] = {-1e30f, -1e30f};
    float lrow[2] = {0.f, 0.f};

    int qq = lane >> 3, lr = lane & 7;
    uint32_t qRow = (uint32_t)((warp * 16 + ((qq & 1) << 3) + lr) * 768);
    uint32_t kRow[2];
#pragma unroll
    for (int p = 0; p < 2; ++p)
        kRow[p] = (uint32_t)((((2 * p + (qq >> 1)) << 3) + lr) * 768);

    uint32_t voff = (uint32_t)(((lane & 7) + (((lane >> 3) & 1) << 3)) * VPADB +
                               ((lane >> 4) << 3) * 2);

    int rA = (lane >> 2);
    int colq = (lane & 3) * 2;
    int rowA = q0 + warp * 16 + rA;
    int rowB = rowA + 8;
    int nkt = 4 * qt + 4;

    for (int kt = 0; kt < nkt; ++kt) {
        __syncthreads();
        if (kt + 1 < nkt)
            f_fill_kv(sb + KV_BASE + ((kt + 1) & 1) * KV_STAGE, Kgf, Vgh, Vgl,
                      (long)(kt + 1) * 32, t);
        CP_COMMIT();
        CP_WAIT(1);
        __syncthreads();

        int k0 = kt * 32;
        uint32_t kvb = sb + KV_BASE + (kt & 1) * KV_STAGE;

        // ---- S = Q @ K^T (tf32 single pass, 24 k8 steps) ----
        float sc[4][4];
#pragma unroll
        for (int j = 0; j < 4; j++)
#pragma unroll
            for (int r = 0; r < 4; r++) sc[j][r] = 0.f;

#pragma unroll 2
        for (int k8 = 0; k8 < 24; ++k8) {
            int cA = 2 * k8 + (qq >> 1);
            uint32_t offA = (uint32_t)(((cA & ~7) | ((cA ^ lr) & 7)) << 4);
            uint32_t au[4];
            ldsm4(au[0], au[1], au[2], au[3], sb + qRow + offA);
            int cB = 2 * k8 + (qq & 1);
            uint32_t offB = (uint32_t)(((cB & ~7) | ((cB ^ lr) & 7)) << 4);
            uint32_t bu[4][2];
#pragma unroll
            for (int p = 0; p < 2; ++p) {
                uint32_t r0, r1, r2, r3;
                ldsm4(r0, r1, r2, r3, kvb + kRow[p] + offB);
                bu[2 * p][0] = r0;     bu[2 * p][1] = r1;
                bu[2 * p + 1][0] = r2; bu[2 * p + 1][1] = r3;
            }
#pragma unroll
            for (int j = 0; j < 4; ++j)
                mma_tf32(sc[j], au[0], au[1], au[2], au[3], bu[j][0], bu[j][1]);
        }

        bool diag = (kt >= 4 * qt);
#pragma unroll
        for (int j = 0; j < 4; ++j) {
#pragma unroll
            for (int r = 0; r < 4; r++) sc[j][r] *= SM_SCALE;
            if (diag) {
                int col = k0 + j * 8 + colq;
                if (col > rowA)     sc[j][0] = -1e30f;
                if (col + 1 > rowA) sc[j][1] = -1e30f;
                if (col > rowB)     sc[j][2] = -1e30f;
                if (col + 1 > rowB) sc[j][3] = -1e30f;
            }
        }
        float mxa = -1e30f, mxb = -1e30f;
#pragma unroll
        for (int j = 0; j < 4; ++j) {
            mxa = fmaxf(mxa, fmaxf(sc[j][0], sc[j][1]));
            mxb = fmaxf(mxb, fmaxf(sc[j][2], sc[j][3]));
        }
        mxa = fmaxf(mxa, __shfl_xor_sync(0xffffffffu, mxa, 1));
        mxa = fmaxf(mxa, __shfl_xor_sync(0xffffffffu, mxa, 2));
        mxb = fmaxf(mxb, __shfl_xor_sync(0xffffffffu, mxb, 1));
        mxb = fmaxf(mxb, __shfl_xor_sync(0xffffffffu, mxb, 2));
        float mna = fmaxf(mrow[0], mxa), mnb = fmaxf(mrow[1], mxb);
        float ala = __expf(mrow[0] - mna), alb = __expf(mrow[1] - mnb);
        mrow[0] = mna; mrow[1] = mnb;

        float suma = 0.f, sumb = 0.f;
#pragma unroll
        for (int j = 0; j < 4; ++j) {
            sc[j][0] = __expf(sc[j][0] - mna);
            sc[j][1] = __expf(sc[j][1] - mna);
            sc[j][2] = __expf(sc[j][2] - mnb);
            sc[j][3] = __expf(sc[j][3] - mnb);
            suma += sc[j][0] + sc[j][1];
            sumb += sc[j][2] + sc[j][3];
        }
        suma += __shfl_xor_sync(0xffffffffu, suma, 1);
        suma += __shfl_xor_sync(0xffffffffu, suma, 2);
        sumb += __shfl_xor_sync(0xffffffffu, sumb, 1);
        sumb += __shfl_xor_sync(0xffffffffu, sumb, 2);
        lrow[0] = lrow[0] * ala + suma;
        lrow[1] = lrow[1] * alb + sumb;
#pragma unroll
        for (int nb = 0; nb < 16; ++nb) {
            o[nb][0] *= ala; o[nb][1] *= ala;
            o[nb][2] *= alb; o[nb][3] *= alb;
        }

        // ---- O += P @ V (bf16x3, unchanged) ----
        uint32_t pah[2][4], pal[2][4];
#pragma unroll
        for (int j = 0; j < 2; ++j) {
            split2(sc[2 * j][0],     sc[2 * j][1],     pah[j][0], pal[j][0]);
            split2(sc[2 * j][2],     sc[2 * j][3],     pah[j][1], pal[j][1]);
            split2(sc[2 * j + 1][0], sc[2 * j + 1][1], pah[j][2], pal[j][2]);
            split2(sc[2 * j + 1][2], sc[2 * j + 1][3], pah[j][3], pal[j][3]);
        }

        uint32_t vbase = kvb + FK_B;
#pragma unroll 1
        for (int j = 0; j < 2; ++j) {
#pragma unroll
            for (int nb2 = 0; nb2 < 8; ++nb2) {
                uint32_t va = vbase + voff + j * 16 * VPADB + nb2 * 32;
                uint32_t h0, h1, h2, h3, l0, l1, l2, l3;
                ldsm4t(h0, h1, h2, h3, va);
                ldsm4t(l0, l1, l2, l3, va + VT_B);
                mma16816(o[2 * nb2],     pah[j][0], pah[j][1], pah[j][2], pah[j][3], h0, h1);
                mma16816(o[2 * nb2 + 1], pah[j][0], pah[j][1], pah[j][2], pah[j][3], h2, h3);
                mma16816(o[2 * nb2],     pah[j][0], pah[j][1], pah[j][2], pah[j][3], l0, l1);
                mma16816(o[2 * nb2 + 1], pah[j][0], pah[j][1], pah[j][2], pah[j][3], l2, l3);
                mma16816(o[2 * nb2],     pal[j][0], pal[j][1], pal[j][2], pal[j][3], h0, h1);
                mma16816(o[2 * nb2 + 1], pal[j][0], pal[j][1], pal[j][2], pal[j][3], h2, h3);
            }
        }
    }

    float inva = 1.0f / lrow[0], invb = 1.0f / lrow[1];
#pragma unroll
    for (int nb = 0; nb < 16; ++nb) {
        int col = h * 128 + nb * 8 + colq;
        float2 vA = make_float2(tf32r(o[nb][0] * inva), tf32r(o[nb][1] * inva));
        float2 vB = make_float2(tf32r(o[nb][2] * invb), tf32r(o[nb][3] * invb));
        *(float2*)&O_g[(long)rowA * 2048 + col] = vA;
        *(float2*)&O_g[(long)rowB * 2048 + col] = vB;
    }
}

// ---------------- launch ------------------------------------------------------
extern "C" void kernel_launch(void* const* d_in, const int* in_sizes, int n_in,
                              void* d_out, int out_size)
{
    const float* hidden   = (const float*)d_in[0];
    const int*   pos      = (const int*)d_in[1];
    const float* ln_w     = (const float*)d_in[3];
    const float* wq_a     = (const float*)d_in[4];
    const float* q_a_ln   = (const float*)d_in[5];
    const float* wq_b     = (const float*)d_in[6];
    const float* wkv_a    = (const float*)d_in[7];
    const float* kv_a_ln  = (const float*)d_in[8];
    const float* wkv_b    = (const float*)d_in[9];
    const float* wo       = (const float*)d_in[10];

    float* out   = (float*)d_out;
    float* k_out = out + (long)SEQ * HIDDEN;
    float* v_out = k_out + (long)NHEADS * SEQ * QKD;

    float *p_qackv, *p_q, *p_kv, *p_attn, *p_h, *p_qa, *p_ckvn;
    float *p_wqkva, *p_wqb, *p_wkvb, *p_wo, *p_qf, *p_kf;
    cudaGetSymbolAddress((void**)&p_qackv, g_qackv);
    cudaGetSymbolAddress((void**)&p_q, g_q);
    cudaGetSymbolAddress((void**)&p_kv, g_kv);
    cudaGetSymbolAddress((void**)&p_attn, g_attn_f);
    cudaGetSymbolAddress((void**)&p_h, g_h_f);
    cudaGetSymbolAddress((void**)&p_qa, g_qa_f);
    cudaGetSymbolAddress((void**)&p_ckvn, g_ckvn_f);
    cudaGetSymbolAddress((void**)&p_wqkva, g_wqkva_f);
    cudaGetSymbolAddress((void**)&p_wqb, g_wqb_f);
    cudaGetSymbolAddress((void**)&p_wkvb, g_wkvb_f);
    cudaGetSymbolAddress((void**)&p_wo, g_wo_f);
    cudaGetSymbolAddress((void**)&p_qf, g_qf_f);
    cudaGetSymbolAddress((void**)&p_kf, g_k_f);

    __nv_bfloat16 *v_hi, *v_lo;
    cudaGetSymbolAddress((void**)&v_hi, g_v_hi);
    cudaGetSymbolAddress((void**)&v_lo, g_v_lo);

    cudaFuncSetAttribute(gemm_t32, cudaFuncAttributeMaxDynamicSharedMemorySize, GEMM_SMEM);
    cudaFuncSetAttribute(gemm_t32_pers, cudaFuncAttributeMaxDynamicSharedMemorySize, GEMM_SMEM);
    cudaFuncSetAttribute(gemm_t32_dual_pers, cudaFuncAttributeMaxDynamicSharedMemorySize, GEMM_SMEM);
    cudaFuncSetAttribute(flash_mma, cudaFuncAttributeMaxDynamicSharedMemorySize, FLASH_SMEM);

    // A: rmsnorm(hidden) + round wq_a and wkv_a
    rms_cvt_A<<<SEQ + 1184, 256>>>(
        hidden, ln_w, p_h,
        wq_a, p_wqkva, (long)QLORA * HIDDEN / 4,
        wkv_a, p_wqkva + (long)QLORA * HIDDEN, (long)576 * HIDDEN / 4);
    gemm_t32<<<dim3(17, SEQ / 128), 256, GEMM_SMEM>>>(
        p_h, HIDDEN, p_wqkva, p_qackv, SEQ, QKVN, HIDDEN, nullptr, 0.f);
    rms_cvt_B<<<2 * SEQ + 1184, 256>>>(
        p_qackv, q_a_ln, p_qa, kv_a_ln, p_ckvn,
        wq_b, p_wqb, (long)3072 * QLORA / 4,
        wkv_b, p_wkvb, (long)4096 * KVLORA / 4);
    gemm_t32_dual_pers<<<PERS_GRID, 256, GEMM_SMEM>>>(
        p_qa, QLORA, p_wqb, p_q, 3072, QLORA, 24,
        p_ckvn, KVLORA, p_wkvb, p_kv, 4096, KVLORA, 32,
        24 * 16, 24 * 16 + 32 * 16);
    rope_scatter_cvt<<<SEQ + 1184, 256>>>(
        p_q, p_qackv, p_kv, pos, p_qf,
        k_out, p_kf, v_out, v_hi, v_lo,
        wo, p_wo, (long)HIDDEN * 2048 / 4);
    flash_mma<<<dim3(SEQ / 128, NHEADS), 256, FLASH_SMEM>>>(
        p_qf, p_kf, v_hi, v_lo, p_attn);
    gemm_t32_pers<<<PERS_GRID, 256, GEMM_SMEM>>>(
        p_attn, 2048, p_wo, out, SEQ, HIDDEN, 2048, hidden, RESID_SCALE,
        40, 640);
}

// round 17
// speedup vs baseline: 1.9859x; 1.0041x over previous
#include <cuda_runtime.h>
#include <cuda_bf16.h>
#include <math.h>
#include <stdint.h>

#define HIDDEN 5120
#define NHEADS 16
#define QLORA  1536
#define KVLORA 512
#define NOPE   128
#define ROPE_D 64
#define QKD    192
#define VDIM   128
#define SEQ    2048
#define QKVN   2112
#define SM_SCALE 0.07216878364870322f  // 192^-0.5
#define RESID_SCALE 0.125f
#define PERS_GRID 296   // 2 CTAs/SM x 148 SMs

// ---------------- scratch ----------------------------------------------------
static __device__ float g_qackv[SEQ * QKVN];
static __device__ float g_q[SEQ * NHEADS * QKD];
static __device__ float g_kv[SEQ * 4096];
static __device__ float g_attn_f[SEQ * 2048];

static __device__ float g_h_f[SEQ * HIDDEN];
static __device__ float g_qa_f[SEQ * QLORA];
static __device__ float g_ckvn_f[SEQ * KVLORA];
static __device__ float g_wqkva_f[QKVN * HIDDEN];
static __device__ float g_wqb_f[3072 * QLORA];
static __device__ float g_wkvb_f[4096 * KVLORA];
static __device__ float g_wo_f[HIDDEN * 2048];

static __device__ float g_qf_f[NHEADS * SEQ * QKD];   // tf32-rounded Q [h][s][192]
static __device__ float g_k_f[NHEADS * SEQ * QKD];    // tf32-rounded K [h][s][192]
static __device__ __nv_bfloat16 g_v_hi[NHEADS * SEQ * VDIM], g_v_lo[NHEADS * SEQ * VDIM];

// ---------------- helpers ----------------------------------------------------
__device__ __forceinline__ uint32_t smem_u32(const void* p) {
    return (uint32_t)__cvta_generic_to_shared(p);
}
__device__ __forceinline__ void cpa16(uint32_t dst, const void* src, int sz) {
    asm volatile("cp.async.cg.shared.global [%0], [%1], 16, %2;"
                 :: "r"(dst), "l"(src), "r"(sz) : "memory");
}
#define CP_COMMIT() asm volatile("cp.async.commit_group;" ::: "memory")
#define CP_WAIT(n)  asm volatile("cp.async.wait_group %0;" :: "n"(n) : "memory")

__device__ __forceinline__ void ldsm4(uint32_t& r0, uint32_t& r1, uint32_t& r2, uint32_t& r3,
                                      uint32_t addr) {
    asm volatile("ldmatrix.sync.aligned.m8n8.x4.shared.b16 {%0,%1,%2,%3}, [%4];"
                 : "=r"(r0), "=r"(r1), "=r"(r2), "=r"(r3) : "r"(addr));
}
__device__ __forceinline__ void ldsm4t(uint32_t& r0, uint32_t& r1, uint32_t& r2, uint32_t& r3,
                                       uint32_t addr) {
    asm volatile("ldmatrix.sync.aligned.m8n8.x4.trans.shared.b16 {%0,%1,%2,%3}, [%4];"
                 : "=r"(r0), "=r"(r1), "=r"(r2), "=r"(r3) : "r"(addr));
}
__device__ __forceinline__ void mma16816(float* c, uint32_t a0, uint32_t a1, uint32_t a2,
                                         uint32_t a3, uint32_t b0, uint32_t b1) {
    asm volatile(
        "mma.sync.aligned.m16n8k16.row.col.f32.bf16.bf16.f32 "
        "{%0,%1,%2,%3}, {%4,%5,%6,%7}, {%8,%9}, {%0,%1,%2,%3};"
        : "+f"(c[0]), "+f"(c[1]), "+f"(c[2]), "+f"(c[3])
        : "r"(a0), "r"(a1), "r"(a2), "r"(a3), "r"(b0), "r"(b1));
}
__device__ __forceinline__ void mma_tf32(float* c, uint32_t a0, uint32_t a1, uint32_t a2,
                                         uint32_t a3, uint32_t b0, uint32_t b1) {
    asm volatile(
        "mma.sync.aligned.m16n8k8.row.col.f32.tf32.tf32.f32 "
        "{%0,%1,%2,%3}, {%4,%5,%6,%7}, {%8,%9}, {%0,%1,%2,%3};"
        : "+f"(c[0]), "+f"(c[1]), "+f"(c[2]), "+f"(c[3])
        : "r"(a0), "r"(a1), "r"(a2), "r"(a3), "r"(b0), "r"(b1));
}
__device__ __forceinline__ float tf32r(float x) {
    uint32_t u;
    asm("cvt.rna.tf32.f32 %0, %1;" : "=r"(u) : "f"(x));
    return __uint_as_float(u);
}
__device__ __forceinline__ void split2(float v0, float v1, uint32_t& hi, uint32_t& lo) {
    __nv_bfloat16 h0 = __float2bfloat16(v0), h1 = __float2bfloat16(v1);
    float r0 = v0 - __bfloat162float(h0), r1 = v1 - __bfloat162float(h1);
    __nv_bfloat162 th; th.x = h0; th.y = h1;
    hi = *reinterpret_cast<uint32_t*>(&th);
    __nv_bfloat162 tl; tl.x = __float2bfloat16(r0); tl.y = __float2bfloat16(r1);
    lo = *reinterpret_cast<uint32_t*>(&tl);
}

// ---------------- shared elementwise bodies -----------------------------------
__device__ __forceinline__ void cvt_body(const float* __restrict__ src, float* __restrict__ dst,
                                         long n4, long bid, long nb)
{
    const float4* s4 = (const float4*)src;
    float4* d4 = (float4*)dst;
    for (long i = bid * 256 + threadIdx.x; i < n4; i += nb * 256) {
        float4 v = s4[i];
        v.x = tf32r(v.x); v.y = tf32r(v.y); v.z = tf32r(v.z); v.w = tf32r(v.w);
        d4[i] = v;
    }
}

// single-barrier rmsnorm (warp-shuffle reduce + smem exchange)
__device__ __forceinline__ void rms_body(const float* __restrict__ x, const float* __restrict__ w,
                                         float* __restrict__ y,
                                         int cols, int strideIn, int strideOut, int row)
{
    __shared__ float red[8];
    int t = threadIdx.x;
    const float4* xr = (const float4*)(x + (long)row * strideIn);
    const float4* w4 = (const float4*)w;
    int c4 = cols >> 2;
    float ss = 0.f;
    for (int c = t; c < c4; c += 256) {
        float4 v = xr[c];
        ss = fmaf(v.x, v.x, fmaf(v.y, v.y, fmaf(v.z, v.z, fmaf(v.w, v.w, ss))));
    }
#pragma unroll
    for (int off = 16; off > 0; off >>= 1)
        ss += __shfl_xor_sync(0xffffffffu, ss, off);
    if ((t & 31) == 0) red[t >> 5] = ss;
    __syncthreads();
    float tot = red[0] + red[1] + red[2] + red[3] + red[4] + red[5] + red[6] + red[7];
    float scale = rsqrtf(tot / (float)cols + 1e-6f);
    float4* yr = (float4*)(y + (long)row * strideOut);
    for (int c = t; c < c4; c += 256) {
        float4 v = xr[c];
        float4 wv = w4[c];
        float4 o;
        o.x = tf32r(v.x * scale * wv.x);
        o.y = tf32r(v.y * scale * wv.y);
        o.z = tf32r(v.z * scale * wv.z);
        o.w = tf32r(v.w * scale * wv.w);
        yr[c] = o;
    }
}

__global__ void rms_cvt_A(const float* __restrict__ x, const float* __restrict__ w,
                          float* __restrict__ y,
                          const float* __restrict__ ws1, float* __restrict__ wd1, long n1,
                          const float* __restrict__ ws2, float* __restrict__ wd2, long n2)
{
    if ((int)blockIdx.x < SEQ)
        rms_body(x, w, y, HIDDEN, HIDDEN, HIDDEN, blockIdx.x);
    else {
        long bid = blockIdx.x - SEQ, nb = gridDim.x - SEQ;
        cvt_body(ws1, wd1, n1, bid, nb);
        cvt_body(ws2, wd2, n2, bid, nb);
    }
}

__global__ void rms_cvt_B(const float* __restrict__ qackv,
                          const float* __restrict__ qw, float* __restrict__ qy,
                          const float* __restrict__ cw, float* __restrict__ cy,
                          const float* __restrict__ ws1, float* __restrict__ wd1, long n1,
                          const float* __restrict__ ws2, float* __restrict__ wd2, long n2)
{
    if ((int)blockIdx.x < SEQ)
        rms_body(qackv, qw, qy, QLORA, QKVN, QLORA, blockIdx.x);
    else if ((int)blockIdx.x < 2 * SEQ)
        rms_body(qackv + QLORA, cw, cy, KVLORA, QKVN, KVLORA, blockIdx.x - SEQ);
    else {
        long bid = blockIdx.x - 2 * SEQ, nb = gridDim.x - 2 * SEQ;
        cvt_body(ws1, wd1, n1, bid, nb);
        cvt_body(ws2, wd2, n2, bid, nb);
    }
}

// ---------------- tf32 single-pass GEMM (ldmatrix frags), 3 stages ------------
#define T32_TILE 16384
#define T32_STAGE (2 * T32_TILE)
#define GSTAGES 3
#define GEMM_SMEM (GSTAGES * T32_STAGE)  // 98304; 2 CTAs/SM

__device__ __forceinline__ void gt_fill(uint32_t dstBase, const float* __restrict__ src,
                                        long ld, int rmax, int t)
{
#pragma unroll
    for (int i = 0; i < 4; ++i) {
        int id = t + 256 * i;
        int row = id >> 3, ch = id & 7;
        bool ok = row < rmax;
        const float* g = src + (long)(ok ? row : 0) * ld + ch * 4;
        uint32_t cs = (uint32_t)(ch ^ (row & 7));
        cpa16(dstBase + row * 128 + cs * 16, g, ok ? 16 : 0);
    }
}

__device__ __forceinline__ void gemm_t32_core(
    const float* __restrict__ A, int lda,
    const float* __restrict__ B,
    float* __restrict__ C, int M, int N, int K,
    const float* __restrict__ D, float beta,
    int bx, int by, char* smem)
{
    uint32_t sb = smem_u32(smem);
    int t = threadIdx.x;
    int warp = t >> 5, lane = t & 31;
    int wm = warp >> 2, wn = warp & 3;
    int n0 = bx * 128, m0 = by * 128;
    int nc = K / 32;
    int q = lane >> 3, lr = lane & 7;

    uint32_t aRow[4];
#pragma unroll
    for (int im = 0; im < 4; ++im)
        aRow[im] = (uint32_t)((wm * 64 + im * 16 + ((q & 1) << 3) + lr) * 128);
    uint32_t bRow[2];
#pragma unroll
    for (int p = 0; p < 2; ++p)
        bRow[p] = (uint32_t)((wn * 32 + ((2 * p + (q >> 1)) << 3) + lr) * 128) + T32_TILE;

    float acc[4][4][4];
#pragma unroll
    for (int i = 0; i < 4; i++)
#pragma unroll
        for (int j = 0; j < 4; j++)
#pragma unroll
            for (int r = 0; r < 4; r++) acc[i][j][r] = 0.f;

#pragma unroll
    for (int s = 0; s < 2; ++s) {
        uint32_t b0 = sb + s * T32_STAGE;
        int kc0 = s * 32;
        gt_fill(b0,            A + (long)m0 * lda + kc0, lda, M - m0, t);
        gt_fill(b0 + T32_TILE, B + (long)n0 * K + kc0, K, N - n0, t);
        CP_COMMIT();
    }

    int stage = 0;
    for (int c = 0; c < nc; ++c) {
        CP_WAIT(1);
        __syncthreads();
        if (c + 2 < nc) {
            int ps = stage + 2; if (ps >= GSTAGES) ps -= GSTAGES;
            uint32_t bn = sb + ps * T32_STAGE;
            int kc0 = (c + 2) * 32;
            gt_fill(bn,            A + (long)m0 * lda + kc0, lda, M - m0, t);
            gt_fill(bn + T32_TILE, B + (long)n0 * K + kc0, K, N - n0, t);
        }
        CP_COMMIT();

        uint32_t sbase = sb + stage * T32_STAGE;
#pragma unroll
        for (int k8 = 0; k8 < 4; ++k8) {
            uint32_t swA = (uint32_t)(((2 * k8 + (q >> 1)) ^ lr) << 4);
            uint32_t swB = (uint32_t)(((2 * k8 + (q & 1)) ^ lr) << 4);
            uint32_t au[4][4];
#pragma unroll
            for (int im = 0; im < 4; ++im)
                ldsm4(au[im][0], au[im][1], au[im][2], au[im][3],
                      sbase + aRow[im] + swA);
            uint32_t bu[4][2];
#pragma unroll
            for (int p = 0; p < 2; ++p) {
                uint32_t r0, r1, r2, r3;
                ldsm4(r0, r1, r2, r3, sbase + bRow[p] + swB);
                bu[2 * p][0] = r0;     bu[2 * p][1] = r1;
                bu[2 * p + 1][0] = r2; bu[2 * p + 1][1] = r3;
            }
#pragma unroll
            for (int im = 0; im < 4; ++im)
#pragma unroll
                for (int jn = 0; jn < 4; ++jn)
                    mma_tf32(acc[im][jn], au[im][0], au[im][1], au[im][2], au[im][3],
                             bu[jn][0], bu[jn][1]);
        }
        if (++stage >= GSTAGES) stage = 0;
    }

#pragma unroll
    for (int im = 0; im < 4; ++im) {
        int row0 = m0 + wm * 64 + im * 16 + (lane >> 2);
#pragma unroll
        for (int jn = 0; jn < 4; ++jn) {
            int col = n0 + wn * 32 + jn * 8 + (lane & 3) * 2;
            if (col < N) {
                float2 v0 = make_float2(acc[im][jn][0], acc[im][jn][1]);
                float2 v1 = make_float2(acc[im][jn][2], acc[im][jn][3]);
                if (D) {
                    float2 d0 = *(const float2*)&D[(long)row0 * N + col];
                    float2 d1 = *(const float2*)&D[(long)(row0 + 8) * N + col];
                    v0.x = fmaf(beta, d0.x, v0.x); v0.y = fmaf(beta, d0.y, v0.y);
                    v1.x = fmaf(beta, d1.x, v1.x); v1.y = fmaf(beta, d1.y, v1.y);
                }
                *(float2*)&C[(long)row0 * N + col] = v0;
                *(float2*)&C[(long)(row0 + 8) * N + col] = v1;
            }
        }
    }
}

__global__ __launch_bounds__(256, 2)
void gemm_t32(const float* __restrict__ A, int lda, const float* __restrict__ B,
              float* __restrict__ C, int M, int N, int K,
              const float* __restrict__ D, float beta)
{
    extern __shared__ __align__(128) char smem[];
    gemm_t32_core(A, lda, B, C, M, N, K, D, beta, blockIdx.x, blockIdx.y, smem);
}

__global__ __launch_bounds__(256, 2)
void gemm_t32_pers(const float* __restrict__ A, int lda, const float* __restrict__ B,
                   float* __restrict__ C, int M, int N, int K,
                   const float* __restrict__ D, float beta, int nbx, int ntiles)
{
    extern __shared__ __align__(128) char smem[];
    for (int tile = blockIdx.x; tile < ntiles; tile += gridDim.x) {
        gemm_t32_core(A, lda, B, C, M, N, K, D, beta, tile % nbx, tile / nbx, smem);
        __syncthreads();
    }
}

__global__ __launch_bounds__(256, 2)
void gemm_t32_dual_pers(const float* __restrict__ A1, int lda1, const float* __restrict__ B1,
                        float* __restrict__ C1, int N1, int K1, int nbx1,
                        const float* __restrict__ A2, int lda2, const float* __restrict__ B2,
                        float* __restrict__ C2, int N2, int K2, int nbx2,
                        int ntiles1, int ntiles)
{
    extern __shared__ __align__(128) char smem[];
    for (int tile = blockIdx.x; tile < ntiles; tile += gridDim.x) {
        if (tile < ntiles1)
            gemm_t32_core(A1, lda1, B1, C1, SEQ, N1, K1, nullptr, 0.f,
                          tile % nbx1, tile / nbx1, smem);
        else {
            int t2 = tile - ntiles1;
            gemm_t32_core(A2, lda2, B2, C2, SEQ, N2, K2, nullptr, 0.f,
                          t2 % nbx2, t2 / nbx2, smem);
        }
        __syncthreads();
    }
}

// ---------------- RoPE + scatter (tf32 Q/K for flash) + wo tf32-round ---------
__global__ void rope_scatter_cvt(const float* __restrict__ qin,
                                 const float* __restrict__ qackv,
                                 const float* __restrict__ kvin,
                                 const int* __restrict__ pos_ids,
                                 float* __restrict__ qf,
                                 float* __restrict__ kout,
                                 float* __restrict__ kf,
                                 float* __restrict__ vout,
                                 __nv_bfloat16* __restrict__ vh, __nv_bfloat16* __restrict__ vl,
                                 const float* __restrict__ ws, float* __restrict__ wd, long n4)
{
    if ((int)blockIdx.x >= SEQ) {
        cvt_body(ws, wd, n4, blockIdx.x - SEQ, gridDim.x - SEQ);
        return;
    }
    int s = blockIdx.x;
    int t = threadIdx.x;
    __shared__ float cs[32], sn[32], kr[64];
    if (t < 32) {
        double invf = exp(-(double)t * 0.28782313662425575); // ln(10000)/32
        double ang = (double)pos_ids[s] * invf;
        cs[t] = (float)cos(ang);
        sn[t] = (float)sin(ang);
    }
    __syncthreads();
    if (t < 32) {
        float x0 = qackv[(long)s * QKVN + 2048 + 2 * t];
        float x1 = qackv[(long)s * QKVN + 2048 + 2 * t + 1];
        kr[t]      = x0 * cs[t] - x1 * sn[t];
        kr[32 + t] = x1 * cs[t] + x0 * sn[t];
    }
    __syncthreads();
    // q pe
    {
        int h = t >> 4, j2 = t & 15;
        int j0 = 2 * j2, j1 = j0 + 1;
        const float* qb = qin + (long)s * 3072 + h * 192;
        float x0 = qb[128 + 2 * j0], x1 = qb[128 + 2 * j0 + 1];
        float x2 = qb[128 + 2 * j1], x3 = qb[128 + 2 * j1 + 1];
        float a0 = x0 * cs[j0] - x1 * sn[j0];
        float b0 = x1 * cs[j0] + x0 * sn[j0];
        float a1 = x2 * cs[j1] - x3 * sn[j1];
        float b1 = x3 * cs[j1] + x2 * sn[j1];
        long o = ((long)h * SEQ + s) * 192;
        *(float2*)&qf[o + 128 + j0] = make_float2(tf32r(a0), tf32r(a1));
        *(float2*)&qf[o + 160 + j0] = make_float2(tf32r(b0), tf32r(b1));
    }
    // q nope
    for (int idx = t; idx < 1024; idx += 256) {
        int h = idx >> 6, d = (idx & 63) * 2;
        float2 v = *(const float2*)&qin[(long)s * 3072 + h * 192 + d];
        long o = ((long)h * SEQ + s) * 192 + d;
        *(float2*)&qf[o] = make_float2(tf32r(v.x), tf32r(v.y));
    }
    // k: exact out + tf32 flash operand
    for (int idx = t; idx < 1536; idx += 256) {
        int h = idx / 96, d = (idx - h * 96) * 2;
        float2 v;
        if (d < 128) v = *(const float2*)&kvin[(long)s * 4096 + h * 256 + d];
        else         v = make_float2(kr[d - 128], kr[d - 127]);
        long o = ((long)h * SEQ + s) * 192 + d;
        *(float2*)&kout[o] = v;
        *(float2*)&kf[o] = make_float2(tf32r(v.x), tf32r(v.y));
    }
    // v: exact out + bf16 hi/lo for PV
    for (int idx = t; idx < 1024; idx += 256) {
        int h = idx >> 6, d = (idx & 63) * 2;
        float2 v = *(const float2*)&kvin[(long)s * 4096 + h * 256 + 128 + d];
        long o = ((long)h * SEQ + s) * 128 + d;
        *(float2*)&vout[o] = v;
        uint32_t hi, lo;
        split2(v.x, v.y, hi, lo);
        *(uint32_t*)&vh[o] = hi; *(uint32_t*)&vl[o] = lo;
    }
}

// ---------------- flash attention: tf32 QK, bf16x3 PV -------------------------
#define VPADB 272
#define FQ_B (128 * 768)
#define FK_B (32 * 768)
#define VT_B (32 * VPADB)
#define KV_BASE FQ_B
#define KV_STAGE (FK_B + 2 * VT_B)
#define FLASH_SMEM (KV_BASE + 2 * KV_STAGE)  // 182272

__device__ __forceinline__ void f_fill_kv(uint32_t dst,
                                          const float* __restrict__ Kf,
                                          const __nv_bfloat16* __restrict__ Vh,
                                          const __nv_bfloat16* __restrict__ Vl,
                                          long k0, int t)
{
#pragma unroll
    for (int i = 0; i < 6; ++i) {
        int id = t + 256 * i;
        int row = id / 48, c = id % 48;
        uint32_t cp = (uint32_t)((c & ~7) | ((c ^ row) & 7));
        cpa16(dst + row * 768 + cp * 16, Kf + (k0 + row) * 192 + c * 4, 16);
    }
#pragma unroll
    for (int i = 0; i < 2; ++i) {
        int id = t + 256 * i;
        int row = id >> 4, ch = id & 15;
        cpa16(dst + FK_B + row * VPADB + ch * 16, Vh + (k0 + row) * 128 + ch * 8, 16);
        cpa16(dst + FK_B + VT_B + row * VPADB + ch * 16, Vl + (k0 + row) * 128 + ch * 8, 16);
    }
}

__global__ __launch_bounds__(256, 1)
void flash_mma(const float* __restrict__ Qf_g, const float* __restrict__ Kf_g,
               const __nv_bfloat16* __restrict__ Vh_g, const __nv_bfloat16* __restrict__ Vl_g,
               float* __restrict__ O_g)
{
    extern __shared__ __align__(128) char smem[];
    uint32_t sb = smem_u32(smem);
    int qt = (int)gridDim.x - 1 - (int)blockIdx.x;
    int h = blockIdx.y;
    int q0 = qt * 128;
    int t = threadIdx.x;
    int warp = t >> 5, lane = t & 31;

    const float* Kgf = Kf_g + (long)h * SEQ * 192;
    const __nv_bfloat16* Vgh = Vh_g + (long)h * SEQ * 128;
    const __nv_bfloat16* Vgl = Vl_g + (long)h * SEQ * 128;

    {
        const float* qg = Qf_g + ((long)h * SEQ + q0) * 192;
#pragma unroll
        for (int i = 0; i < 24; ++i) {
            int id = t + 256 * i;
            int row = id / 48, c = id % 48;
            uint32_t cp = (uint32_t)((c & ~7) | ((c ^ row) & 7));
            cpa16(sb + row * 768 + cp * 16, qg + (long)row * 192 + c * 4, 16);
        }
        CP_COMMIT();
    }
    f_fill_kv(sb + KV_BASE, Kgf, Vgh, Vgl, 0, t);
    CP_COMMIT();

    float o[16][4];
#pragma unroll
    for (int i = 0; i < 16; i++)
#pragma unroll
        for (int r = 0; r < 4; r++) o[i][r] = 0.f;
    float mrow[2] = {-1e30f, -1e30f};
    float lrow[2] = {0.f, 0.f};

    int qq = lane >> 3, lr = lane & 7;
    uint32_t qRow = (uint32_t)((warp * 16 + ((qq & 1) << 3) + lr) * 768);
    uint32_t kRow[2];
#pragma unroll
    for (int p = 0; p < 2; ++p)
        kRow[p] = (uint32_t)((((2 * p + (qq >> 1)) << 3) + lr) * 768);

    uint32_t voff = (uint32_t)(((lane & 7) + (((lane >> 3) & 1) << 3)) * VPADB +
                               ((lane >> 4) << 3) * 2);

    int rA = (lane >> 2);
    int colq = (lane & 3) * 2;
    int rowA = q0 + warp * 16 + rA;
    int rowB = rowA + 8;
    int nkt = 4 * qt + 4;

    for (int kt = 0; kt < nkt; ++kt) {
        __syncthreads();
        if (kt + 1 < nkt)
            f_fill_kv(sb + KV_BASE + ((kt + 1) & 1) * KV_STAGE, Kgf, Vgh, Vgl,
                      (long)(kt + 1) * 32, t);
        CP_COMMIT();
        CP_WAIT(1);
        __syncthreads();

        int k0 = kt * 32;
        uint32_t kvb = sb + KV_BASE + (kt & 1) * KV_STAGE;

        float sc[4][4];
#pragma unroll
        for (int j = 0; j < 4; j++)
#pragma unroll
            for (int r = 0; r < 4; r++) sc[j][r] = 0.f;

#pragma unroll 2
        for (int k8 = 0; k8 < 24; ++k8) {
            int cA = 2 * k8 + (qq >> 1);
            uint32_t offA = (uint32_t)(((cA & ~7) | ((cA ^ lr) & 7)) << 4);
            uint32_t au[4];
            ldsm4(au[0], au[1], au[2], au[3], sb + qRow + offA);
            int cB = 2 * k8 + (qq & 1);
            uint32_t offB = (uint32_t)(((cB & ~7) | ((cB ^ lr) & 7)) << 4);
            uint32_t bu[4][2];
#pragma unroll
            for (int p = 0; p < 2; ++p) {
                uint32_t r0, r1, r2, r3;
                ldsm4(r0, r1, r2, r3, kvb + kRow[p] + offB);
                bu[2 * p][0] = r0;     bu[2 * p][1] = r1;
                bu[2 * p + 1][0] = r2; bu[2 * p + 1][1] = r3;
            }
#pragma unroll
            for (int j = 0; j < 4; ++j)
                mma_tf32(sc[j], au[0], au[1], au[2], au[3], bu[j][0], bu[j][1]);
        }

        bool diag = (kt >= 4 * qt);
#pragma unroll
        for (int j = 0; j < 4; ++j) {
#pragma unroll
            for (int r = 0; r < 4; r++) sc[j][r] *= SM_SCALE;
            if (diag) {
                int col = k0 + j * 8 + colq;
                if (col > rowA)     sc[j][0] = -1e30f;
                if (col + 1 > rowA) sc[j][1] = -1e30f;
                if (col > rowB)     sc[j][2] = -1e30f;
                if (col + 1 > rowB) sc[j][3] = -1e30f;
            }
        }
        float mxa = -1e30f, mxb = -1e30f;
#pragma unroll
        for (int j = 0; j < 4; ++j) {
            mxa = fmaxf(mxa, fmaxf(sc[j][0], sc[j][1]));
            mxb = fmaxf(mxb, fmaxf(sc[j][2], sc[j][3]));
        }
        mxa = fmaxf(mxa, __shfl_xor_sync(0xffffffffu, mxa, 1));
        mxa = fmaxf(mxa, __shfl_xor_sync(0xffffffffu, mxa, 2));
        mxb = fmaxf(mxb, __shfl_xor_sync(0xffffffffu, mxb, 1));
        mxb = fmaxf(mxb, __shfl_xor_sync(0xffffffffu, mxb, 2));
        float mna = fmaxf(mrow[0], mxa), mnb = fmaxf(mrow[1], mxb);
        float ala = __expf(mrow[0] - mna), alb = __expf(mrow[1] - mnb);
        mrow[0] = mna; mrow[1] = mnb;

        float suma = 0.f, sumb = 0.f;
#pragma unroll
        for (int j = 0; j < 4; ++j) {
            sc[j][0] = __expf(sc[j][0] - mna);
            sc[j][1] = __expf(sc[j][1] - mna);
            sc[j][2] = __expf(sc[j][2] - mnb);
            sc[j][3] = __expf(sc[j][3] - mnb);
            suma += sc[j][0] + sc[j][1];
            sumb += sc[j][2] + sc[j][3];
        }
        suma += __shfl_xor_sync(0xffffffffu, suma, 1);
        suma += __shfl_xor_sync(0xffffffffu, suma, 2);
        sumb += __shfl_xor_sync(0xffffffffu, sumb, 1);
        sumb += __shfl_xor_sync(0xffffffffu, sumb, 2);
        lrow[0] = lrow[0] * ala + suma;
        lrow[1] = lrow[1] * alb + sumb;
#pragma unroll
        for (int nb = 0; nb < 16; ++nb) {
            o[nb][0] *= ala; o[nb][1] *= ala;
            o[nb][2] *= alb; o[nb][3] *= alb;
        }

        uint32_t pah[2][4], pal[2][4];
#pragma unroll
        for (int j = 0; j < 2; ++j) {
            split2(sc[2 * j][0],     sc[2 * j][1],     pah[j][0], pal[j][0]);
            split2(sc[2 * j][2],     sc[2 * j][3],     pah[j][1], pal[j][1]);
            split2(sc[2 * j + 1][0], sc[2 * j + 1][1], pah[j][2], pal[j][2]);
            split2(sc[2 * j + 1][2], sc[2 * j + 1][3], pah[j][3], pal[j][3]);
        }

        uint32_t vbase = kvb + FK_B;
#pragma unroll 1
        for (int j = 0; j < 2; ++j) {
#pragma unroll
            for (int nb2 = 0; nb2 < 8; ++nb2) {
                uint32_t va = vbase + voff + j * 16 * VPADB + nb2 * 32;
                uint32_t h0, h1, h2, h3, l0, l1, l2, l3;
                ldsm4t(h0, h1, h2, h3, va);
                ldsm4t(l0, l1, l2, l3, va + VT_B);
                mma16816(o[2 * nb2],     pah[j][0], pah[j][1], pah[j][2], pah[j][3], h0, h1);
                mma16816(o[2 * nb2 + 1], pah[j][0], pah[j][1], pah[j][2], pah[j][3], h2, h3);
                mma16816(o[2 * nb2],     pah[j][0], pah[j][1], pah[j][2], pah[j][3], l0, l1);
                mma16816(o[2 * nb2 + 1], pah[j][0], pah[j][1], pah[j][2], pah[j][3], l2, l3);
                mma16816(o[2 * nb2],     pal[j][0], pal[j][1], pal[j][2], pal[j][3], h0, h1);
                mma16816(o[2 * nb2 + 1], pal[j][0], pal[j][1], pal[j][2], pal[j][3], h2, h3);
            }
        }
    }

    float inva = 1.0f / lrow[0], invb = 1.0f / lrow[1];
#pragma unroll
    for (int nb = 0; nb < 16; ++nb) {
        int col = h * 128 + nb * 8 + colq;
        float2 vA = make_float2(tf32r(o[nb][0] * inva), tf32r(o[nb][1] * inva));
        float2 vB = make_float2(tf32r(o[nb][2] * invb), tf32r(o[nb][3] * invb));
        *(float2*)&O_g[(long)rowA * 2048 + col] = vA;
        *(float2*)&O_g[(long)rowB * 2048 + col] = vB;
    }
}

// ---------------- launch ------------------------------------------------------
extern "C" void kernel_launch(void* const* d_in, const int* in_sizes, int n_in,
                              void* d_out, int out_size)
{
    const float* hidden   = (const float*)d_in[0];
    const int*   pos      = (const int*)d_in[1];
    const float* ln_w     = (const float*)d_in[3];
    const float* wq_a     = (const float*)d_in[4];
    const float* q_a_ln   = (const float*)d_in[5];
    const float* wq_b     = (const float*)d_in[6];
    const float* wkv_a    = (const float*)d_in[7];
    const float* kv_a_ln  = (const float*)d_in[8];
    const float* wkv_b    = (const float*)d_in[9];
    const float* wo       = (const float*)d_in[10];

    float* out   = (float*)d_out;
    float* k_out = out + (long)SEQ * HIDDEN;
    float* v_out = k_out + (long)NHEADS * SEQ * QKD;

    float *p_qackv, *p_q, *p_kv, *p_attn, *p_h, *p_qa, *p_ckvn;
    float *p_wqkva, *p_wqb, *p_wkvb, *p_wo, *p_qf, *p_kf;
    cudaGetSymbolAddress((void**)&p_qackv, g_qackv);
    cudaGetSymbolAddress((void**)&p_q, g_q);
    cudaGetSymbolAddress((void**)&p_kv, g_kv);
    cudaGetSymbolAddress((void**)&p_attn, g_attn_f);
    cudaGetSymbolAddress((void**)&p_h, g_h_f);
    cudaGetSymbolAddress((void**)&p_qa, g_qa_f);
    cudaGetSymbolAddress((void**)&p_ckvn, g_ckvn_f);
    cudaGetSymbolAddress((void**)&p_wqkva, g_wqkva_f);
    cudaGetSymbolAddress((void**)&p_wqb, g_wqb_f);
    cudaGetSymbolAddress((void**)&p_wkvb, g_wkvb_f);
    cudaGetSymbolAddress((void**)&p_wo, g_wo_f);
    cudaGetSymbolAddress((void**)&p_qf, g_qf_f);
    cudaGetSymbolAddress((void**)&p_kf, g_k_f);

    __nv_bfloat16 *v_hi, *v_lo;
    cudaGetSymbolAddress((void**)&v_hi, g_v_hi);
    cudaGetSymbolAddress((void**)&v_lo, g_v_lo);

    cudaFuncSetAttribute(gemm_t32, cudaFuncAttributeMaxDynamicSharedMemorySize, GEMM_SMEM);
    cudaFuncSetAttribute(gemm_t32_pers, cudaFuncAttributeMaxDynamicSharedMemorySize, GEMM_SMEM);
    cudaFuncSetAttribute(gemm_t32_dual_pers, cudaFuncAttributeMaxDynamicSharedMemorySize, GEMM_SMEM);
    cudaFuncSetAttribute(flash_mma, cudaFuncAttributeMaxDynamicSharedMemorySize, FLASH_SMEM);

    rms_cvt_A<<<SEQ + 1184, 256>>>(
        hidden, ln_w, p_h,
        wq_a, p_wqkva, (long)QLORA * HIDDEN / 4,
        wkv_a, p_wqkva + (long)QLORA * HIDDEN, (long)576 * HIDDEN / 4);
    gemm_t32<<<dim3(17, SEQ / 128), 256, GEMM_SMEM>>>(
        p_h, HIDDEN, p_wqkva, p_qackv, SEQ, QKVN, HIDDEN, nullptr, 0.f);
    rms_cvt_B<<<2 * SEQ + 1184, 256>>>(
        p_qackv, q_a_ln, p_qa, kv_a_ln, p_ckvn,
        wq_b, p_wqb, (long)3072 * QLORA / 4,
        wkv_b, p_wkvb, (long)4096 * KVLORA / 4);
    gemm_t32_dual_pers<<<PERS_GRID, 256, GEMM_SMEM>>>(
        p_qa, QLORA, p_wqb, p_q, 3072, QLORA, 24,
        p_ckvn, KVLORA, p_wkvb, p_kv, 4096, KVLORA, 32,
        24 * 16, 24 * 16 + 32 * 16);
    rope_scatter_cvt<<<SEQ + 1184, 256>>>(
        p_q, p_qackv, p_kv, pos, p_qf,
        k_out, p_kf, v_out, v_hi, v_lo,
        wo, p_wo, (long)HIDDEN * 2048 / 4);
    flash_mma<<<dim3(SEQ / 128, NHEADS), 256, FLASH_SMEM>>>(
        p_qf, p_kf, v_hi, v_lo, p_attn);
    gemm_t32_pers<<<PERS_GRID, 256, GEMM_SMEM>>>(
        p_attn, 2048, p_wo, out, SEQ, HIDDEN, 2048, hidden, RESID_SCALE,
        40, 640);
}